// round 4
// baseline (speedup 1.0000x reference)
#include <cuda_runtime.h>
#include <math.h>
#include <stdint.h>

#define BATCH 64
#define SEQ   512
#define DIN   1024
#define DENSE 1024
#define HID   768
#define G4    (4*HID)    // 3072
#define E2    (2*HID)    // 1536
#define NINT  60
#define MT    (BATCH*SEQ) // 32768

// transposed-weight offsets (floats) in d_wT, layout [N][K]
#define O_WREG 0u
#define O_WI0F 1048576u
#define O_WI0B 4194304u
#define O_WI1F 7340032u
#define O_WI1B 12058624u
#define O_WKEY 16777216u
#define WTOT   19136512u

// ---------------- static device buffers ----------------
__device__ float d_reg [(size_t)MT * DENSE];
__device__ float d_xpf [(size_t)MT * G4];
__device__ float d_xpb [(size_t)MT * G4];
__device__ float d_enc0[(size_t)MT * E2];
__device__ float d_enc1[(size_t)MT * E2];
__device__ float d_whT [4][(size_t)G4 * HID];   // [layer*2+dir][n][k]
__device__ float d_wT  [WTOT];                  // all GEMM weights, [N][K]
__device__ float d_h   [2][2][BATCH][HID];      // [parity][dir][b][k]
__device__ float d_scores[MT];
__device__ float d_attn  [MT];
__device__ float d_ctx [BATCH * E2];
__device__ float d_ctx2[BATCH * E2];
__device__ unsigned d_bar_cnt = 0;
__device__ volatile unsigned d_bar_gen = 0;

__device__ __forceinline__ float* buf_sel(int s) {
    switch (s) {
        case 0: return d_reg;
        case 1: return d_xpf;
        case 2: return d_xpb;
        case 3: return d_enc0;
        default: return d_enc1;
    }
}

// packed fp32x2 FMA: d = a*b + d (elementwise on 2 fp32 lanes)
__device__ __forceinline__ void ffma2(unsigned long long& d,
                                      unsigned long long a,
                                      unsigned long long b) {
    asm("fma.rn.f32x2 %0, %1, %2, %0;" : "+l"(d) : "l"(a), "l"(b));
}
__device__ __forceinline__ float ull_sum2(unsigned long long v) {
    float x, y;
    asm("mov.b64 {%0,%1}, %2;" : "=f"(x), "=f"(y) : "l"(v));
    return x + y;
}

// ---------------- software grid barrier (all blocks co-resident) ----------------
__device__ __forceinline__ void grid_bar() {
    __syncthreads();
    if (threadIdx.x == 0) {
        unsigned gen = d_bar_gen;
        __threadfence();
        unsigned arrived = atomicAdd(&d_bar_cnt, 1u);
        if (arrived == gridDim.x - 1) {
            d_bar_cnt = 0;
            __threadfence();
            d_bar_gen = gen + 1;
        } else {
            while (d_bar_gen == gen) { }
        }
        __threadfence();
    }
    __syncthreads();
}

// ================= FFMA2 SGEMM =================
// C[M,N] = act(A[M,K] @ W[K,N] + bias), W pre-transposed to [N][K].
// Tile 128(M) x 64(N), k-tile 32 (16 f32x2 pairs), 256 threads.
// Thread microtile: 8 rows x 4 cols (cols interleaved by 16 for bank-free loads).
// smem layout: per k-pair plane of float2 -> both operand loads are LDS.64.
template <bool TANH>
__global__ void __launch_bounds__(256) gemm2(
    const float* __restrict__ Aext, int aSel, unsigned wOff,
    const float* __restrict__ bias, int cSel, int N, int K)
{
    const float* __restrict__ A = (aSel < 0) ? Aext : buf_sel(aSel);
    const float* __restrict__ Bw = d_wT + wOff;   // [N][K]
    float* __restrict__ C = buf_sel(cSel);

    __shared__ float2 As2[16][128];
    __shared__ float2 Bs2[16][64];

    const int tid = threadIdx.x;
    const int tx = tid & 15;     // col group: cols bn + tx + 16*j
    const int ty = tid >> 4;     // row group: rows bm + ty*8 + i
    const int bm = blockIdx.y * 128;
    const int bn = blockIdx.x * 64;

    unsigned long long acc[8][4];
#pragma unroll
    for (int i = 0; i < 8; i++)
#pragma unroll
        for (int j = 0; j < 4; j++) acc[i][j] = 0ull;

    float4 ra[4], rb[2];
    // indices for staging: A: 128 rows x 8 float4, B: 64 rows x 8 float4
    const int ar[4] = { (tid + 0) >> 3, (tid + 256) >> 3, (tid + 512) >> 3, (tid + 768) >> 3 };
    const int ac = tid & 7;
    const int br_[2] = { (tid + 0) >> 3, (tid + 256) >> 3 };

    auto loadA = [&](int k0) {
#pragma unroll
        for (int i = 0; i < 4; i++)
            ra[i] = *(const float4*)&A[(size_t)(bm + ar[i]) * K + k0 + ac * 4];
    };
    auto loadB = [&](int k0) {
#pragma unroll
        for (int i = 0; i < 2; i++)
            rb[i] = *(const float4*)&Bw[(size_t)(bn + br_[i]) * K + k0 + ac * 4];
    };
    auto storeAB = [&]() {
#pragma unroll
        for (int i = 0; i < 4; i++) {
            As2[ac * 2 + 0][ar[i]] = make_float2(ra[i].x, ra[i].y);
            As2[ac * 2 + 1][ar[i]] = make_float2(ra[i].z, ra[i].w);
        }
#pragma unroll
        for (int i = 0; i < 2; i++) {
            Bs2[ac * 2 + 0][br_[i]] = make_float2(rb[i].x, rb[i].y);
            Bs2[ac * 2 + 1][br_[i]] = make_float2(rb[i].z, rb[i].w);
        }
    };
    auto compute = [&]() {
#pragma unroll
        for (int kp = 0; kp < 16; kp++) {
            unsigned long long a2[8], b2[4];
#pragma unroll
            for (int i = 0; i < 8; i++)
                a2[i] = *(const unsigned long long*)&As2[kp][ty * 8 + i];
#pragma unroll
            for (int j = 0; j < 4; j++)
                b2[j] = *(const unsigned long long*)&Bs2[kp][tx + 16 * j];
#pragma unroll
            for (int i = 0; i < 8; i++)
#pragma unroll
                for (int j = 0; j < 4; j++)
                    ffma2(acc[i][j], a2[i], b2[j]);
        }
    };

    loadA(0); loadB(0);
    storeAB();
    __syncthreads();

    for (int k0 = 32; ; k0 += 32) {
        const bool more = (k0 < K);
        if (more) { loadA(k0); loadB(k0); }
        compute();
        if (!more) break;
        __syncthreads();
        storeAB();
        __syncthreads();
    }

    // epilogue
#pragma unroll
    for (int i = 0; i < 8; i++) {
        const int row = bm + ty * 8 + i;
#pragma unroll
        for (int j = 0; j < 4; j++) {
            const int col = bn + tx + 16 * j;
            float v = ull_sum2(acc[i][j]) + (bias ? bias[col] : 0.f);
            if (TANH) v = tanhf(v);
            C[(size_t)row * N + col] = v;
        }
    }
}

// ---------------- weight transpose into d_wT: [K][N] -> [N][K] ----------------
__global__ void conv_wT(const float* __restrict__ W, int K, int N, unsigned off) {
    __shared__ float tile[32][33];
    int n0 = blockIdx.x * 32, k0 = blockIdx.y * 32;
    int tx = threadIdx.x, ty = threadIdx.y;
    for (int i = ty; i < 32; i += 8)
        tile[i][tx] = W[(size_t)(k0 + i) * N + n0 + tx];
    __syncthreads();
    for (int i = ty; i < 32; i += 8)
        d_wT[off + (size_t)(n0 + i) * K + k0 + tx] = tile[tx][i];
}

// ---------------- Wh transpose: Wt[n][k] = W[k][n], K=768, N=3072 ----------------
__global__ void transpose_wh(const float* __restrict__ W, int widx) {
    __shared__ float tile[32][33];
    float* Wt = d_whT[widx];
    int k0 = blockIdx.y * 32, n0 = blockIdx.x * 32;
    int tx = threadIdx.x, ty = threadIdx.y;
    for (int i = ty; i < 32; i += 8)
        tile[i][tx] = W[(size_t)(k0 + i) * G4 + n0 + tx];
    __syncthreads();
    for (int i = ty; i < 32; i += 8)
        Wt[(size_t)(n0 + i) * HID + k0 + tx] = tile[tx][i];
}

// ---------------- persistent BiLSTM layer (fwd+bwd), 128 blocks x 384 threads ----
// Block = (dir, 16-batch tile, 48-j tile). Thread = 2 batches x j x 4 gates.
// Inner dot products use fma.rn.f32x2 packed over the k dimension.
__global__ void __launch_bounds__(384, 1) lstm_layer(int layer, const int* __restrict__ lens) {
    __shared__ float Hs[16][HID];  // 48KB

    const int tid = threadIdx.x;
    const int dir = blockIdx.x >> 6;
    const int rem = blockIdx.x & 63;
    const int b0 = (rem >> 4) * 16;
    const int jbase = (rem & 15) * 48;
    const int tx = tid % 48;
    const int ty = tid / 48;              // 0..7
    const int j = jbase + tx;
    const int bloc0 = ty * 2;

    const float* xp = dir ? d_xpb : d_xpf;
    const float* whT = d_whT[layer * 2 + dir];
    float* enc = layer ? d_enc1 : d_enc0;

    int myb[2], myL[2];
#pragma unroll
    for (int bi = 0; bi < 2; bi++) {
        myb[bi] = b0 + bloc0 + bi;
        myL[bi] = lens[myb[bi]];
    }
    int maxL = max(myL[0], myL[1]);

    for (int i = tid; i < 16 * 48; i += 384)
        d_h[0][dir][b0 + (i / 48)][jbase + (i % 48)] = 0.f;
    float c2[2] = {0.f, 0.f};
    grid_bar();

    const float* wr0 = whT + (size_t)(0 * HID + j) * HID;
    const float* wr1 = whT + (size_t)(1 * HID + j) * HID;
    const float* wr2 = whT + (size_t)(2 * HID + j) * HID;
    const float* wr3 = whT + (size_t)(3 * HID + j) * HID;

    for (int t = 0; t < SEQ; t++) {
        const int p = t & 1;
        const float4* hsrc = (const float4*)&d_h[p][dir][b0][0];
        float4* hdst = (float4*)&Hs[0][0];
#pragma unroll
        for (int i = 0; i < 8; i++)
            hdst[tid + i * 384] = __ldcg(hsrc + tid + i * 384);
        __syncthreads();

        unsigned long long acc2[2][4];
#pragma unroll
        for (int bi = 0; bi < 2; bi++)
#pragma unroll
            for (int g = 0; g < 4; g++) acc2[bi][g] = 0ull;

        if (t < maxL) {
#pragma unroll 2
            for (int k = 0; k < HID; k += 4) {
                ulonglong2 w0 = *(const ulonglong2*)(wr0 + k);
                ulonglong2 w1 = *(const ulonglong2*)(wr1 + k);
                ulonglong2 w2 = *(const ulonglong2*)(wr2 + k);
                ulonglong2 w3 = *(const ulonglong2*)(wr3 + k);
#pragma unroll
                for (int bi = 0; bi < 2; bi++) {
                    ulonglong2 h = *(const ulonglong2*)&Hs[bloc0 + bi][k];
                    ffma2(acc2[bi][0], w0.x, h.x); ffma2(acc2[bi][0], w0.y, h.y);
                    ffma2(acc2[bi][1], w1.x, h.x); ffma2(acc2[bi][1], w1.y, h.y);
                    ffma2(acc2[bi][2], w2.x, h.x); ffma2(acc2[bi][2], w2.y, h.y);
                    ffma2(acc2[bi][3], w3.x, h.x); ffma2(acc2[bi][3], w3.y, h.y);
                }
            }
        }

#pragma unroll
        for (int bi = 0; bi < 2; bi++) {
            const int b = myb[bi];
            const int L = myL[bi];
            const bool alive = (t < L);
            const int src = dir ? (alive ? (L - 1 - t) : t) : t;
            float hold = Hs[bloc0 + bi][j];
            float hnew, outv;
            if (alive) {
                const float* xr = xp + ((size_t)b * SEQ + src) * G4;
                float zi = ull_sum2(acc2[bi][0]) + xr[j];
                float zf = ull_sum2(acc2[bi][1]) + xr[HID + j];
                float zg = ull_sum2(acc2[bi][2]) + xr[2 * HID + j];
                float zo = ull_sum2(acc2[bi][3]) + xr[3 * HID + j];
                float si = 1.f / (1.f + expf(-zi));
                float sf = 1.f / (1.f + expf(-zf));
                float so = 1.f / (1.f + expf(-zo));
                float nc = sf * c2[bi] + si * tanhf(zg);
                c2[bi] = nc;
                hnew = so * tanhf(nc);
                outv = hnew;
            } else {
                hnew = hold;
                outv = 0.f;
            }
            d_h[p ^ 1][dir][b][j] = hnew;
            enc[((size_t)b * SEQ + src) * E2 + dir * HID + j] = outv;
        }
        grid_bar();
    }
}

// ---------------- attention tail ----------------
__global__ void scores_kernel(const float* __restrict__ we) {  // ekey lives in d_xpf
    const int warp = threadIdx.x >> 5, lane = threadIdx.x & 31;
    const size_t row = (size_t)blockIdx.x * 8 + warp;
    const float* r = d_xpf + row * E2;
    float s = 0.f;
    for (int k = lane; k < E2; k += 32) s += r[k] * we[k];
#pragma unroll
    for (int o = 16; o; o >>= 1) s += __shfl_down_sync(0xffffffffu, s, o);
    if (!lane) d_scores[row] = s;
}

__global__ void softmax_kernel(const int* __restrict__ lens) {
    __shared__ float red[512];
    const int b = blockIdx.x, t = threadIdx.x;
    const int L = lens[b];
    float v = (t < L) ? d_scores[b * SEQ + t] : -INFINITY;
    red[t] = v;
    __syncthreads();
    for (int s = 256; s > 0; s >>= 1) { if (t < s) red[t] = fmaxf(red[t], red[t + s]); __syncthreads(); }
    float m = red[0];
    __syncthreads();
    float e = (t < L) ? expf(v - m) : 0.f;
    red[t] = e;
    __syncthreads();
    for (int s = 256; s > 0; s >>= 1) { if (t < s) red[t] += red[t + s]; __syncthreads(); }
    d_attn[b * SEQ + t] = e / red[0];
}

__global__ void context_kernel() {
    const int b = blockIdx.y;
    const int h = blockIdx.x * 256 + threadIdx.x;
    float acc = 0.f;
    const float* a = d_attn + b * SEQ;
    const float* e = d_enc1 + (size_t)b * SEQ * E2 + h;
    for (int t = 0; t < SEQ; t++) acc += a[t] * e[(size_t)t * E2];
    d_ctx[b * E2 + h] = acc;
}

__global__ void post_kernel(const float* __restrict__ Wp, const float* __restrict__ bp) {
    const int b = blockIdx.y;
    const int n = blockIdx.x * 256 + threadIdx.x;
    float acc = bp[n];
    const float* c = d_ctx + b * E2;
    for (int k = 0; k < E2; k++) acc += c[k] * Wp[(size_t)k * E2 + n];
    d_ctx2[b * E2 + n] = acc;
}

__global__ void intents_kernel(const float* __restrict__ Wi, const float* __restrict__ bi, float* __restrict__ out) {
    const int b = blockIdx.x, n = threadIdx.x;
    if (n >= NINT) return;
    float acc = bi[n];
    const float* c = d_ctx2 + b * E2;
    for (int k = 0; k < E2; k++) acc += c[k] * Wi[k * NINT + n];
    out[b * NINT + n] = acc;
}

// ---------------- launch ----------------
extern "C" void kernel_launch(void* const* d_in, const int* in_sizes, int n_in,
                              void* d_out, int out_size) {
    const float* X    = (const float*)d_in[0];
    const int*   lens = (const int*)  d_in[1];
    const int s = (n_in >= 23) ? 3 : 2;  // skip is_test if present
    const float* W_reg  = (const float*)d_in[s + 0];
    const float* b_reg  = (const float*)d_in[s + 1];
    const float* Wi0f   = (const float*)d_in[s + 2];
    const float* Wh0f   = (const float*)d_in[s + 3];
    const float* b0f    = (const float*)d_in[s + 4];
    const float* Wi0b   = (const float*)d_in[s + 5];
    const float* Wh0b   = (const float*)d_in[s + 6];
    const float* b0b    = (const float*)d_in[s + 7];
    const float* Wi1f   = (const float*)d_in[s + 8];
    const float* Wh1f   = (const float*)d_in[s + 9];
    const float* b1f    = (const float*)d_in[s + 10];
    const float* Wi1b   = (const float*)d_in[s + 11];
    const float* Wh1b   = (const float*)d_in[s + 12];
    const float* b1b    = (const float*)d_in[s + 13];
    const float* W_keys = (const float*)d_in[s + 14];
    const float* W_en   = (const float*)d_in[s + 15];
    const float* W_post = (const float*)d_in[s + 16];
    const float* b_post = (const float*)d_in[s + 17];
    const float* W_int  = (const float*)d_in[s + 18];
    const float* b_int  = (const float*)d_in[s + 19];

    // 1) LSTM recurrent-weight transposes
    {
        dim3 g(G4 / 32, HID / 32), b(32, 8);
        transpose_wh<<<g, b>>>(Wh0f, 0);
        transpose_wh<<<g, b>>>(Wh0b, 1);
        transpose_wh<<<g, b>>>(Wh1f, 2);
        transpose_wh<<<g, b>>>(Wh1b, 3);
    }
    // 2) GEMM weight transposes -> d_wT [N][K]
    {
        dim3 b(32, 8);
        conv_wT<<<dim3(DENSE / 32, DIN / 32), b>>>(W_reg, DIN, DENSE, O_WREG);
        conv_wT<<<dim3(G4 / 32, DENSE / 32), b>>>(Wi0f, DENSE, G4, O_WI0F);
        conv_wT<<<dim3(G4 / 32, DENSE / 32), b>>>(Wi0b, DENSE, G4, O_WI0B);
        conv_wT<<<dim3(G4 / 32, E2 / 32),    b>>>(Wi1f, E2, G4, O_WI1F);
        conv_wT<<<dim3(G4 / 32, E2 / 32),    b>>>(Wi1b, E2, G4, O_WI1B);
        conv_wT<<<dim3(E2 / 32, E2 / 32),    b>>>(W_keys, E2, E2, O_WKEY);
    }

    // 3) reg = X @ W_reg + b_reg
    gemm2<false><<<dim3(DENSE / 64, MT / 128), 256>>>(X, -1, O_WREG, b_reg, 0, DENSE, DIN);

    // 4) layer-0 input projections
    gemm2<false><<<dim3(G4 / 64, MT / 128), 256>>>(nullptr, 0, O_WI0F, b0f, 1, G4, DENSE);
    gemm2<false><<<dim3(G4 / 64, MT / 128), 256>>>(nullptr, 0, O_WI0B, b0b, 2, G4, DENSE);

    // 5) layer-0 recurrence -> enc0
    lstm_layer<<<128, 384>>>(0, lens);

    // 6) layer-1 input projections
    gemm2<false><<<dim3(G4 / 64, MT / 128), 256>>>(nullptr, 3, O_WI1F, b1f, 1, G4, E2);
    gemm2<false><<<dim3(G4 / 64, MT / 128), 256>>>(nullptr, 3, O_WI1B, b1b, 2, G4, E2);

    // 7) layer-1 recurrence -> enc1
    lstm_layer<<<128, 384>>>(1, lens);

    // 8) ekey = tanh(enc1 @ W_keys) -> d_xpf
    gemm2<true><<<dim3(E2 / 64, MT / 128), 256>>>(nullptr, 4, O_WKEY, nullptr, 1, E2, E2);

    // 9) attention tail
    scores_kernel<<<MT / 8, 256>>>(W_en);
    softmax_kernel<<<BATCH, 512>>>(lens);
    context_kernel<<<dim3(E2 / 256, BATCH), 256>>>();
    post_kernel<<<dim3(E2 / 256, BATCH), 256>>>(W_post, b_post);
    intents_kernel<<<BATCH, 64>>>(W_int, b_int, (float*)d_out);
}

// round 5
// speedup vs baseline: 1.0953x; 1.0953x over previous
#include <cuda_runtime.h>
#include <math.h>
#include <stdint.h>

#define BATCH 64
#define SEQ   512
#define DIN   1024
#define DENSE 1024
#define HID   768
#define G4    (4*HID)    // 3072
#define E2    (2*HID)    // 1536
#define NINT  60
#define MT    (BATCH*SEQ) // 32768

// ---------------- static device buffers ----------------
__device__ float d_reg [(size_t)MT * DENSE];
__device__ float d_xpf [(size_t)MT * G4];
__device__ float d_xpb [(size_t)MT * G4];
__device__ float d_enc0[(size_t)MT * E2];
__device__ float d_enc1[(size_t)MT * E2];
__device__ float d_whT [4][(size_t)G4 * HID];   // [layer*2+dir][n][k]
__device__ float d_h   [2][2][BATCH][HID];      // [parity][dir][b][k]
__device__ float d_scores[MT];
__device__ float d_attn  [MT];
__device__ float d_ctx [BATCH * E2];
__device__ float d_ctx2[BATCH * E2];
__device__ unsigned d_bar_cnt = 0;
__device__ volatile unsigned d_bar_gen = 0;

__device__ __forceinline__ float* buf_sel(int s) {
    switch (s) {
        case 0: return d_reg;
        case 1: return d_xpf;
        case 2: return d_xpb;
        case 3: return d_enc0;
        default: return d_enc1;
    }
}

// ---------------- software grid barrier (all blocks co-resident) ----------------
__device__ __forceinline__ void grid_bar() {
    __syncthreads();
    if (threadIdx.x == 0) {
        unsigned gen = d_bar_gen;
        __threadfence();
        unsigned arrived = atomicAdd(&d_bar_cnt, 1u);
        if (arrived == gridDim.x - 1) {
            d_bar_cnt = 0;
            __threadfence();
            d_bar_gen = gen + 1;
        } else {
            while (d_bar_gen == gen) { }
        }
        __threadfence();
    }
    __syncthreads();
}

// ================= double-buffered FFMA SGEMM =================
// C[M,N] = act(A[M,K] @ W[K,N] + bias). Tile 128x128, Kt=16, 256 threads,
// 8x8 microtile (4+4 split). One __syncthreads per k-step; global prefetch
// into registers overlaps previous tile's compute.
// SKIP: whole-block early-out when all 128 rows have t >= len[b].
#define SSTRIDE 132   // padded row stride (floats), 16B-aligned

template <bool TANH>
__global__ void __launch_bounds__(256, 2) gemm3(
    const float* __restrict__ Aext, int aSel,
    const float* __restrict__ W, const float* __restrict__ bias,
    int cSel, int N, int K, const int* __restrict__ lens)
{
    const int bm = blockIdx.y * 128;
    if (lens) {
        const int b = bm >> 9, t0 = bm & 511;
        if (t0 >= lens[b]) return;   // dead rows: outputs never consumed
    }
    const float* __restrict__ A = (aSel < 0) ? Aext : buf_sel(aSel);
    float* __restrict__ C = buf_sel(cSel);

    __shared__ float As[2][16 * SSTRIDE];
    __shared__ float Bs[2][16 * SSTRIDE];

    const int tid = threadIdx.x;
    const int bn = blockIdx.x * 128;
    const int tx = tid & 15;
    const int ty = tid >> 4;

    // staging indices: A 128 rows x 16k (512 float4), B 16k x 128n (512 float4)
    const int a_row0 = tid >> 2;            // + i*64
    const int a_kq   = (tid & 3) * 4;
    const int b_kr0  = tid >> 5;            // + i*8
    const int b_nq   = (tid & 31) * 4;

    float acc[8][8];
#pragma unroll
    for (int i = 0; i < 8; i++)
#pragma unroll
        for (int j = 0; j < 8; j++) acc[i][j] = 0.f;

    float4 ra[2], rb[2];
    auto loadG = [&](int k0) {
#pragma unroll
        for (int i = 0; i < 2; i++)
            ra[i] = *(const float4*)&A[(size_t)(bm + a_row0 + i * 64) * K + k0 + a_kq];
#pragma unroll
        for (int i = 0; i < 2; i++)
            rb[i] = *(const float4*)&W[(size_t)(k0 + b_kr0 + i * 8) * N + bn + b_nq];
    };
    auto storeS = [&](int buf) {
        float* as = As[buf];
        float* bs = Bs[buf];
#pragma unroll
        for (int i = 0; i < 2; i++) {
            const int r = a_row0 + i * 64;
            as[(a_kq + 0) * SSTRIDE + r] = ra[i].x;
            as[(a_kq + 1) * SSTRIDE + r] = ra[i].y;
            as[(a_kq + 2) * SSTRIDE + r] = ra[i].z;
            as[(a_kq + 3) * SSTRIDE + r] = ra[i].w;
        }
#pragma unroll
        for (int i = 0; i < 2; i++)
            *(float4*)&bs[(b_kr0 + i * 8) * SSTRIDE + b_nq] = rb[i];
    };
    auto compute = [&](int buf) {
        const float* as = As[buf];
        const float* bs = Bs[buf];
#pragma unroll
        for (int kk = 0; kk < 16; kk++) {
            float arr[8], brr[8];
            *(float4*)&arr[0] = *(const float4*)&as[kk * SSTRIDE + ty * 4];
            *(float4*)&arr[4] = *(const float4*)&as[kk * SSTRIDE + 64 + ty * 4];
            *(float4*)&brr[0] = *(const float4*)&bs[kk * SSTRIDE + tx * 4];
            *(float4*)&brr[4] = *(const float4*)&bs[kk * SSTRIDE + 64 + tx * 4];
#pragma unroll
            for (int i = 0; i < 8; i++)
#pragma unroll
                for (int j = 0; j < 8; j++)
                    acc[i][j] = fmaf(arr[i], brr[j], acc[i][j]);
        }
    };

    loadG(0);
    storeS(0);
    __syncthreads();

    const int NT = K >> 4;
    for (int kt = 0; kt < NT; kt++) {
        const int buf = kt & 1;
        const bool more = (kt + 1 < NT);
        if (more) loadG((kt + 1) << 4);
        compute(buf);
        if (more) {
            storeS(buf ^ 1);
            __syncthreads();
        }
    }

    // epilogue
#pragma unroll
    for (int hm = 0; hm < 2; hm++) {
#pragma unroll
        for (int i = 0; i < 4; i++) {
            const int row = bm + hm * 64 + ty * 4 + i;
            const int ri = hm * 4 + i;
#pragma unroll
            for (int hn = 0; hn < 2; hn++) {
                const int cb = bn + hn * 64 + tx * 4;
                float4 v;
                v.x = acc[ri][hn * 4 + 0] + (bias ? bias[cb + 0] : 0.f);
                v.y = acc[ri][hn * 4 + 1] + (bias ? bias[cb + 1] : 0.f);
                v.z = acc[ri][hn * 4 + 2] + (bias ? bias[cb + 2] : 0.f);
                v.w = acc[ri][hn * 4 + 3] + (bias ? bias[cb + 3] : 0.f);
                if (TANH) { v.x = tanhf(v.x); v.y = tanhf(v.y); v.z = tanhf(v.z); v.w = tanhf(v.w); }
                *(float4*)&C[(size_t)row * N + cb] = v;
            }
        }
    }
}

// ---------------- Wh transpose: Wt[n][k] = W[k][n], K=768, N=3072 ----------------
__global__ void transpose_wh(const float* __restrict__ W, int widx) {
    __shared__ float tile[32][33];
    float* Wt = d_whT[widx];
    int k0 = blockIdx.y * 32, n0 = blockIdx.x * 32;
    int tx = threadIdx.x, ty = threadIdx.y;
    for (int i = ty; i < 32; i += 8)
        tile[i][tx] = W[(size_t)(k0 + i) * G4 + n0 + tx];
    __syncthreads();
    for (int i = ty; i < 32; i += 8)
        Wt[(size_t)(n0 + i) * HID + k0 + tx] = tile[tx][i];
}

// ---------------- persistent BiLSTM layer (fwd+bwd), 128 blocks x 384 threads ----
// Block = (dir, 16-batch tile, 48-j tile). Thread = 2 batches x j x 4 gates.
// Cell state c lives in registers all 512 steps; h ping-pongs in global.
__global__ void __launch_bounds__(384, 1) lstm_layer(int layer, const int* __restrict__ lens) {
    __shared__ float Hs[16][HID];  // 48KB

    const int tid = threadIdx.x;
    const int dir = blockIdx.x >> 6;
    const int rem = blockIdx.x & 63;
    const int b0 = (rem >> 4) * 16;
    const int jbase = (rem & 15) * 48;
    const int tx = tid % 48;
    const int ty = tid / 48;              // 0..7
    const int j = jbase + tx;
    const int bloc0 = ty * 2;

    const float* xp = dir ? d_xpb : d_xpf;
    const float* whT = d_whT[layer * 2 + dir];
    float* enc = layer ? d_enc1 : d_enc0;

    int myb[2], myL[2];
#pragma unroll
    for (int bi = 0; bi < 2; bi++) {
        myb[bi] = b0 + bloc0 + bi;
        myL[bi] = lens[myb[bi]];
    }
    int maxL = max(myL[0], myL[1]);

    for (int i = tid; i < 16 * 48; i += 384)
        d_h[0][dir][b0 + (i / 48)][jbase + (i % 48)] = 0.f;
    float c2[2] = {0.f, 0.f};
    grid_bar();

    const float* wr0 = whT + (size_t)(0 * HID + j) * HID;
    const float* wr1 = whT + (size_t)(1 * HID + j) * HID;
    const float* wr2 = whT + (size_t)(2 * HID + j) * HID;
    const float* wr3 = whT + (size_t)(3 * HID + j) * HID;

    for (int t = 0; t < SEQ; t++) {
        const int p = t & 1;
        const float4* hsrc = (const float4*)&d_h[p][dir][b0][0];
        float4* hdst = (float4*)&Hs[0][0];
#pragma unroll
        for (int i = 0; i < 8; i++)
            hdst[tid + i * 384] = __ldcg(hsrc + tid + i * 384);
        __syncthreads();

        float acc[2][4];
#pragma unroll
        for (int bi = 0; bi < 2; bi++)
#pragma unroll
            for (int g = 0; g < 4; g++) acc[bi][g] = 0.f;

        if (t < maxL) {
#pragma unroll 2
            for (int k = 0; k < HID; k += 4) {
                float4 w0 = *(const float4*)(wr0 + k);
                float4 w1 = *(const float4*)(wr1 + k);
                float4 w2 = *(const float4*)(wr2 + k);
                float4 w3 = *(const float4*)(wr3 + k);
#pragma unroll
                for (int bi = 0; bi < 2; bi++) {
                    float4 hv = *(const float4*)&Hs[bloc0 + bi][k];
                    acc[bi][0] += hv.x * w0.x + hv.y * w0.y + hv.z * w0.z + hv.w * w0.w;
                    acc[bi][1] += hv.x * w1.x + hv.y * w1.y + hv.z * w1.z + hv.w * w1.w;
                    acc[bi][2] += hv.x * w2.x + hv.y * w2.y + hv.z * w2.z + hv.w * w2.w;
                    acc[bi][3] += hv.x * w3.x + hv.y * w3.y + hv.z * w3.z + hv.w * w3.w;
                }
            }
        }

#pragma unroll
        for (int bi = 0; bi < 2; bi++) {
            const int b = myb[bi];
            const int L = myL[bi];
            const bool alive = (t < L);
            const int src = dir ? (alive ? (L - 1 - t) : t) : t;
            float hold = Hs[bloc0 + bi][j];
            float hnew, outv;
            if (alive) {
                const float* xr = xp + ((size_t)b * SEQ + src) * G4;
                float zi = acc[bi][0] + xr[j];
                float zf = acc[bi][1] + xr[HID + j];
                float zg = acc[bi][2] + xr[2 * HID + j];
                float zo = acc[bi][3] + xr[3 * HID + j];
                float si = 1.f / (1.f + expf(-zi));
                float sf = 1.f / (1.f + expf(-zf));
                float so = 1.f / (1.f + expf(-zo));
                float nc = sf * c2[bi] + si * tanhf(zg);
                c2[bi] = nc;
                hnew = so * tanhf(nc);
                outv = hnew;
            } else {
                hnew = hold;
                outv = 0.f;
            }
            d_h[p ^ 1][dir][b][j] = hnew;
            enc[((size_t)b * SEQ + src) * E2 + dir * HID + j] = outv;
        }
        grid_bar();
    }
}

// ---------------- attention tail ----------------
__global__ void scores_kernel(const float* __restrict__ we) {  // ekey lives in d_xpf
    const int warp = threadIdx.x >> 5, lane = threadIdx.x & 31;
    const size_t row = (size_t)blockIdx.x * 8 + warp;
    const float* r = d_xpf + row * E2;
    float s = 0.f;
    for (int k = lane; k < E2; k += 32) s += r[k] * we[k];
#pragma unroll
    for (int o = 16; o; o >>= 1) s += __shfl_down_sync(0xffffffffu, s, o);
    if (!lane) d_scores[row] = s;
}

__global__ void softmax_kernel(const int* __restrict__ lens) {
    __shared__ float red[512];
    const int b = blockIdx.x, t = threadIdx.x;
    const int L = lens[b];
    float v = (t < L) ? d_scores[b * SEQ + t] : -INFINITY;
    red[t] = v;
    __syncthreads();
    for (int s = 256; s > 0; s >>= 1) { if (t < s) red[t] = fmaxf(red[t], red[t + s]); __syncthreads(); }
    float m = red[0];
    __syncthreads();
    float e = (t < L) ? expf(v - m) : 0.f;
    red[t] = e;
    __syncthreads();
    for (int s = 256; s > 0; s >>= 1) { if (t < s) red[t] += red[t + s]; __syncthreads(); }
    d_attn[b * SEQ + t] = e / red[0];
}

__global__ void context_kernel() {
    const int b = blockIdx.y;
    const int h = blockIdx.x * 256 + threadIdx.x;
    float acc = 0.f;
    const float* a = d_attn + b * SEQ;
    const float* e = d_enc1 + (size_t)b * SEQ * E2 + h;
    for (int t = 0; t < SEQ; t++) acc += a[t] * e[(size_t)t * E2];
    d_ctx[b * E2 + h] = acc;
}

__global__ void post_kernel(const float* __restrict__ Wp, const float* __restrict__ bp) {
    const int b = blockIdx.y;
    const int n = blockIdx.x * 256 + threadIdx.x;
    float acc = bp[n];
    const float* c = d_ctx + b * E2;
    for (int k = 0; k < E2; k++) acc += c[k] * Wp[(size_t)k * E2 + n];
    d_ctx2[b * E2 + n] = acc;
}

__global__ void intents_kernel(const float* __restrict__ Wi, const float* __restrict__ bi, float* __restrict__ out) {
    const int b = blockIdx.x, n = threadIdx.x;
    if (n >= NINT) return;
    float acc = bi[n];
    const float* c = d_ctx2 + b * E2;
    for (int k = 0; k < E2; k++) acc += c[k] * Wi[k * NINT + n];
    out[b * NINT + n] = acc;
}

// ---------------- launch ----------------
extern "C" void kernel_launch(void* const* d_in, const int* in_sizes, int n_in,
                              void* d_out, int out_size) {
    const float* X    = (const float*)d_in[0];
    const int*   lens = (const int*)  d_in[1];
    const int s = (n_in >= 23) ? 3 : 2;  // skip is_test if present
    const float* W_reg  = (const float*)d_in[s + 0];
    const float* b_reg  = (const float*)d_in[s + 1];
    const float* Wi0f   = (const float*)d_in[s + 2];
    const float* Wh0f   = (const float*)d_in[s + 3];
    const float* b0f    = (const float*)d_in[s + 4];
    const float* Wi0b   = (const float*)d_in[s + 5];
    const float* Wh0b   = (const float*)d_in[s + 6];
    const float* b0b    = (const float*)d_in[s + 7];
    const float* Wi1f   = (const float*)d_in[s + 8];
    const float* Wh1f   = (const float*)d_in[s + 9];
    const float* b1f    = (const float*)d_in[s + 10];
    const float* Wi1b   = (const float*)d_in[s + 11];
    const float* Wh1b   = (const float*)d_in[s + 12];
    const float* b1b    = (const float*)d_in[s + 13];
    const float* W_keys = (const float*)d_in[s + 14];
    const float* W_en   = (const float*)d_in[s + 15];
    const float* W_post = (const float*)d_in[s + 16];
    const float* b_post = (const float*)d_in[s + 17];
    const float* W_int  = (const float*)d_in[s + 18];
    const float* b_int  = (const float*)d_in[s + 19];

    // launches 0-3: LSTM recurrent-weight transposes
    {
        dim3 g(G4 / 32, HID / 32), b(32, 8);
        transpose_wh<<<g, b>>>(Wh0f, 0);
        transpose_wh<<<g, b>>>(Wh0b, 1);
        transpose_wh<<<g, b>>>(Wh1f, 2);
        transpose_wh<<<g, b>>>(Wh1b, 3);
    }

    // launch 4: reg = X @ W_reg + b_reg
    gemm3<false><<<dim3(DENSE / 128, MT / 128), 256>>>(X, -1, W_reg, b_reg, 0, DENSE, DIN, lens);

    // launch 5 (ncu-captured): layer-0 fwd input projection — the biggest GEMM
    gemm3<false><<<dim3(G4 / 128, MT / 128), 256>>>(nullptr, 0, Wi0f, b0f, 1, G4, DENSE, lens);
    gemm3<false><<<dim3(G4 / 128, MT / 128), 256>>>(nullptr, 0, Wi0b, b0b, 2, G4, DENSE, lens);

    // layer-0 recurrence -> enc0
    lstm_layer<<<128, 384>>>(0, lens);

    // layer-1 input projections
    gemm3<false><<<dim3(G4 / 128, MT / 128), 256>>>(nullptr, 3, Wi1f, b1f, 1, G4, E2, lens);
    gemm3<false><<<dim3(G4 / 128, MT / 128), 256>>>(nullptr, 3, Wi1b, b1b, 2, G4, E2, lens);

    // layer-1 recurrence -> enc1
    lstm_layer<<<128, 384>>>(1, lens);

    // ekey = tanh(enc1 @ W_keys) -> d_xpf
    gemm3<true><<<dim3(E2 / 128, MT / 128), 256>>>(nullptr, 4, W_keys, nullptr, 1, E2, E2, lens);

    // attention tail
    scores_kernel<<<MT / 8, 256>>>(W_en);
    softmax_kernel<<<BATCH, 512>>>(lens);
    context_kernel<<<dim3(E2 / 256, BATCH), 256>>>();
    post_kernel<<<dim3(E2 / 256, BATCH), 256>>>(W_post, b_post);
    intents_kernel<<<BATCH, 64>>>(W_int, b_int, (float*)d_out);
}

// round 6
// speedup vs baseline: 1.1031x; 1.0071x over previous
#include <cuda_runtime.h>
#include <math.h>
#include <stdint.h>

#define BATCH 64
#define SEQ   512
#define DIN   1024
#define DENSE 1024
#define HID   768
#define G4    (4*HID)    // 3072
#define E2    (2*HID)    // 1536
#define NINT  60
#define MT    (BATCH*SEQ) // 32768

// ---------------- static device buffers ----------------
__device__ float d_reg [(size_t)MT * DENSE];
__device__ float d_xpf [(size_t)MT * G4];
__device__ float d_xpb [(size_t)MT * G4];
__device__ float d_enc0[(size_t)MT * E2];
__device__ float d_enc1[(size_t)MT * E2];
__device__ float d_whT [4][(size_t)G4 * HID];   // [layer*2+dir][n][k]
__device__ float d_h   [2][2][BATCH][HID];      // [parity][dir][b][k]
__device__ float d_scores[MT];
__device__ float d_attn  [MT];
__device__ float d_ctx [BATCH * E2];
__device__ float d_ctx2[BATCH * E2];
__device__ unsigned d_bar_cnt = 0;
__device__ volatile unsigned d_bar_gen = 0;

__device__ __forceinline__ float* buf_sel(int s) {
    switch (s) {
        case 0: return d_reg;
        case 1: return d_xpf;
        case 2: return d_xpb;
        case 3: return d_enc0;
        default: return d_enc1;
    }
}

// ---------------- software grid barrier (all blocks co-resident) ----------------
__device__ __forceinline__ void grid_bar() {
    __syncthreads();
    if (threadIdx.x == 0) {
        unsigned gen = d_bar_gen;
        __threadfence();
        unsigned arrived = atomicAdd(&d_bar_cnt, 1u);
        if (arrived == gridDim.x - 1) {
            d_bar_cnt = 0;
            __threadfence();
            d_bar_gen = gen + 1;
        } else {
            while (d_bar_gen == gen) { }
        }
        __threadfence();
    }
    __syncthreads();
}

// ================= FFMA SGEMM (R1 structure + double buffer + skip) ==========
// C[M,N] = act(A[M,K] @ W[K,N] + bias). Tile 128x128, Kt=8, 256 threads,
// 8x8 microtile (4+4 split). Double-buffered smem, ONE sync per k-step,
// only 8 prefetch registers live across compute (no spills at 128-reg cap).
// Whole-block early-out for rows with t >= len[b] (outputs never consumed).
template <bool TANH>
__global__ void __launch_bounds__(256, 2) gemm1(
    const float* __restrict__ Aext, int aSel,
    const float* __restrict__ W, const float* __restrict__ bias,
    int cSel, int N, int K, const int* __restrict__ lens)
{
    const int bm = blockIdx.y * 128;
    if (lens) {
        const int b = bm >> 9, t0 = bm & 511;
        if (t0 >= lens[b]) return;
    }
    const float* __restrict__ A = (aSel < 0) ? Aext : buf_sel(aSel);
    float* __restrict__ C = buf_sel(cSel);

    __shared__ float As[2][8][128];
    __shared__ float Bs[2][8][128];

    const int tid = threadIdx.x;
    const int bn = blockIdx.x * 128;
    const int a_m = tid >> 1;
    const int a_k = (tid & 1) * 4;
    const int b_k = tid >> 5;
    const int b_n = (tid & 31) * 4;
    const int tx = tid & 15;
    const int ty = tid >> 4;

    float acc[8][8];
#pragma unroll
    for (int i = 0; i < 8; i++)
#pragma unroll
        for (int j = 0; j < 8; j++) acc[i][j] = 0.f;

    float4 av, bv;
    auto loadG = [&](int k0) {
        av = *(const float4*)&A[(size_t)(bm + a_m) * K + k0 + a_k];
        bv = *(const float4*)&W[(size_t)(k0 + b_k) * N + bn + b_n];
    };
    auto storeS = [&](int buf) {
        As[buf][a_k + 0][a_m] = av.x;
        As[buf][a_k + 1][a_m] = av.y;
        As[buf][a_k + 2][a_m] = av.z;
        As[buf][a_k + 3][a_m] = av.w;
        *(float4*)&Bs[buf][b_k][b_n] = bv;
    };
    auto compute = [&](int buf) {
#pragma unroll
        for (int kk = 0; kk < 8; kk++) {
            float ar[8], br[8];
            *(float4*)&ar[0] = *(const float4*)&As[buf][kk][ty * 4];
            *(float4*)&ar[4] = *(const float4*)&As[buf][kk][64 + ty * 4];
            *(float4*)&br[0] = *(const float4*)&Bs[buf][kk][tx * 4];
            *(float4*)&br[4] = *(const float4*)&Bs[buf][kk][64 + tx * 4];
#pragma unroll
            for (int i = 0; i < 8; i++)
#pragma unroll
                for (int j = 0; j < 8; j++)
                    acc[i][j] = fmaf(ar[i], br[j], acc[i][j]);
        }
    };

    loadG(0);
    storeS(0);
    __syncthreads();

    const int NT = K >> 3;
    for (int kt = 0; kt < NT; kt++) {
        const int buf = kt & 1;
        const bool more = (kt + 1 < NT);
        if (more) loadG((kt + 1) << 3);
        compute(buf);
        if (more) {
            storeS(buf ^ 1);   // writes the buffer no warp is reading
            __syncthreads();
        }
    }

    // epilogue
#pragma unroll
    for (int hm = 0; hm < 2; hm++) {
#pragma unroll
        for (int i = 0; i < 4; i++) {
            const int row = bm + hm * 64 + ty * 4 + i;
            const int ri = hm * 4 + i;
#pragma unroll
            for (int hn = 0; hn < 2; hn++) {
                const int cb = bn + hn * 64 + tx * 4;
                float4 v;
                v.x = acc[ri][hn * 4 + 0] + (bias ? bias[cb + 0] : 0.f);
                v.y = acc[ri][hn * 4 + 1] + (bias ? bias[cb + 1] : 0.f);
                v.z = acc[ri][hn * 4 + 2] + (bias ? bias[cb + 2] : 0.f);
                v.w = acc[ri][hn * 4 + 3] + (bias ? bias[cb + 3] : 0.f);
                if (TANH) { v.x = tanhf(v.x); v.y = tanhf(v.y); v.z = tanhf(v.z); v.w = tanhf(v.w); }
                *(float4*)&C[(size_t)row * N + cb] = v;
            }
        }
    }
}

// ---------------- Wh transpose: Wt[n][k] = W[k][n], K=768, N=3072 ----------------
__global__ void transpose_wh(const float* __restrict__ W, int widx) {
    __shared__ float tile[32][33];
    float* Wt = d_whT[widx];
    int k0 = blockIdx.y * 32, n0 = blockIdx.x * 32;
    int tx = threadIdx.x, ty = threadIdx.y;
    for (int i = ty; i < 32; i += 8)
        tile[i][tx] = W[(size_t)(k0 + i) * G4 + n0 + tx];
    __syncthreads();
    for (int i = ty; i < 32; i += 8)
        Wt[(size_t)(n0 + i) * HID + k0 + tx] = tile[tx][i];
}

// ---------------- persistent BiLSTM layer (fwd+bwd), 128 blocks x 384 threads ----
// Block = (dir, 16-batch tile, 48-j tile). Thread = 2 batches x j x 4 gates.
// Cell state c lives in registers all 512 steps; h ping-pongs in global.
__global__ void __launch_bounds__(384, 1) lstm_layer(int layer, const int* __restrict__ lens) {
    __shared__ float Hs[16][HID];  // 48KB

    const int tid = threadIdx.x;
    const int dir = blockIdx.x >> 6;
    const int rem = blockIdx.x & 63;
    const int b0 = (rem >> 4) * 16;
    const int jbase = (rem & 15) * 48;
    const int tx = tid % 48;
    const int ty = tid / 48;              // 0..7
    const int j = jbase + tx;
    const int bloc0 = ty * 2;

    const float* xp = dir ? d_xpb : d_xpf;
    const float* whT = d_whT[layer * 2 + dir];
    float* enc = layer ? d_enc1 : d_enc0;

    int myb[2], myL[2];
#pragma unroll
    for (int bi = 0; bi < 2; bi++) {
        myb[bi] = b0 + bloc0 + bi;
        myL[bi] = lens[myb[bi]];
    }
    int maxL = max(myL[0], myL[1]);

    for (int i = tid; i < 16 * 48; i += 384)
        d_h[0][dir][b0 + (i / 48)][jbase + (i % 48)] = 0.f;
    float c2[2] = {0.f, 0.f};
    grid_bar();

    const float* wr0 = whT + (size_t)(0 * HID + j) * HID;
    const float* wr1 = whT + (size_t)(1 * HID + j) * HID;
    const float* wr2 = whT + (size_t)(2 * HID + j) * HID;
    const float* wr3 = whT + (size_t)(3 * HID + j) * HID;

    for (int t = 0; t < SEQ; t++) {
        const int p = t & 1;
        const float4* hsrc = (const float4*)&d_h[p][dir][b0][0];
        float4* hdst = (float4*)&Hs[0][0];
#pragma unroll
        for (int i = 0; i < 8; i++)
            hdst[tid + i * 384] = __ldcg(hsrc + tid + i * 384);
        __syncthreads();

        float acc[2][4];
#pragma unroll
        for (int bi = 0; bi < 2; bi++)
#pragma unroll
            for (int g = 0; g < 4; g++) acc[bi][g] = 0.f;

        if (t < maxL) {
#pragma unroll 2
            for (int k = 0; k < HID; k += 4) {
                float4 w0 = *(const float4*)(wr0 + k);
                float4 w1 = *(const float4*)(wr1 + k);
                float4 w2 = *(const float4*)(wr2 + k);
                float4 w3 = *(const float4*)(wr3 + k);
#pragma unroll
                for (int bi = 0; bi < 2; bi++) {
                    float4 hv = *(const float4*)&Hs[bloc0 + bi][k];
                    acc[bi][0] += hv.x * w0.x + hv.y * w0.y + hv.z * w0.z + hv.w * w0.w;
                    acc[bi][1] += hv.x * w1.x + hv.y * w1.y + hv.z * w1.z + hv.w * w1.w;
                    acc[bi][2] += hv.x * w2.x + hv.y * w2.y + hv.z * w2.z + hv.w * w2.w;
                    acc[bi][3] += hv.x * w3.x + hv.y * w3.y + hv.z * w3.z + hv.w * w3.w;
                }
            }
        }

#pragma unroll
        for (int bi = 0; bi < 2; bi++) {
            const int b = myb[bi];
            const int L = myL[bi];
            const bool alive = (t < L);
            const int src = dir ? (alive ? (L - 1 - t) : t) : t;
            float hold = Hs[bloc0 + bi][j];
            float hnew, outv;
            if (alive) {
                const float* xr = xp + ((size_t)b * SEQ + src) * G4;
                float zi = acc[bi][0] + xr[j];
                float zf = acc[bi][1] + xr[HID + j];
                float zg = acc[bi][2] + xr[2 * HID + j];
                float zo = acc[bi][3] + xr[3 * HID + j];
                float si = 1.f / (1.f + expf(-zi));
                float sf = 1.f / (1.f + expf(-zf));
                float so = 1.f / (1.f + expf(-zo));
                float nc = sf * c2[bi] + si * tanhf(zg);
                c2[bi] = nc;
                hnew = so * tanhf(nc);
                outv = hnew;
            } else {
                hnew = hold;
                outv = 0.f;
            }
            d_h[p ^ 1][dir][b][j] = hnew;
            enc[((size_t)b * SEQ + src) * E2 + dir * HID + j] = outv;
        }
        grid_bar();
    }
}

// ---------------- attention tail ----------------
__global__ void scores_kernel(const float* __restrict__ we) {  // ekey lives in d_xpf
    const int warp = threadIdx.x >> 5, lane = threadIdx.x & 31;
    const size_t row = (size_t)blockIdx.x * 8 + warp;
    const float* r = d_xpf + row * E2;
    float s = 0.f;
    for (int k = lane; k < E2; k += 32) s += r[k] * we[k];
#pragma unroll
    for (int o = 16; o; o >>= 1) s += __shfl_down_sync(0xffffffffu, s, o);
    if (!lane) d_scores[row] = s;
}

__global__ void softmax_kernel(const int* __restrict__ lens) {
    __shared__ float red[512];
    const int b = blockIdx.x, t = threadIdx.x;
    const int L = lens[b];
    float v = (t < L) ? d_scores[b * SEQ + t] : -INFINITY;
    red[t] = v;
    __syncthreads();
    for (int s = 256; s > 0; s >>= 1) { if (t < s) red[t] = fmaxf(red[t], red[t + s]); __syncthreads(); }
    float m = red[0];
    __syncthreads();
    float e = (t < L) ? expf(v - m) : 0.f;
    red[t] = e;
    __syncthreads();
    for (int s = 256; s > 0; s >>= 1) { if (t < s) red[t] += red[t + s]; __syncthreads(); }
    d_attn[b * SEQ + t] = e / red[0];
}

__global__ void context_kernel() {
    const int b = blockIdx.y;
    const int h = blockIdx.x * 256 + threadIdx.x;
    float acc = 0.f;
    const float* a = d_attn + b * SEQ;
    const float* e = d_enc1 + (size_t)b * SEQ * E2 + h;
    for (int t = 0; t < SEQ; t++) acc += a[t] * e[(size_t)t * E2];
    d_ctx[b * E2 + h] = acc;
}

__global__ void post_kernel(const float* __restrict__ Wp, const float* __restrict__ bp) {
    const int b = blockIdx.y;
    const int n = blockIdx.x * 256 + threadIdx.x;
    float acc = bp[n];
    const float* c = d_ctx + b * E2;
    for (int k = 0; k < E2; k++) acc += c[k] * Wp[(size_t)k * E2 + n];
    d_ctx2[b * E2 + n] = acc;
}

__global__ void intents_kernel(const float* __restrict__ Wi, const float* __restrict__ bi, float* __restrict__ out) {
    const int b = blockIdx.x, n = threadIdx.x;
    if (n >= NINT) return;
    float acc = bi[n];
    const float* c = d_ctx2 + b * E2;
    for (int k = 0; k < E2; k++) acc += c[k] * Wi[k * NINT + n];
    out[b * NINT + n] = acc;
}

// ---------------- launch ----------------
extern "C" void kernel_launch(void* const* d_in, const int* in_sizes, int n_in,
                              void* d_out, int out_size) {
    const float* X    = (const float*)d_in[0];
    const int*   lens = (const int*)  d_in[1];
    const int s = (n_in >= 23) ? 3 : 2;  // skip is_test if present
    const float* W_reg  = (const float*)d_in[s + 0];
    const float* b_reg  = (const float*)d_in[s + 1];
    const float* Wi0f   = (const float*)d_in[s + 2];
    const float* Wh0f   = (const float*)d_in[s + 3];
    const float* b0f    = (const float*)d_in[s + 4];
    const float* Wi0b   = (const float*)d_in[s + 5];
    const float* Wh0b   = (const float*)d_in[s + 6];
    const float* b0b    = (const float*)d_in[s + 7];
    const float* Wi1f   = (const float*)d_in[s + 8];
    const float* Wh1f   = (const float*)d_in[s + 9];
    const float* b1f    = (const float*)d_in[s + 10];
    const float* Wi1b   = (const float*)d_in[s + 11];
    const float* Wh1b   = (const float*)d_in[s + 12];
    const float* b1b    = (const float*)d_in[s + 13];
    const float* W_keys = (const float*)d_in[s + 14];
    const float* W_en   = (const float*)d_in[s + 15];
    const float* W_post = (const float*)d_in[s + 16];
    const float* b_post = (const float*)d_in[s + 17];
    const float* W_int  = (const float*)d_in[s + 18];
    const float* b_int  = (const float*)d_in[s + 19];

    // LSTM recurrent-weight transposes
    {
        dim3 g(G4 / 32, HID / 32), b(32, 8);
        transpose_wh<<<g, b>>>(Wh0f, 0);
        transpose_wh<<<g, b>>>(Wh0b, 1);
        transpose_wh<<<g, b>>>(Wh1f, 2);
        transpose_wh<<<g, b>>>(Wh1b, 3);
    }

    // reg = X @ W_reg + b_reg
    gemm1<false><<<dim3(DENSE / 128, MT / 128), 256>>>(X, -1, W_reg, b_reg, 0, DENSE, DIN, lens);

    // layer-0 input projections
    gemm1<false><<<dim3(G4 / 128, MT / 128), 256>>>(nullptr, 0, Wi0f, b0f, 1, G4, DENSE, lens);
    gemm1<false><<<dim3(G4 / 128, MT / 128), 256>>>(nullptr, 0, Wi0b, b0b, 2, G4, DENSE, lens);

    // layer-0 recurrence -> enc0
    lstm_layer<<<128, 384>>>(0, lens);

    // layer-1 input projections
    gemm1<false><<<dim3(G4 / 128, MT / 128), 256>>>(nullptr, 3, Wi1f, b1f, 1, G4, E2, lens);
    gemm1<false><<<dim3(G4 / 128, MT / 128), 256>>>(nullptr, 3, Wi1b, b1b, 2, G4, E2, lens);

    // layer-1 recurrence -> enc1
    lstm_layer<<<128, 384>>>(1, lens);

    // ekey = tanh(enc1 @ W_keys) -> d_xpf
    gemm1<true><<<dim3(E2 / 128, MT / 128), 256>>>(nullptr, 4, W_keys, nullptr, 1, E2, E2, lens);

    // attention tail
    scores_kernel<<<MT / 8, 256>>>(W_en);
    softmax_kernel<<<BATCH, 512>>>(lens);
    context_kernel<<<dim3(E2 / 256, BATCH), 256>>>();
    post_kernel<<<dim3(E2 / 256, BATCH), 256>>>(W_post, b_post);
    intents_kernel<<<BATCH, 64>>>(W_int, b_int, (float*)d_out);
}

// round 7
// speedup vs baseline: 1.7014x; 1.5424x over previous
#include <cuda_runtime.h>
#include <math.h>
#include <stdint.h>

#define BATCH 64
#define SEQ   512
#define DIN   1024
#define DENSE 1024
#define HID   768
#define G4    (4*HID)    // 3072
#define E2    (2*HID)    // 1536
#define NINT  60
#define MT    (BATCH*SEQ) // 32768

// ---------------- static device buffers ----------------
__device__ float d_reg [(size_t)MT * DENSE];
__device__ float d_xpf [(size_t)MT * G4];
__device__ float d_xpb [(size_t)MT * G4];
__device__ float d_enc0[(size_t)MT * E2];
__device__ float d_enc1[(size_t)MT * E2];
__device__ float d_whT [4][(size_t)G4 * HID];   // [layer*2+dir][n][k]
__device__ float d_h   [2][2][BATCH][HID];      // [parity][dir][b][k]
__device__ float d_scores[MT];
__device__ float d_attn  [MT];
__device__ float d_ctx [BATCH * E2];
__device__ float d_ctx2[BATCH * E2];
__device__ unsigned d_bar_cnt = 0;
__device__ volatile unsigned d_bar_gen = 0;

__device__ __forceinline__ float* buf_sel(int s) {
    switch (s) {
        case 0: return d_reg;
        case 1: return d_xpf;
        case 2: return d_xpb;
        case 3: return d_enc0;
        default: return d_enc1;
    }
}

// ---------------- cp.async helpers (Ampere+ base ISA, ok on compute_103) ------
__device__ __forceinline__ uint32_t sptr(const void* p) {
    return (uint32_t)__cvta_generic_to_shared(p);
}
__device__ __forceinline__ void cpa16(uint32_t d, const void* s) {
    asm volatile("cp.async.cg.shared.global [%0], [%1], 16;" :: "r"(d), "l"(s));
}
__device__ __forceinline__ void cpa8(uint32_t d, const void* s) {
    asm volatile("cp.async.ca.shared.global [%0], [%1], 8;" :: "r"(d), "l"(s));
}
#define CPA_COMMIT() asm volatile("cp.async.commit_group;")
#define CPA_WAIT(n)  asm volatile("cp.async.wait_group %0;" :: "n"(n))

// ---------------- software grid barrier (all blocks co-resident) ----------------
__device__ __forceinline__ void grid_bar() {
    __syncthreads();
    if (threadIdx.x == 0) {
        unsigned gen = d_bar_gen;
        __threadfence();
        unsigned arrived = atomicAdd(&d_bar_cnt, 1u);
        if (arrived == gridDim.x - 1) {
            d_bar_cnt = 0;
            __threadfence();
            d_bar_gen = gen + 1;
        } else {
            while (d_bar_gen == gen) { }
        }
        __threadfence();
    }
    __syncthreads();
}

// ================= cp.async pipelined FFMA SGEMM =================
// C[M,N] = act(A[M,K] @ W[K,N] + bias). Tile 128x128, Kt=8, 256 threads,
// 8x8 microtile (4+4 split). 4-stage cp.async pipeline: 3 tile-loads always
// in flight, zero prefetch registers live across compute.
// A smem: row-major, 40B row stride -> conflict-free broadcast LDS.32.
// B smem: [k][n] rows of 512B -> LDS.128 as in R1.
// Whole-block early-out for rows with t >= len[b] (outputs never consumed).
#define STAGES 4
#define A_ROWB 40                      // bytes per A row (32 data + 8 pad)
#define A_STG  (128 * A_ROWB)          // 5120 B per stage
#define B_STG  (8 * 512)               // 4096 B per stage

template <bool TANH>
__global__ void __launch_bounds__(256) gemmca(
    const float* __restrict__ Aext, int aSel,
    const float* __restrict__ W, const float* __restrict__ bias,
    int cSel, int N, int K, const int* __restrict__ lens)
{
    const int bm = blockIdx.y * 128;
    if (lens) {
        const int b = bm >> 9, t0 = bm & 511;
        if (t0 >= lens[b]) return;
    }
    const float* __restrict__ A = (aSel < 0) ? Aext : buf_sel(aSel);
    float* __restrict__ C = buf_sel(cSel);

    __shared__ __align__(16) char Asm[STAGES * A_STG];
    __shared__ __align__(16) char Bsm[STAGES * B_STG];

    const int tid = threadIdx.x;
    const int bn = blockIdx.x * 128;
    const int tx = tid & 15;
    const int ty = tid >> 4;

    const uint32_t aBase = sptr(Asm);
    const uint32_t bBase = sptr(Bsm);

    // staging indices
    const int a_r0 = tid >> 2, a_c0 = tid & 3;          // chunk ids tid, tid+256
    const int a_r1 = (tid + 256) >> 2, a_c1 = (tid + 256) & 3;
    const int b_kr = tid >> 5, b_n4 = tid & 31;

    float acc[8][8];
#pragma unroll
    for (int i = 0; i < 8; i++)
#pragma unroll
        for (int j = 0; j < 8; j++) acc[i][j] = 0.f;

    const int NT = K >> 3;

    auto stage = [&](int kt) {
        const int buf = kt & (STAGES - 1);
        const int k0 = kt << 3;
        const uint32_t ab = aBase + buf * A_STG;
        cpa8(ab + a_r0 * A_ROWB + a_c0 * 8, &A[(size_t)(bm + a_r0) * K + k0 + a_c0 * 2]);
        cpa8(ab + a_r1 * A_ROWB + a_c1 * 8, &A[(size_t)(bm + a_r1) * K + k0 + a_c1 * 2]);
        const uint32_t bb = bBase + buf * B_STG;
        cpa16(bb + b_kr * 512 + b_n4 * 16, &W[(size_t)(k0 + b_kr) * N + bn + b_n4 * 4]);
    };

    // prologue: fill STAGES-1 stages
#pragma unroll
    for (int i = 0; i < STAGES - 1; i++) {
        stage(i);
        CPA_COMMIT();
    }

    for (int kt = 0; kt < NT; kt++) {
        if (kt + STAGES - 1 < NT) stage(kt + STAGES - 1);
        CPA_COMMIT();                 // unconditional: keeps group count aligned
        CPA_WAIT(STAGES - 1);         // group kt complete
        __syncthreads();

        const int buf = kt & (STAGES - 1);
        const char* as = Asm + buf * A_STG;
        const float* bs = (const float*)(Bsm + buf * B_STG);
#pragma unroll
        for (int kk = 0; kk < 8; kk++) {
            float ar[8], br[8];
#pragma unroll
            for (int i = 0; i < 4; i++) {
                ar[i]     = *(const float*)(as + (ty * 4 + i) * A_ROWB + kk * 4);
                ar[4 + i] = *(const float*)(as + (64 + ty * 4 + i) * A_ROWB + kk * 4);
            }
            *(float4*)&br[0] = *(const float4*)&bs[kk * 128 + tx * 4];
            *(float4*)&br[4] = *(const float4*)&bs[kk * 128 + 64 + tx * 4];
#pragma unroll
            for (int i = 0; i < 8; i++)
#pragma unroll
                for (int j = 0; j < 8; j++)
                    acc[i][j] = fmaf(ar[i], br[j], acc[i][j]);
        }
        __syncthreads();              // buffer kt reused at iteration kt+1's stage
    }

    // epilogue
#pragma unroll
    for (int hm = 0; hm < 2; hm++) {
#pragma unroll
        for (int i = 0; i < 4; i++) {
            const int row = bm + hm * 64 + ty * 4 + i;
            const int ri = hm * 4 + i;
#pragma unroll
            for (int hn = 0; hn < 2; hn++) {
                const int cb = bn + hn * 64 + tx * 4;
                float4 v;
                v.x = acc[ri][hn * 4 + 0] + (bias ? bias[cb + 0] : 0.f);
                v.y = acc[ri][hn * 4 + 1] + (bias ? bias[cb + 1] : 0.f);
                v.z = acc[ri][hn * 4 + 2] + (bias ? bias[cb + 2] : 0.f);
                v.w = acc[ri][hn * 4 + 3] + (bias ? bias[cb + 3] : 0.f);
                if (TANH) { v.x = tanhf(v.x); v.y = tanhf(v.y); v.z = tanhf(v.z); v.w = tanhf(v.w); }
                *(float4*)&C[(size_t)row * N + cb] = v;
            }
        }
    }
}

// ---------------- Wh transpose: Wt[n][k] = W[k][n], K=768, N=3072 ----------------
__global__ void transpose_wh(const float* __restrict__ W, int widx) {
    __shared__ float tile[32][33];
    float* Wt = d_whT[widx];
    int k0 = blockIdx.y * 32, n0 = blockIdx.x * 32;
    int tx = threadIdx.x, ty = threadIdx.y;
    for (int i = ty; i < 32; i += 8)
        tile[i][tx] = W[(size_t)(k0 + i) * G4 + n0 + tx];
    __syncthreads();
    for (int i = ty; i < 32; i += 8)
        Wt[(size_t)(n0 + i) * HID + k0 + tx] = tile[tx][i];
}

// ---------------- persistent BiLSTM layer — EXACT R1 version -------------------
// 128 blocks x 192 threads. Block = (dir, 16-batch tile, 48-j tile).
// Thread = 4 batches x j x 4 gates. c in registers; h ping-pongs in global.
__global__ void __launch_bounds__(192, 1) lstm_layer(int layer, const int* __restrict__ lens) {
    __shared__ float Hs[16][HID];  // 48KB

    const int tid = threadIdx.x;
    const int dir = blockIdx.x >> 6;
    const int rem = blockIdx.x & 63;
    const int b0 = (rem >> 4) * 16;
    const int jbase = (rem & 15) * 48;
    const int tx = tid % 48;
    const int ty = tid / 48;              // 0..3
    const int j = jbase + tx;
    const int bloc0 = ty * 4;

    const float* xp = dir ? d_xpb : d_xpf;
    const float* whT = d_whT[layer * 2 + dir];
    float* enc = layer ? d_enc1 : d_enc0;

    int myb[4], myL[4];
#pragma unroll
    for (int bi = 0; bi < 4; bi++) {
        myb[bi] = b0 + bloc0 + bi;
        myL[bi] = lens[myb[bi]];
    }
    int maxL = max(max(myL[0], myL[1]), max(myL[2], myL[3]));

    for (int i = tid; i < 16 * 48; i += 192)
        d_h[0][dir][b0 + (i / 48)][jbase + (i % 48)] = 0.f;
    float c4[4] = {0.f, 0.f, 0.f, 0.f};
    grid_bar();

    const float* wr0 = whT + (size_t)(0 * HID + j) * HID;
    const float* wr1 = whT + (size_t)(1 * HID + j) * HID;
    const float* wr2 = whT + (size_t)(2 * HID + j) * HID;
    const float* wr3 = whT + (size_t)(3 * HID + j) * HID;

    for (int t = 0; t < SEQ; t++) {
        const int p = t & 1;
        const float4* hsrc = (const float4*)&d_h[p][dir][b0][0];
        float4* hdst = (float4*)&Hs[0][0];
        for (int i = tid; i < (16 * HID) / 4; i += 192)
            hdst[i] = __ldcg(hsrc + i);
        __syncthreads();

        float acc[4][4];
#pragma unroll
        for (int bi = 0; bi < 4; bi++)
#pragma unroll
            for (int g = 0; g < 4; g++) acc[bi][g] = 0.f;

        if (t < maxL) {
#pragma unroll 2
            for (int k = 0; k < HID; k += 4) {
                float4 w0 = *(const float4*)(wr0 + k);
                float4 w1 = *(const float4*)(wr1 + k);
                float4 w2 = *(const float4*)(wr2 + k);
                float4 w3 = *(const float4*)(wr3 + k);
#pragma unroll
                for (int bi = 0; bi < 4; bi++) {
                    float4 hv = *(const float4*)&Hs[bloc0 + bi][k];
                    acc[bi][0] += hv.x * w0.x + hv.y * w0.y + hv.z * w0.z + hv.w * w0.w;
                    acc[bi][1] += hv.x * w1.x + hv.y * w1.y + hv.z * w1.z + hv.w * w1.w;
                    acc[bi][2] += hv.x * w2.x + hv.y * w2.y + hv.z * w2.z + hv.w * w2.w;
                    acc[bi][3] += hv.x * w3.x + hv.y * w3.y + hv.z * w3.z + hv.w * w3.w;
                }
            }
        }

#pragma unroll
        for (int bi = 0; bi < 4; bi++) {
            const int b = myb[bi];
            const int L = myL[bi];
            const bool alive = (t < L);
            const int src = dir ? (alive ? (L - 1 - t) : t) : t;
            float hold = Hs[bloc0 + bi][j];
            float hnew, outv;
            if (alive) {
                const float* xr = xp + ((size_t)b * SEQ + src) * G4;
                float zi = acc[bi][0] + xr[j];
                float zf = acc[bi][1] + xr[HID + j];
                float zg = acc[bi][2] + xr[2 * HID + j];
                float zo = acc[bi][3] + xr[3 * HID + j];
                float si = 1.f / (1.f + expf(-zi));
                float sf = 1.f / (1.f + expf(-zf));
                float so = 1.f / (1.f + expf(-zo));
                float nc = sf * c4[bi] + si * tanhf(zg);
                c4[bi] = nc;
                hnew = so * tanhf(nc);
                outv = hnew;
            } else {
                hnew = hold;
                outv = 0.f;
            }
            d_h[p ^ 1][dir][b][j] = hnew;
            enc[((size_t)b * SEQ + src) * E2 + dir * HID + j] = outv;
        }
        grid_bar();
    }
}

// ---------------- attention tail ----------------
__global__ void scores_kernel(const float* __restrict__ we) {  // ekey lives in d_xpf
    const int warp = threadIdx.x >> 5, lane = threadIdx.x & 31;
    const size_t row = (size_t)blockIdx.x * 8 + warp;
    const float* r = d_xpf + row * E2;
    float s = 0.f;
    for (int k = lane; k < E2; k += 32) s += r[k] * we[k];
#pragma unroll
    for (int o = 16; o; o >>= 1) s += __shfl_down_sync(0xffffffffu, s, o);
    if (!lane) d_scores[row] = s;
}

__global__ void softmax_kernel(const int* __restrict__ lens) {
    __shared__ float red[512];
    const int b = blockIdx.x, t = threadIdx.x;
    const int L = lens[b];
    float v = (t < L) ? d_scores[b * SEQ + t] : -INFINITY;
    red[t] = v;
    __syncthreads();
    for (int s = 256; s > 0; s >>= 1) { if (t < s) red[t] = fmaxf(red[t], red[t + s]); __syncthreads(); }
    float m = red[0];
    __syncthreads();
    float e = (t < L) ? expf(v - m) : 0.f;
    red[t] = e;
    __syncthreads();
    for (int s = 256; s > 0; s >>= 1) { if (t < s) red[t] += red[t + s]; __syncthreads(); }
    d_attn[b * SEQ + t] = e / red[0];
}

__global__ void context_kernel() {
    const int b = blockIdx.y;
    const int h = blockIdx.x * 256 + threadIdx.x;
    float acc = 0.f;
    const float* a = d_attn + b * SEQ;
    const float* e = d_enc1 + (size_t)b * SEQ * E2 + h;
    for (int t = 0; t < SEQ; t++) acc += a[t] * e[(size_t)t * E2];
    d_ctx[b * E2 + h] = acc;
}

__global__ void post_kernel(const float* __restrict__ Wp, const float* __restrict__ bp) {
    const int b = blockIdx.y;
    const int n = blockIdx.x * 256 + threadIdx.x;
    float acc = bp[n];
    const float* c = d_ctx + b * E2;
    for (int k = 0; k < E2; k++) acc += c[k] * Wp[(size_t)k * E2 + n];
    d_ctx2[b * E2 + n] = acc;
}

__global__ void intents_kernel(const float* __restrict__ Wi, const float* __restrict__ bi, float* __restrict__ out) {
    const int b = blockIdx.x, n = threadIdx.x;
    if (n >= NINT) return;
    float acc = bi[n];
    const float* c = d_ctx2 + b * E2;
    for (int k = 0; k < E2; k++) acc += c[k] * Wi[k * NINT + n];
    out[b * NINT + n] = acc;
}

// ---------------- launch ----------------
extern "C" void kernel_launch(void* const* d_in, const int* in_sizes, int n_in,
                              void* d_out, int out_size) {
    const float* X    = (const float*)d_in[0];
    const int*   lens = (const int*)  d_in[1];
    const int s = (n_in >= 23) ? 3 : 2;  // skip is_test if present
    const float* W_reg  = (const float*)d_in[s + 0];
    const float* b_reg  = (const float*)d_in[s + 1];
    const float* Wi0f   = (const float*)d_in[s + 2];
    const float* Wh0f   = (const float*)d_in[s + 3];
    const float* b0f    = (const float*)d_in[s + 4];
    const float* Wi0b   = (const float*)d_in[s + 5];
    const float* Wh0b   = (const float*)d_in[s + 6];
    const float* b0b    = (const float*)d_in[s + 7];
    const float* Wi1f   = (const float*)d_in[s + 8];
    const float* Wh1f   = (const float*)d_in[s + 9];
    const float* b1f    = (const float*)d_in[s + 10];
    const float* Wi1b   = (const float*)d_in[s + 11];
    const float* Wh1b   = (const float*)d_in[s + 12];
    const float* b1b    = (const float*)d_in[s + 13];
    const float* W_keys = (const float*)d_in[s + 14];
    const float* W_en   = (const float*)d_in[s + 15];
    const float* W_post = (const float*)d_in[s + 16];
    const float* b_post = (const float*)d_in[s + 17];
    const float* W_int  = (const float*)d_in[s + 18];
    const float* b_int  = (const float*)d_in[s + 19];

    // launch 0 (ncu-visible first kernel of the graph): the big reg GEMM
    gemmca<false><<<dim3(DENSE / 128, MT / 128), 256>>>(X, -1, W_reg, b_reg, 0, DENSE, DIN, lens);

    // LSTM recurrent-weight transposes (independent of gemm above)
    {
        dim3 g(G4 / 32, HID / 32), b(32, 8);
        transpose_wh<<<g, b>>>(Wh0f, 0);
        transpose_wh<<<g, b>>>(Wh0b, 1);
        transpose_wh<<<g, b>>>(Wh1f, 2);
        transpose_wh<<<g, b>>>(Wh1b, 3);
    }

    // layer-0 input projections
    gemmca<false><<<dim3(G4 / 128, MT / 128), 256>>>(nullptr, 0, Wi0f, b0f, 1, G4, DENSE, lens);
    gemmca<false><<<dim3(G4 / 128, MT / 128), 256>>>(nullptr, 0, Wi0b, b0b, 2, G4, DENSE, lens);

    // layer-0 recurrence -> enc0
    lstm_layer<<<128, 192>>>(0, lens);

    // layer-1 input projections
    gemmca<false><<<dim3(G4 / 128, MT / 128), 256>>>(nullptr, 3, Wi1f, b1f, 1, G4, E2, lens);
    gemmca<false><<<dim3(G4 / 128, MT / 128), 256>>>(nullptr, 3, Wi1b, b1b, 2, G4, E2, lens);

    // layer-1 recurrence -> enc1
    lstm_layer<<<128, 192>>>(1, lens);

    // ekey = tanh(enc1 @ W_keys) -> d_xpf
    gemmca<true><<<dim3(E2 / 128, MT / 128), 256>>>(nullptr, 4, W_keys, nullptr, 1, E2, E2, lens);

    // attention tail
    scores_kernel<<<MT / 8, 256>>>(W_en);
    softmax_kernel<<<BATCH, 512>>>(lens);
    context_kernel<<<dim3(E2 / 256, BATCH), 256>>>();
    post_kernel<<<dim3(E2 / 256, BATCH), 256>>>(W_post, b_post);
    intents_kernel<<<BATCH, 64>>>(W_int, b_int, (float*)d_out);
}

// round 9
// speedup vs baseline: 3.2580x; 1.9149x over previous
#include <cuda_runtime.h>
#include <math.h>
#include <stdint.h>

#define BATCH 64
#define SEQ   512
#define DIN   1024
#define DENSE 1024
#define HID   768
#define G4    (4*HID)    // 3072
#define E2    (2*HID)    // 1536
#define NINT  60
#define MT    (BATCH*SEQ) // 32768

// ---------------- static device buffers ----------------
__device__ float d_reg [(size_t)MT * DENSE];
__device__ float d_xpf [(size_t)MT * G4];
__device__ float d_xpb [(size_t)MT * G4];
__device__ float d_enc0[(size_t)MT * E2];
__device__ float d_enc1[(size_t)MT * E2];
// blocked recurrent weights: [(ld*16+jt)*48+kc] chunks of 768 float4
// chunk layout: idx = (g*4+kq)*48 + jl ; float4 spans k = kc*16+kq*4 .. +3
__device__ float4 d_wblk4[(size_t)4 * 16 * 48 * 768];
__device__ float d_h   [2][2][BATCH][HID];      // [parity][dir][b][k]
__device__ float d_scores[MT];
__device__ float d_attn  [MT];
__device__ float d_ctx [BATCH * E2];
__device__ float d_ctx2[BATCH * E2];
__device__ unsigned d_bar_cnt = 0;
__device__ volatile unsigned d_bar_gen = 0;

__device__ __forceinline__ float* buf_sel(int s) {
    switch (s) {
        case 0: return d_reg;
        case 1: return d_xpf;
        case 2: return d_xpb;
        case 3: return d_enc0;
        default: return d_enc1;
    }
}

// ---------------- software grid barrier (all blocks co-resident) ----------------
__device__ __forceinline__ void grid_bar() {
    __syncthreads();
    if (threadIdx.x == 0) {
        unsigned gen = d_bar_gen;
        __threadfence();
        unsigned arrived = atomicAdd(&d_bar_cnt, 1u);
        if (arrived == gridDim.x - 1) {
            d_bar_cnt = 0;
            __threadfence();
            d_bar_gen = gen + 1;
        } else {
            while (d_bar_gen == gen) { }
        }
        __threadfence();
    }
    __syncthreads();
}

// ================= FFMA SGEMM — EXACT R1 structure + dead-block skip ==========
// C[M,N] = act(A[M,K] @ W[K,N] + bias). Tile 128x128, Kt=8, 256 threads,
// 8x8 microtile (4+4 split).
template <bool TANH>
__global__ void __launch_bounds__(256) gemm1(
    const float* __restrict__ Aext, int aSel,
    const float* __restrict__ W, const float* __restrict__ bias,
    int cSel, int N, int K, const int* __restrict__ lens)
{
    const int bm = blockIdx.y * 128;
    if (lens) {
        const int b = bm >> 9, t0 = bm & 511;
        if (t0 >= lens[b]) return;   // dead rows: outputs never consumed
    }
    const float* __restrict__ A = (aSel < 0) ? Aext : buf_sel(aSel);
    float* __restrict__ C = buf_sel(cSel);

    __shared__ float As[8][128];
    __shared__ float Bs[8][128];

    const int tid = threadIdx.x;
    const int bn = blockIdx.x * 128;
    const int a_m = tid >> 1;
    const int a_k = (tid & 1) * 4;
    const int b_k = tid >> 5;
    const int b_n = (tid & 31) * 4;
    const int tx = tid & 15;
    const int ty = tid >> 4;

    float acc[8][8];
#pragma unroll
    for (int i = 0; i < 8; i++)
#pragma unroll
        for (int j = 0; j < 8; j++) acc[i][j] = 0.f;

    for (int k0 = 0; k0 < K; k0 += 8) {
        float4 av = *(const float4*)&A[(size_t)(bm + a_m) * K + k0 + a_k];
        As[a_k + 0][a_m] = av.x;
        As[a_k + 1][a_m] = av.y;
        As[a_k + 2][a_m] = av.z;
        As[a_k + 3][a_m] = av.w;
        *(float4*)&Bs[b_k][b_n] = *(const float4*)&W[(size_t)(k0 + b_k) * N + bn + b_n];
        __syncthreads();
#pragma unroll
        for (int kk = 0; kk < 8; kk++) {
            float ar[8], br[8];
            *(float4*)&ar[0] = *(const float4*)&As[kk][ty * 4];
            *(float4*)&ar[4] = *(const float4*)&As[kk][64 + ty * 4];
            *(float4*)&br[0] = *(const float4*)&Bs[kk][tx * 4];
            *(float4*)&br[4] = *(const float4*)&Bs[kk][64 + tx * 4];
#pragma unroll
            for (int i = 0; i < 8; i++)
#pragma unroll
                for (int j = 0; j < 8; j++)
                    acc[i][j] = fmaf(ar[i], br[j], acc[i][j]);
        }
        __syncthreads();
    }

#pragma unroll
    for (int hm = 0; hm < 2; hm++) {
#pragma unroll
        for (int i = 0; i < 4; i++) {
            int r = bm + hm * 64 + ty * 4 + i;
            int ri = hm * 4 + i;
#pragma unroll
            for (int hn = 0; hn < 2; hn++) {
                int cb = bn + hn * 64 + tx * 4;
                float4 v;
                v.x = acc[ri][hn * 4 + 0] + (bias ? bias[cb + 0] : 0.f);
                v.y = acc[ri][hn * 4 + 1] + (bias ? bias[cb + 1] : 0.f);
                v.z = acc[ri][hn * 4 + 2] + (bias ? bias[cb + 2] : 0.f);
                v.w = acc[ri][hn * 4 + 3] + (bias ? bias[cb + 3] : 0.f);
                if (TANH) { v.x = tanhf(v.x); v.y = tanhf(v.y); v.z = tanhf(v.z); v.w = tanhf(v.w); }
                *(float4*)&C[(size_t)r * N + cb] = v;
            }
        }
    }
}

// ---------------- build blocked recurrent weights ------------------------------
// 3072 blocks x 192 threads; block = (ld, jt, kc); thread writes 4 float4.
__global__ void conv_wblk(const float* __restrict__ W0, const float* __restrict__ W1,
                          const float* __restrict__ W2, const float* __restrict__ W3) {
    const int bid = blockIdx.x;
    const int ld = bid / 768, r = bid % 768, jt = r / 48, kc = r % 48;
    const float* W = (ld == 0) ? W0 : (ld == 1) ? W1 : (ld == 2) ? W2 : W3;
    float4* dst = d_wblk4 + ((size_t)(ld * 16 + jt) * 48 + kc) * 768;
#pragma unroll
    for (int q = 0; q < 4; q++) {
        int c = threadIdx.x + 192 * q;
        int jl = c % 48;
        int gq = c / 48;          // 0..15
        int g = gq >> 2, kq = gq & 3;
        int n = g * HID + jt * 48 + jl;
        int k = kc * 16 + kq * 4;
        float4 v;
        v.x = W[(size_t)(k + 0) * G4 + n];
        v.y = W[(size_t)(k + 1) * G4 + n];
        v.z = W[(size_t)(k + 2) * G4 + n];
        v.w = W[(size_t)(k + 3) * G4 + n];
        dst[c] = v;
    }
}

// ---------------- persistent BiLSTM layer v2 (barrier-safe) ---------------------
// 128 blocks x 192 threads. Block = (dir, 16-batch tile, 48-j tile).
// Thread = 4 batches x j x 4 gates; c in registers; h ping-pongs in global.
// Recurrent weights streamed coalesced via double-buffered smem chunks (16 k each).
// The weight-stream skip predicate (blockMaxL) is BLOCK-UNIFORM: computed over
// all 16 batches of the block, so the barriers inside never diverge.
#define HS4   193                 // float4 per Hs row (772 floats)
#define WOFF  (16 * HS4)          // 3088 float4
#define LSTM_SMEM ((WOFF + 2 * 768) * 16)

__global__ void __launch_bounds__(192, 1) lstm_layer(int layer, const int* __restrict__ lens) {
    extern __shared__ float4 sm4[];
    float4* Hs  = sm4;                 // [16][HS4]
    float4* Wb0 = sm4 + WOFF;          // [768]
    float4* Wb1 = sm4 + WOFF + 768;    // [768]

    const int tid = threadIdx.x;
    const int dir = blockIdx.x >> 6;
    const int rem = blockIdx.x & 63;
    const int b0 = (rem >> 4) * 16;
    const int jt = rem & 15;
    const int jbase = jt * 48;
    const int tx = tid % 48;
    const int ty = tid / 48;           // 0..3
    const int j = jbase + tx;
    const int bloc0 = ty * 4;

    const float* xp = dir ? d_xpb : d_xpf;
    float* enc = layer ? d_enc1 : d_enc0;
    const float4* wsrc = d_wblk4 + ((size_t)((layer * 2 + dir) * 16 + jt) * 48) * 768;

    int myb[4], myL[4];
#pragma unroll
    for (int bi = 0; bi < 4; bi++) {
        myb[bi] = b0 + bloc0 + bi;
        myL[bi] = lens[myb[bi]];
    }
    // BLOCK-UNIFORM max length over all 16 batches of this block
    int blockMaxL = 0;
#pragma unroll
    for (int i = 0; i < 16; i++) blockMaxL = max(blockMaxL, lens[b0 + i]);

    for (int i = tid; i < 16 * 48; i += 192)
        d_h[0][dir][b0 + (i / 48)][jbase + (i % 48)] = 0.f;
    float c4[4] = {0.f, 0.f, 0.f, 0.f};
    grid_bar();

    for (int t = 0; t < SEQ; t++) {
        const int p = t & 1;
        // h snapshot: 16 rows x 192 float4, padded rows (HS4=193)
        const float4* hsrc = (const float4*)&d_h[p][dir][b0][0];
#pragma unroll
        for (int b = 0; b < 16; b++)
            Hs[b * HS4 + tid] = __ldcg(hsrc + b * 192 + tid);
        __syncthreads();

        float acc[4][4];
#pragma unroll
        for (int bi = 0; bi < 4; bi++)
#pragma unroll
            for (int g = 0; g < 4; g++) acc[bi][g] = 0.f;

        if (t < blockMaxL) {          // uniform predicate -> barriers below are safe
            // prologue: stage chunk 0
            float4 pf0 = wsrc[tid];
            float4 pf1 = wsrc[tid + 192];
            float4 pf2 = wsrc[tid + 384];
            float4 pf3 = wsrc[tid + 576];
            Wb0[tid] = pf0; Wb0[tid + 192] = pf1;
            Wb0[tid + 384] = pf2; Wb0[tid + 576] = pf3;
            __syncthreads();

            for (int c = 0; c < 48; c++) {
                const float4* Wc = (c & 1) ? Wb1 : Wb0;
                float4* Wn = (c & 1) ? Wb0 : Wb1;
                const bool more = (c + 1 < 48);
                if (more) {
                    const float4* s = wsrc + (size_t)(c + 1) * 768;
                    pf0 = s[tid];       pf1 = s[tid + 192];
                    pf2 = s[tid + 384]; pf3 = s[tid + 576];
                }
#pragma unroll
                for (int kq = 0; kq < 4; kq++) {
                    const float4 w0 = Wc[(0 * 4 + kq) * 48 + tx];
                    const float4 w1 = Wc[(1 * 4 + kq) * 48 + tx];
                    const float4 w2 = Wc[(2 * 4 + kq) * 48 + tx];
                    const float4 w3 = Wc[(3 * 4 + kq) * 48 + tx];
                    const int kk = c * 4 + kq;
#pragma unroll
                    for (int bi = 0; bi < 4; bi++) {
                        const float4 hv = Hs[(bloc0 + bi) * HS4 + kk];
                        acc[bi][0] += hv.x * w0.x + hv.y * w0.y + hv.z * w0.z + hv.w * w0.w;
                        acc[bi][1] += hv.x * w1.x + hv.y * w1.y + hv.z * w1.z + hv.w * w1.w;
                        acc[bi][2] += hv.x * w2.x + hv.y * w2.y + hv.z * w2.z + hv.w * w2.w;
                        acc[bi][3] += hv.x * w3.x + hv.y * w3.y + hv.z * w3.z + hv.w * w3.w;
                    }
                }
                if (more) {
                    Wn[tid] = pf0;       Wn[tid + 192] = pf1;
                    Wn[tid + 384] = pf2; Wn[tid + 576] = pf3;
                }
                __syncthreads();
            }
        }

        const float* HsF = (const float*)Hs;
#pragma unroll
        for (int bi = 0; bi < 4; bi++) {
            const int b = myb[bi];
            const int L = myL[bi];
            const bool alive = (t < L);
            const int src = dir ? (alive ? (L - 1 - t) : t) : t;
            float hold = HsF[(bloc0 + bi) * (HS4 * 4) + j];
            float hnew, outv;
            if (alive) {
                const float* xr = xp + ((size_t)b * SEQ + src) * G4;
                float zi = acc[bi][0] + xr[j];
                float zf = acc[bi][1] + xr[HID + j];
                float zg = acc[bi][2] + xr[2 * HID + j];
                float zo = acc[bi][3] + xr[3 * HID + j];
                float si = 1.f / (1.f + expf(-zi));
                float sf = 1.f / (1.f + expf(-zf));
                float so = 1.f / (1.f + expf(-zo));
                float nc = sf * c4[bi] + si * tanhf(zg);
                c4[bi] = nc;
                hnew = so * tanhf(nc);
                outv = hnew;
            } else {
                hnew = hold;
                outv = 0.f;
            }
            d_h[p ^ 1][dir][b][j] = hnew;
            enc[((size_t)b * SEQ + src) * E2 + dir * HID + j] = outv;
        }
        grid_bar();
    }
}

// ---------------- attention tail ----------------
__global__ void scores_kernel(const float* __restrict__ we) {  // ekey lives in d_xpf
    const int warp = threadIdx.x >> 5, lane = threadIdx.x & 31;
    const size_t row = (size_t)blockIdx.x * 8 + warp;
    const float* r = d_xpf + row * E2;
    float s = 0.f;
    for (int k = lane; k < E2; k += 32) s += r[k] * we[k];
#pragma unroll
    for (int o = 16; o; o >>= 1) s += __shfl_down_sync(0xffffffffu, s, o);
    if (!lane) d_scores[row] = s;
}

__global__ void softmax_kernel(const int* __restrict__ lens) {
    __shared__ float red[512];
    const int b = blockIdx.x, t = threadIdx.x;
    const int L = lens[b];
    float v = (t < L) ? d_scores[b * SEQ + t] : -INFINITY;
    red[t] = v;
    __syncthreads();
    for (int s = 256; s > 0; s >>= 1) { if (t < s) red[t] = fmaxf(red[t], red[t + s]); __syncthreads(); }
    float m = red[0];
    __syncthreads();
    float e = (t < L) ? expf(v - m) : 0.f;
    red[t] = e;
    __syncthreads();
    for (int s = 256; s > 0; s >>= 1) { if (t < s) red[t] += red[t + s]; __syncthreads(); }
    d_attn[b * SEQ + t] = e / red[0];
}

__global__ void context_kernel() {
    const int b = blockIdx.y;
    const int h = blockIdx.x * 256 + threadIdx.x;
    float acc = 0.f;
    const float* a = d_attn + b * SEQ;
    const float* e = d_enc1 + (size_t)b * SEQ * E2 + h;
    for (int t = 0; t < SEQ; t++) acc += a[t] * e[(size_t)t * E2];
    d_ctx[b * E2 + h] = acc;
}

__global__ void post_kernel(const float* __restrict__ Wp, const float* __restrict__ bp) {
    const int b = blockIdx.y;
    const int n = blockIdx.x * 256 + threadIdx.x;
    float acc = bp[n];
    const float* c = d_ctx + b * E2;
    for (int k = 0; k < E2; k++) acc += c[k] * Wp[(size_t)k * E2 + n];
    d_ctx2[b * E2 + n] = acc;
}

__global__ void intents_kernel(const float* __restrict__ Wi, const float* __restrict__ bi, float* __restrict__ out) {
    const int b = blockIdx.x, n = threadIdx.x;
    if (n >= NINT) return;
    float acc = bi[n];
    const float* c = d_ctx2 + b * E2;
    for (int k = 0; k < E2; k++) acc += c[k] * Wi[k * NINT + n];
    out[b * NINT + n] = acc;
}

// ---------------- launch ----------------
extern "C" void kernel_launch(void* const* d_in, const int* in_sizes, int n_in,
                              void* d_out, int out_size) {
    const float* X    = (const float*)d_in[0];
    const int*   lens = (const int*)  d_in[1];
    const int s = (n_in >= 23) ? 3 : 2;  // skip is_test if present
    const float* W_reg  = (const float*)d_in[s + 0];
    const float* b_reg  = (const float*)d_in[s + 1];
    const float* Wi0f   = (const float*)d_in[s + 2];
    const float* Wh0f   = (const float*)d_in[s + 3];
    const float* b0f    = (const float*)d_in[s + 4];
    const float* Wi0b   = (const float*)d_in[s + 5];
    const float* Wh0b   = (const float*)d_in[s + 6];
    const float* b0b    = (const float*)d_in[s + 7];
    const float* Wi1f   = (const float*)d_in[s + 8];
    const float* Wh1f   = (const float*)d_in[s + 9];
    const float* b1f    = (const float*)d_in[s + 10];
    const float* Wi1b   = (const float*)d_in[s + 11];
    const float* Wh1b   = (const float*)d_in[s + 12];
    const float* b1b    = (const float*)d_in[s + 13];
    const float* W_keys = (const float*)d_in[s + 14];
    const float* W_en   = (const float*)d_in[s + 15];
    const float* W_post = (const float*)d_in[s + 16];
    const float* b_post = (const float*)d_in[s + 17];
    const float* W_int  = (const float*)d_in[s + 18];
    const float* b_int  = (const float*)d_in[s + 19];

    cudaFuncSetAttribute(lstm_layer, cudaFuncAttributeMaxDynamicSharedMemorySize, LSTM_SMEM);

    // reg = X @ W_reg + b_reg
    gemm1<false><<<dim3(DENSE / 128, MT / 128), 256>>>(X, -1, W_reg, b_reg, 0, DENSE, DIN, lens);

    // blocked recurrent weights (independent of gemm above)
    conv_wblk<<<3072, 192>>>(Wh0f, Wh0b, Wh1f, Wh1b);

    // layer-0 input projections
    gemm1<false><<<dim3(G4 / 128, MT / 128), 256>>>(nullptr, 0, Wi0f, b0f, 1, G4, DENSE, lens);
    gemm1<false><<<dim3(G4 / 128, MT / 128), 256>>>(nullptr, 0, Wi0b, b0b, 2, G4, DENSE, lens);

    // layer-0 recurrence -> enc0
    lstm_layer<<<128, 192, LSTM_SMEM>>>(0, lens);

    // layer-1 input projections
    gemm1<false><<<dim3(G4 / 128, MT / 128), 256>>>(nullptr, 3, Wi1f, b1f, 1, G4, E2, lens);
    gemm1<false><<<dim3(G4 / 128, MT / 128), 256>>>(nullptr, 3, Wi1b, b1b, 2, G4, E2, lens);

    // layer-1 recurrence -> enc1
    lstm_layer<<<128, 192, LSTM_SMEM>>>(1, lens);

    // ekey = tanh(enc1 @ W_keys) -> d_xpf
    gemm1<true><<<dim3(E2 / 128, MT / 128), 256>>>(nullptr, 4, W_keys, nullptr, 1, E2, E2, lens);

    // attention tail
    scores_kernel<<<MT / 8, 256>>>(W_en);
    softmax_kernel<<<BATCH, 512>>>(lens);
    context_kernel<<<dim3(E2 / 256, BATCH), 256>>>();
    post_kernel<<<dim3(E2 / 256, BATCH), 256>>>(W_post, b_post);
    intents_kernel<<<BATCH, 64>>>(W_int, b_int, (float*)d_out);
}

// round 10
// speedup vs baseline: 3.2622x; 1.0013x over previous
#include <cuda_runtime.h>
#include <math.h>
#include <stdint.h>

#define BATCH 64
#define SEQ   512
#define DIN   1024
#define DENSE 1024
#define HID   768
#define G4    (4*HID)    // 3072
#define E2    (2*HID)    // 1536
#define NINT  60
#define MT    (BATCH*SEQ) // 32768

// ---------------- static device buffers ----------------
__device__ float d_reg [(size_t)MT * DENSE];
__device__ float d_xpf [(size_t)MT * G4];
__device__ float d_xpb [(size_t)MT * G4];
__device__ float d_enc0[(size_t)MT * E2];
__device__ float d_enc1[(size_t)MT * E2];
// blocked recurrent weights: [(ld*16+jt)*48+kc] chunks of 768 float4
// chunk layout: idx = (g*4+kq)*48 + jl ; float4 spans k = kc*16+kq*4 .. +3
__device__ float4 d_wblk4[(size_t)4 * 16 * 48 * 768];
__device__ float d_h   [2][2][BATCH][HID];      // [parity][dir][b][k]
__device__ float d_scores[MT];
__device__ float d_attn  [MT];
__device__ float d_ctx [BATCH * E2];
__device__ float d_ctx2[BATCH * E2];
__device__ unsigned d_bar_cnt = 0;
__device__ volatile unsigned d_bar_gen = 0;

__device__ __forceinline__ float* buf_sel(int s) {
    switch (s) {
        case 0: return d_reg;
        case 1: return d_xpf;
        case 2: return d_xpb;
        case 3: return d_enc0;
        default: return d_enc1;
    }
}

// ---------------- software grid barrier (all blocks co-resident) ----------------
__device__ __forceinline__ void grid_bar() {
    __syncthreads();
    if (threadIdx.x == 0) {
        unsigned gen = d_bar_gen;
        __threadfence();
        unsigned arrived = atomicAdd(&d_bar_cnt, 1u);
        if (arrived == gridDim.x - 1) {
            d_bar_cnt = 0;
            __threadfence();
            d_bar_gen = gen + 1;
        } else {
            while (d_bar_gen == gen) { }
        }
        __threadfence();
    }
    __syncthreads();
}

// ================= FFMA SGEMM — EXACT R1 structure + dead-block skip ==========
// C[M,N] = act(A[M,K] @ W[K,N] + bias). Tile 128x128, Kt=8, 256 threads,
// 8x8 microtile (4+4 split). Measured: fma 63.1%, issue 70.8%.
template <bool TANH>
__global__ void __launch_bounds__(256) gemm1(
    const float* __restrict__ Aext, int aSel,
    const float* __restrict__ W, const float* __restrict__ bias,
    int cSel, int N, int K, const int* __restrict__ lens)
{
    const int bm = blockIdx.y * 128;
    if (lens) {
        const int b = bm >> 9, t0 = bm & 511;
        if (t0 >= lens[b]) return;   // dead rows: outputs never consumed
    }
    const float* __restrict__ A = (aSel < 0) ? Aext : buf_sel(aSel);
    float* __restrict__ C = buf_sel(cSel);

    __shared__ float As[8][128];
    __shared__ float Bs[8][128];

    const int tid = threadIdx.x;
    const int bn = blockIdx.x * 128;
    const int a_m = tid >> 1;
    const int a_k = (tid & 1) * 4;
    const int b_k = tid >> 5;
    const int b_n = (tid & 31) * 4;
    const int tx = tid & 15;
    const int ty = tid >> 4;

    float acc[8][8];
#pragma unroll
    for (int i = 0; i < 8; i++)
#pragma unroll
        for (int j = 0; j < 8; j++) acc[i][j] = 0.f;

    for (int k0 = 0; k0 < K; k0 += 8) {
        float4 av = *(const float4*)&A[(size_t)(bm + a_m) * K + k0 + a_k];
        As[a_k + 0][a_m] = av.x;
        As[a_k + 1][a_m] = av.y;
        As[a_k + 2][a_m] = av.z;
        As[a_k + 3][a_m] = av.w;
        *(float4*)&Bs[b_k][b_n] = *(const float4*)&W[(size_t)(k0 + b_k) * N + bn + b_n];
        __syncthreads();
#pragma unroll
        for (int kk = 0; kk < 8; kk++) {
            float ar[8], br[8];
            *(float4*)&ar[0] = *(const float4*)&As[kk][ty * 4];
            *(float4*)&ar[4] = *(const float4*)&As[kk][64 + ty * 4];
            *(float4*)&br[0] = *(const float4*)&Bs[kk][tx * 4];
            *(float4*)&br[4] = *(const float4*)&Bs[kk][64 + tx * 4];
#pragma unroll
            for (int i = 0; i < 8; i++)
#pragma unroll
                for (int j = 0; j < 8; j++)
                    acc[i][j] = fmaf(ar[i], br[j], acc[i][j]);
        }
        __syncthreads();
    }

#pragma unroll
    for (int hm = 0; hm < 2; hm++) {
#pragma unroll
        for (int i = 0; i < 4; i++) {
            int r = bm + hm * 64 + ty * 4 + i;
            int ri = hm * 4 + i;
#pragma unroll
            for (int hn = 0; hn < 2; hn++) {
                int cb = bn + hn * 64 + tx * 4;
                float4 v;
                v.x = acc[ri][hn * 4 + 0] + (bias ? bias[cb + 0] : 0.f);
                v.y = acc[ri][hn * 4 + 1] + (bias ? bias[cb + 1] : 0.f);
                v.z = acc[ri][hn * 4 + 2] + (bias ? bias[cb + 2] : 0.f);
                v.w = acc[ri][hn * 4 + 3] + (bias ? bias[cb + 3] : 0.f);
                if (TANH) { v.x = tanhf(v.x); v.y = tanhf(v.y); v.z = tanhf(v.z); v.w = tanhf(v.w); }
                *(float4*)&C[(size_t)r * N + cb] = v;
            }
        }
    }
}

// ---------------- build blocked recurrent weights ------------------------------
// 3072 blocks x 192 threads; block = (ld, jt, kc); thread writes 4 float4.
__global__ void conv_wblk(const float* __restrict__ W0, const float* __restrict__ W1,
                          const float* __restrict__ W2, const float* __restrict__ W3) {
    const int bid = blockIdx.x;
    const int ld = bid / 768, r = bid % 768, jt = r / 48, kc = r % 48;
    const float* W = (ld == 0) ? W0 : (ld == 1) ? W1 : (ld == 2) ? W2 : W3;
    float4* dst = d_wblk4 + ((size_t)(ld * 16 + jt) * 48 + kc) * 768;
#pragma unroll
    for (int q = 0; q < 4; q++) {
        int c = threadIdx.x + 192 * q;
        int jl = c % 48;
        int gq = c / 48;          // 0..15
        int g = gq >> 2, kq = gq & 3;
        int n = g * HID + jt * 48 + jl;
        int k = kc * 16 + kq * 4;
        float4 v;
        v.x = W[(size_t)(k + 0) * G4 + n];
        v.y = W[(size_t)(k + 1) * G4 + n];
        v.z = W[(size_t)(k + 2) * G4 + n];
        v.w = W[(size_t)(k + 3) * G4 + n];
        dst[c] = v;
    }
}

// ---------------- persistent BiLSTM layer v3 ------------------------------------
// 128 blocks x 384 threads. Block = (dir, 16-batch tile, 48-j tile).
// Thread = 2 batches x j x 4 gates (8 ty-groups); c in registers;
// h ping-pongs in global. Weights streamed coalesced via double-buffered smem
// chunks — loaded ONCE per block per step (thread count doesn't change traffic).
// Block-uniform skip predicate keeps all barriers convergent.
#define HS4   193                 // float4 per Hs row (772 floats)
#define WOFF  (16 * HS4)          // 3088 float4
#define LSTM_SMEM ((WOFF + 2 * 768) * 16)

__global__ void __launch_bounds__(384, 1) lstm_layer(int layer, const int* __restrict__ lens) {
    extern __shared__ float4 sm4[];
    float4* Hs  = sm4;                 // [16][HS4]
    float4* Wb0 = sm4 + WOFF;          // [768]
    float4* Wb1 = sm4 + WOFF + 768;    // [768]

    const int tid = threadIdx.x;
    const int dir = blockIdx.x >> 6;
    const int rem = blockIdx.x & 63;
    const int b0 = (rem >> 4) * 16;
    const int jt = rem & 15;
    const int jbase = jt * 48;
    const int tx = tid % 48;
    const int ty = tid / 48;           // 0..7
    const int j = jbase + tx;
    const int bloc0 = ty * 2;

    const float* xp = dir ? d_xpb : d_xpf;
    float* enc = layer ? d_enc1 : d_enc0;
    const float4* wsrc = d_wblk4 + ((size_t)((layer * 2 + dir) * 16 + jt) * 48) * 768;

    int myb[2], myL[2];
#pragma unroll
    for (int bi = 0; bi < 2; bi++) {
        myb[bi] = b0 + bloc0 + bi;
        myL[bi] = lens[myb[bi]];
    }
    // BLOCK-UNIFORM max length over all 16 batches of this block
    int blockMaxL = 0;
#pragma unroll
    for (int i = 0; i < 16; i++) blockMaxL = max(blockMaxL, lens[b0 + i]);

    for (int i = tid; i < 16 * 48; i += 384)
        d_h[0][dir][b0 + (i / 48)][jbase + (i % 48)] = 0.f;
    float c2[2] = {0.f, 0.f};
    grid_bar();

    for (int t = 0; t < SEQ; t++) {
        const int p = t & 1;
        // h snapshot: 16 rows x 192 float4, padded rows (HS4=193)
        const float4* hsrc = (const float4*)&d_h[p][dir][b0][0];
#pragma unroll
        for (int q = 0; q < 8; q++) {
            int idx = tid + q * 384;          // 0..3071
            int b = idx / 192, c = idx % 192;
            Hs[b * HS4 + c] = __ldcg(hsrc + idx);
        }
        __syncthreads();

        float acc[2][4];
#pragma unroll
        for (int bi = 0; bi < 2; bi++)
#pragma unroll
            for (int g = 0; g < 4; g++) acc[bi][g] = 0.f;

        if (t < blockMaxL) {          // uniform predicate -> barriers below are safe
            // prologue: stage chunk 0 (768 float4, 384 threads -> 2 each)
            float4 pf0 = wsrc[tid];
            float4 pf1 = wsrc[tid + 384];
            Wb0[tid] = pf0; Wb0[tid + 384] = pf1;
            __syncthreads();

            for (int c = 0; c < 48; c++) {
                const float4* Wc = (c & 1) ? Wb1 : Wb0;
                float4* Wn = (c & 1) ? Wb0 : Wb1;
                const bool more = (c + 1 < 48);
                if (more) {
                    const float4* s = wsrc + (size_t)(c + 1) * 768;
                    pf0 = s[tid];
                    pf1 = s[tid + 384];
                }
#pragma unroll
                for (int kq = 0; kq < 4; kq++) {
                    const float4 w0 = Wc[(0 * 4 + kq) * 48 + tx];
                    const float4 w1 = Wc[(1 * 4 + kq) * 48 + tx];
                    const float4 w2 = Wc[(2 * 4 + kq) * 48 + tx];
                    const float4 w3 = Wc[(3 * 4 + kq) * 48 + tx];
                    const int kk = c * 4 + kq;
#pragma unroll
                    for (int bi = 0; bi < 2; bi++) {
                        const float4 hv = Hs[(bloc0 + bi) * HS4 + kk];
                        acc[bi][0] += hv.x * w0.x + hv.y * w0.y + hv.z * w0.z + hv.w * w0.w;
                        acc[bi][1] += hv.x * w1.x + hv.y * w1.y + hv.z * w1.z + hv.w * w1.w;
                        acc[bi][2] += hv.x * w2.x + hv.y * w2.y + hv.z * w2.z + hv.w * w2.w;
                        acc[bi][3] += hv.x * w3.x + hv.y * w3.y + hv.z * w3.z + hv.w * w3.w;
                    }
                }
                if (more) {
                    Wn[tid] = pf0;
                    Wn[tid + 384] = pf1;
                }
                __syncthreads();
            }
        }

        const float* HsF = (const float*)Hs;
#pragma unroll
        for (int bi = 0; bi < 2; bi++) {
            const int b = myb[bi];
            const int L = myL[bi];
            const bool alive = (t < L);
            const int src = dir ? (alive ? (L - 1 - t) : t) : t;
            float hold = HsF[(bloc0 + bi) * (HS4 * 4) + j];
            float hnew, outv;
            if (alive) {
                const float* xr = xp + ((size_t)b * SEQ + src) * G4;
                float zi = acc[bi][0] + xr[j];
                float zf = acc[bi][1] + xr[HID + j];
                float zg = acc[bi][2] + xr[2 * HID + j];
                float zo = acc[bi][3] + xr[3 * HID + j];
                float si = 1.f / (1.f + expf(-zi));
                float sf = 1.f / (1.f + expf(-zf));
                float so = 1.f / (1.f + expf(-zo));
                float nc = sf * c2[bi] + si * tanhf(zg);
                c2[bi] = nc;
                hnew = so * tanhf(nc);
                outv = hnew;
            } else {
                hnew = hold;
                outv = 0.f;
            }
            d_h[p ^ 1][dir][b][j] = hnew;
            enc[((size_t)b * SEQ + src) * E2 + dir * HID + j] = outv;
        }
        grid_bar();
    }
}

// ---------------- attention tail ----------------
__global__ void scores_kernel(const float* __restrict__ we) {  // ekey lives in d_xpf
    const int warp = threadIdx.x >> 5, lane = threadIdx.x & 31;
    const size_t row = (size_t)blockIdx.x * 8 + warp;
    const float* r = d_xpf + row * E2;
    float s = 0.f;
    for (int k = lane; k < E2; k += 32) s += r[k] * we[k];
#pragma unroll
    for (int o = 16; o; o >>= 1) s += __shfl_down_sync(0xffffffffu, s, o);
    if (!lane) d_scores[row] = s;
}

__global__ void softmax_kernel(const int* __restrict__ lens) {
    __shared__ float red[512];
    const int b = blockIdx.x, t = threadIdx.x;
    const int L = lens[b];
    float v = (t < L) ? d_scores[b * SEQ + t] : -INFINITY;
    red[t] = v;
    __syncthreads();
    for (int s = 256; s > 0; s >>= 1) { if (t < s) red[t] = fmaxf(red[t], red[t + s]); __syncthreads(); }
    float m = red[0];
    __syncthreads();
    float e = (t < L) ? expf(v - m) : 0.f;
    red[t] = e;
    __syncthreads();
    for (int s = 256; s > 0; s >>= 1) { if (t < s) red[t] += red[t + s]; __syncthreads(); }
    d_attn[b * SEQ + t] = e / red[0];
}

__global__ void context_kernel() {
    const int b = blockIdx.y;
    const int h = blockIdx.x * 256 + threadIdx.x;
    float acc = 0.f;
    const float* a = d_attn + b * SEQ;
    const float* e = d_enc1 + (size_t)b * SEQ * E2 + h;
    for (int t = 0; t < SEQ; t++) acc += a[t] * e[(size_t)t * E2];
    d_ctx[b * E2 + h] = acc;
}

__global__ void post_kernel(const float* __restrict__ Wp, const float* __restrict__ bp) {
    const int b = blockIdx.y;
    const int n = blockIdx.x * 256 + threadIdx.x;
    float acc = bp[n];
    const float* c = d_ctx + b * E2;
    for (int k = 0; k < E2; k++) acc += c[k] * Wp[(size_t)k * E2 + n];
    d_ctx2[b * E2 + n] = acc;
}

__global__ void intents_kernel(const float* __restrict__ Wi, const float* __restrict__ bi, float* __restrict__ out) {
    const int b = blockIdx.x, n = threadIdx.x;
    if (n >= NINT) return;
    float acc = bi[n];
    const float* c = d_ctx2 + b * E2;
    for (int k = 0; k < E2; k++) acc += c[k] * Wi[k * NINT + n];
    out[b * NINT + n] = acc;
}

// ---------------- launch ----------------
extern "C" void kernel_launch(void* const* d_in, const int* in_sizes, int n_in,
                              void* d_out, int out_size) {
    const float* X    = (const float*)d_in[0];
    const int*   lens = (const int*)  d_in[1];
    const int s = (n_in >= 23) ? 3 : 2;  // skip is_test if present
    const float* W_reg  = (const float*)d_in[s + 0];
    const float* b_reg  = (const float*)d_in[s + 1];
    const float* Wi0f   = (const float*)d_in[s + 2];
    const float* Wh0f   = (const float*)d_in[s + 3];
    const float* b0f    = (const float*)d_in[s + 4];
    const float* Wi0b   = (const float*)d_in[s + 5];
    const float* Wh0b   = (const float*)d_in[s + 6];
    const float* b0b    = (const float*)d_in[s + 7];
    const float* Wi1f   = (const float*)d_in[s + 8];
    const float* Wh1f   = (const float*)d_in[s + 9];
    const float* b1f    = (const float*)d_in[s + 10];
    const float* Wi1b   = (const float*)d_in[s + 11];
    const float* Wh1b   = (const float*)d_in[s + 12];
    const float* b1b    = (const float*)d_in[s + 13];
    const float* W_keys = (const float*)d_in[s + 14];
    const float* W_en   = (const float*)d_in[s + 15];
    const float* W_post = (const float*)d_in[s + 16];
    const float* b_post = (const float*)d_in[s + 17];
    const float* W_int  = (const float*)d_in[s + 18];
    const float* b_int  = (const float*)d_in[s + 19];

    cudaFuncSetAttribute(lstm_layer, cudaFuncAttributeMaxDynamicSharedMemorySize, LSTM_SMEM);

    // reg = X @ W_reg + b_reg
    gemm1<false><<<dim3(DENSE / 128, MT / 128), 256>>>(X, -1, W_reg, b_reg, 0, DENSE, DIN, lens);

    // blocked recurrent weights (independent of gemm above)
    conv_wblk<<<3072, 192>>>(Wh0f, Wh0b, Wh1f, Wh1b);

    // layer-0 input projections
    gemm1<false><<<dim3(G4 / 128, MT / 128), 256>>>(nullptr, 0, Wi0f, b0f, 1, G4, DENSE, lens);
    gemm1<false><<<dim3(G4 / 128, MT / 128), 256>>>(nullptr, 0, Wi0b, b0b, 2, G4, DENSE, lens);

    // layer-0 recurrence -> enc0
    lstm_layer<<<128, 384, LSTM_SMEM>>>(0, lens);

    // layer-1 input projections
    gemm1<false><<<dim3(G4 / 128, MT / 128), 256>>>(nullptr, 3, Wi1f, b1f, 1, G4, E2, lens);
    gemm1<false><<<dim3(G4 / 128, MT / 128), 256>>>(nullptr, 3, Wi1b, b1b, 2, G4, E2, lens);

    // layer-1 recurrence -> enc1
    lstm_layer<<<128, 384, LSTM_SMEM>>>(1, lens);

    // ekey = tanh(enc1 @ W_keys) -> d_xpf
    gemm1<true><<<dim3(E2 / 128, MT / 128), 256>>>(nullptr, 4, W_keys, nullptr, 1, E2, E2, lens);

    // attention tail
    scores_kernel<<<MT / 8, 256>>>(W_en);
    softmax_kernel<<<BATCH, 512>>>(lens);
    context_kernel<<<dim3(E2 / 256, BATCH), 256>>>();
    post_kernel<<<dim3(E2 / 256, BATCH), 256>>>(W_post, b_post);
    intents_kernel<<<BATCH, 64>>>(W_int, b_int, (float*)d_out);
}

// round 11
// speedup vs baseline: 3.3451x; 1.0254x over previous
#include <cuda_runtime.h>
#include <math.h>
#include <stdint.h>

#define BATCH 64
#define SEQ   512
#define DIN   1024
#define DENSE 1024
#define HID   768
#define G4    (4*HID)    // 3072
#define E2    (2*HID)    // 1536
#define NINT  60
#define MT    (BATCH*SEQ) // 32768

// ---------------- static device buffers ----------------
__device__ float d_reg [(size_t)MT * DENSE];
__device__ float d_xpf [(size_t)MT * G4];
__device__ float d_xpb [(size_t)MT * G4];
__device__ float d_enc0[(size_t)MT * E2];
__device__ float d_enc1[(size_t)MT * E2];
// blocked recurrent weights: [(ld*16+jt)*48+kc] chunks of 768 float4
// chunk layout: idx = (g*4+kq)*48 + jl ; float4 spans k = kc*16+kq*4 .. +3
__device__ float4 d_wblk4[(size_t)4 * 16 * 48 * 768];
__device__ float d_h   [2][2][BATCH][HID];      // [parity][dir][b][k]
__device__ float d_scores[MT];
__device__ float d_attn  [MT];
__device__ float d_ctx [BATCH * E2];
__device__ float d_ctx2[BATCH * E2];
__device__ unsigned d_bar_cnt = 0;
__device__ volatile unsigned d_bar_gen = 0;

__device__ __forceinline__ float* buf_sel(int s) {
    switch (s) {
        case 0: return d_reg;
        case 1: return d_xpf;
        case 2: return d_xpb;
        case 3: return d_enc0;
        default: return d_enc1;
    }
}

// ---------------- software grid barrier (all blocks co-resident) ----------------
__device__ __forceinline__ void grid_bar() {
    __syncthreads();
    if (threadIdx.x == 0) {
        unsigned gen = d_bar_gen;
        __threadfence();
        unsigned arrived = atomicAdd(&d_bar_cnt, 1u);
        if (arrived == gridDim.x - 1) {
            d_bar_cnt = 0;
            __threadfence();
            d_bar_gen = gen + 1;
        } else {
            while (d_bar_gen == gen) { }
        }
        __threadfence();
    }
    __syncthreads();
}

// ================= FFMA SGEMM — EXACT R1 structure + dead-block skip ==========
// C[M,N] = act(A[M,K] @ W[K,N] + bias). Tile 128x128, Kt=8, 256 threads,
// 8x8 microtile (4+4 split). Measured: fma 63.1%, issue 70.8%.
template <bool TANH>
__global__ void __launch_bounds__(256) gemm1(
    const float* __restrict__ Aext, int aSel,
    const float* __restrict__ W, const float* __restrict__ bias,
    int cSel, int N, int K, const int* __restrict__ lens)
{
    const int bm = blockIdx.y * 128;
    if (lens) {
        const int b = bm >> 9, t0 = bm & 511;
        if (t0 >= lens[b]) return;   // dead rows: outputs never consumed
    }
    const float* __restrict__ A = (aSel < 0) ? Aext : buf_sel(aSel);
    float* __restrict__ C = buf_sel(cSel);

    __shared__ float As[8][128];
    __shared__ float Bs[8][128];

    const int tid = threadIdx.x;
    const int bn = blockIdx.x * 128;
    const int a_m = tid >> 1;
    const int a_k = (tid & 1) * 4;
    const int b_k = tid >> 5;
    const int b_n = (tid & 31) * 4;
    const int tx = tid & 15;
    const int ty = tid >> 4;

    float acc[8][8];
#pragma unroll
    for (int i = 0; i < 8; i++)
#pragma unroll
        for (int j = 0; j < 8; j++) acc[i][j] = 0.f;

    for (int k0 = 0; k0 < K; k0 += 8) {
        float4 av = *(const float4*)&A[(size_t)(bm + a_m) * K + k0 + a_k];
        As[a_k + 0][a_m] = av.x;
        As[a_k + 1][a_m] = av.y;
        As[a_k + 2][a_m] = av.z;
        As[a_k + 3][a_m] = av.w;
        *(float4*)&Bs[b_k][b_n] = *(const float4*)&W[(size_t)(k0 + b_k) * N + bn + b_n];
        __syncthreads();
#pragma unroll
        for (int kk = 0; kk < 8; kk++) {
            float ar[8], br[8];
            *(float4*)&ar[0] = *(const float4*)&As[kk][ty * 4];
            *(float4*)&ar[4] = *(const float4*)&As[kk][64 + ty * 4];
            *(float4*)&br[0] = *(const float4*)&Bs[kk][tx * 4];
            *(float4*)&br[4] = *(const float4*)&Bs[kk][64 + tx * 4];
#pragma unroll
            for (int i = 0; i < 8; i++)
#pragma unroll
                for (int j = 0; j < 8; j++)
                    acc[i][j] = fmaf(ar[i], br[j], acc[i][j]);
        }
        __syncthreads();
    }

#pragma unroll
    for (int hm = 0; hm < 2; hm++) {
#pragma unroll
        for (int i = 0; i < 4; i++) {
            int r = bm + hm * 64 + ty * 4 + i;
            int ri = hm * 4 + i;
#pragma unroll
            for (int hn = 0; hn < 2; hn++) {
                int cb = bn + hn * 64 + tx * 4;
                float4 v;
                v.x = acc[ri][hn * 4 + 0] + (bias ? bias[cb + 0] : 0.f);
                v.y = acc[ri][hn * 4 + 1] + (bias ? bias[cb + 1] : 0.f);
                v.z = acc[ri][hn * 4 + 2] + (bias ? bias[cb + 2] : 0.f);
                v.w = acc[ri][hn * 4 + 3] + (bias ? bias[cb + 3] : 0.f);
                if (TANH) { v.x = tanhf(v.x); v.y = tanhf(v.y); v.z = tanhf(v.z); v.w = tanhf(v.w); }
                *(float4*)&C[(size_t)r * N + cb] = v;
            }
        }
    }
}

// ---------------- build blocked recurrent weights ------------------------------
// 3072 blocks x 192 threads; block = (ld, jt, kc); thread writes 4 float4.
__global__ void conv_wblk(const float* __restrict__ W0, const float* __restrict__ W1,
                          const float* __restrict__ W2, const float* __restrict__ W3) {
    const int bid = blockIdx.x;
    const int ld = bid / 768, r = bid % 768, jt = r / 48, kc = r % 48;
    const float* W = (ld == 0) ? W0 : (ld == 1) ? W1 : (ld == 2) ? W2 : W3;
    float4* dst = d_wblk4 + ((size_t)(ld * 16 + jt) * 48 + kc) * 768;
#pragma unroll
    for (int q = 0; q < 4; q++) {
        int c = threadIdx.x + 192 * q;
        int jl = c % 48;
        int gq = c / 48;          // 0..15
        int g = gq >> 2, kq = gq & 3;
        int n = g * HID + jt * 48 + jl;
        int k = kc * 16 + kq * 4;
        float4 v;
        v.x = W[(size_t)(k + 0) * G4 + n];
        v.y = W[(size_t)(k + 1) * G4 + n];
        v.z = W[(size_t)(k + 2) * G4 + n];
        v.w = W[(size_t)(k + 3) * G4 + n];
        dst[c] = v;
    }
}

// ---------------- persistent BiLSTM layer v4: gate-split ------------------------
// 128 blocks x 384 threads. Block = (dir, 16-batch tile, 48-j tile).
// Thread = (tx: j-lane, ty = gh*4+bg): gh picks 2 gates, bg picks 4 batches.
// Per chunk per thread: 8 w-loads, 128 FMA -> FMA-bound (w-traffic halved vs v3).
// Gate halves recombined through a 6KB smem bounce; gh=0 does pointwise+stores.
// gh boundary (tid 192) is a warp boundary; all barriers block-uniform.
#define HS4   193                 // float4 per Hs row (772 floats)
#define WOFF  (16 * HS4)          // 3088 float4
#define GXOFF (WOFF + 2 * 768)    // 4624 float4
#define LSTM_SMEM (GXOFF * 16 + 16 * 2 * 48 * 4)   // 73984 + 6144 = 80128 B

__global__ void __launch_bounds__(384, 1) lstm_layer(int layer, const int* __restrict__ lens) {
    extern __shared__ float4 sm4[];
    float4* Hs  = sm4;                    // [16][HS4]
    float4* Wb0 = sm4 + WOFF;             // [768]
    float4* Wb1 = sm4 + WOFF + 768;       // [768]
    float*  Gx  = (float*)(sm4 + GXOFF);  // [16][2][48] : g,o partials

    const int tid = threadIdx.x;
    const int dir = blockIdx.x >> 6;
    const int rem = blockIdx.x & 63;
    const int b0 = (rem >> 4) * 16;
    const int jt = rem & 15;
    const int jbase = jt * 48;
    const int tx = tid % 48;
    const int ty = tid / 48;           // 0..7
    const int bg = ty & 3;             // batch group: 4 batches
    const int gh = ty >> 2;            // 0: gates i,f ; 1: gates g,o
    const int j = jbase + tx;
    const int bloc0 = bg * 4;

    const float* xp = dir ? d_xpb : d_xpf;
    float* enc = layer ? d_enc1 : d_enc0;
    const float4* wsrc = d_wblk4 + ((size_t)((layer * 2 + dir) * 16 + jt) * 48) * 768;

    int myb[4], myL[4];
#pragma unroll
    for (int bi = 0; bi < 4; bi++) {
        myb[bi] = b0 + bloc0 + bi;
        myL[bi] = lens[myb[bi]];
    }
    // BLOCK-UNIFORM max length over all 16 batches of this block
    int blockMaxL = 0;
#pragma unroll
    for (int i = 0; i < 16; i++) blockMaxL = max(blockMaxL, lens[b0 + i]);

    for (int i = tid; i < 16 * 48; i += 384)
        d_h[0][dir][b0 + (i / 48)][jbase + (i % 48)] = 0.f;
    float c4[4] = {0.f, 0.f, 0.f, 0.f};
    grid_bar();

    // w row offsets for this thread's two gates (absolute gates gh*2, gh*2+1)
    const int gofs0 = (gh * 2 + 0) * 4 * 48 + tx;
    const int gofs1 = (gh * 2 + 1) * 4 * 48 + tx;

    for (int t = 0; t < SEQ; t++) {
        const int p = t & 1;
        // h snapshot: 16 rows x 192 float4, padded rows (HS4=193)
        const float4* hsrc = (const float4*)&d_h[p][dir][b0][0];
#pragma unroll
        for (int q = 0; q < 8; q++) {
            int idx = tid + q * 384;          // 0..3071
            int b = idx / 192, c = idx % 192;
            Hs[b * HS4 + c] = __ldcg(hsrc + idx);
        }
        __syncthreads();

        float acc[4][2];
#pragma unroll
        for (int bi = 0; bi < 4; bi++) {
            acc[bi][0] = 0.f;
            acc[bi][1] = 0.f;
        }

        if (t < blockMaxL) {          // uniform predicate -> barriers below are safe
            // prologue: stage chunk 0 (768 float4, 384 threads -> 2 each)
            float4 pf0 = wsrc[tid];
            float4 pf1 = wsrc[tid + 384];
            Wb0[tid] = pf0; Wb0[tid + 384] = pf1;
            __syncthreads();

            for (int c = 0; c < 48; c++) {
                const float4* Wc = (c & 1) ? Wb1 : Wb0;
                float4* Wn = (c & 1) ? Wb0 : Wb1;
                const bool more = (c + 1 < 48);
                if (more) {
                    const float4* s = wsrc + (size_t)(c + 1) * 768;
                    pf0 = s[tid];
                    pf1 = s[tid + 384];
                }
#pragma unroll
                for (int kq = 0; kq < 4; kq++) {
                    const float4 w0 = Wc[kq * 48 + gofs0];
                    const float4 w1 = Wc[kq * 48 + gofs1];
                    const int kk = c * 4 + kq;
#pragma unroll
                    for (int bi = 0; bi < 4; bi++) {
                        const float4 hv = Hs[(bloc0 + bi) * HS4 + kk];
                        acc[bi][0] += hv.x * w0.x + hv.y * w0.y + hv.z * w0.z + hv.w * w0.w;
                        acc[bi][1] += hv.x * w1.x + hv.y * w1.y + hv.z * w1.z + hv.w * w1.w;
                    }
                }
                if (more) {
                    Wn[tid] = pf0;
                    Wn[tid + 384] = pf1;
                }
                __syncthreads();
            }
        }

        // recombine gate halves: gh=1 (gates g,o) -> smem, gh=0 does pointwise
        if (gh == 1) {
#pragma unroll
            for (int bi = 0; bi < 4; bi++) {
                Gx[((bloc0 + bi) * 2 + 0) * 48 + tx] = acc[bi][0];  // gate g
                Gx[((bloc0 + bi) * 2 + 1) * 48 + tx] = acc[bi][1];  // gate o
            }
        }
        __syncthreads();

        if (gh == 0) {
            const float* HsF = (const float*)Hs;
#pragma unroll
            for (int bi = 0; bi < 4; bi++) {
                const int b = myb[bi];
                const int L = myL[bi];
                const bool alive = (t < L);
                const int src = dir ? (alive ? (L - 1 - t) : t) : t;
                float hold = HsF[(bloc0 + bi) * (HS4 * 4) + j];
                float hnew, outv;
                if (alive) {
                    const float* xr = xp + ((size_t)b * SEQ + src) * G4;
                    float zi = acc[bi][0] + xr[j];
                    float zf = acc[bi][1] + xr[HID + j];
                    float zg = Gx[((bloc0 + bi) * 2 + 0) * 48 + tx] + xr[2 * HID + j];
                    float zo = Gx[((bloc0 + bi) * 2 + 1) * 48 + tx] + xr[3 * HID + j];
                    float si = 1.f / (1.f + expf(-zi));
                    float sf = 1.f / (1.f + expf(-zf));
                    float so = 1.f / (1.f + expf(-zo));
                    float nc = sf * c4[bi] + si * tanhf(zg);
                    c4[bi] = nc;
                    hnew = so * tanhf(nc);
                    outv = hnew;
                } else {
                    hnew = hold;
                    outv = 0.f;
                }
                d_h[p ^ 1][dir][b][j] = hnew;
                enc[((size_t)b * SEQ + src) * E2 + dir * HID + j] = outv;
            }
        }
        grid_bar();
    }
}

// ---------------- attention tail ----------------
__global__ void scores_kernel(const float* __restrict__ we) {  // ekey lives in d_xpf
    const int warp = threadIdx.x >> 5, lane = threadIdx.x & 31;
    const size_t row = (size_t)blockIdx.x * 8 + warp;
    const float* r = d_xpf + row * E2;
    float s = 0.f;
    for (int k = lane; k < E2; k += 32) s += r[k] * we[k];
#pragma unroll
    for (int o = 16; o; o >>= 1) s += __shfl_down_sync(0xffffffffu, s, o);
    if (!lane) d_scores[row] = s;
}

__global__ void softmax_kernel(const int* __restrict__ lens) {
    __shared__ float red[512];
    const int b = blockIdx.x, t = threadIdx.x;
    const int L = lens[b];
    float v = (t < L) ? d_scores[b * SEQ + t] : -INFINITY;
    red[t] = v;
    __syncthreads();
    for (int s = 256; s > 0; s >>= 1) { if (t < s) red[t] = fmaxf(red[t], red[t + s]); __syncthreads(); }
    float m = red[0];
    __syncthreads();
    float e = (t < L) ? expf(v - m) : 0.f;
    red[t] = e;
    __syncthreads();
    for (int s = 256; s > 0; s >>= 1) { if (t < s) red[t] += red[t + s]; __syncthreads(); }
    d_attn[b * SEQ + t] = e / red[0];
}

__global__ void context_kernel() {
    const int b = blockIdx.y;
    const int h = blockIdx.x * 256 + threadIdx.x;
    float acc = 0.f;
    const float* a = d_attn + b * SEQ;
    const float* e = d_enc1 + (size_t)b * SEQ * E2 + h;
    for (int t = 0; t < SEQ; t++) acc += a[t] * e[(size_t)t * E2];
    d_ctx[b * E2 + h] = acc;
}

__global__ void post_kernel(const float* __restrict__ Wp, const float* __restrict__ bp) {
    const int b = blockIdx.y;
    const int n = blockIdx.x * 256 + threadIdx.x;
    float acc = bp[n];
    const float* c = d_ctx + b * E2;
    for (int k = 0; k < E2; k++) acc += c[k] * Wp[(size_t)k * E2 + n];
    d_ctx2[b * E2 + n] = acc;
}

__global__ void intents_kernel(const float* __restrict__ Wi, const float* __restrict__ bi, float* __restrict__ out) {
    const int b = blockIdx.x, n = threadIdx.x;
    if (n >= NINT) return;
    float acc = bi[n];
    const float* c = d_ctx2 + b * E2;
    for (int k = 0; k < E2; k++) acc += c[k] * Wi[k * NINT + n];
    out[b * NINT + n] = acc;
}

// ---------------- launch ----------------
extern "C" void kernel_launch(void* const* d_in, const int* in_sizes, int n_in,
                              void* d_out, int out_size) {
    const float* X    = (const float*)d_in[0];
    const int*   lens = (const int*)  d_in[1];
    const int s = (n_in >= 23) ? 3 : 2;  // skip is_test if present
    const float* W_reg  = (const float*)d_in[s + 0];
    const float* b_reg  = (const float*)d_in[s + 1];
    const float* Wi0f   = (const float*)d_in[s + 2];
    const float* Wh0f   = (const float*)d_in[s + 3];
    const float* b0f    = (const float*)d_in[s + 4];
    const float* Wi0b   = (const float*)d_in[s + 5];
    const float* Wh0b   = (const float*)d_in[s + 6];
    const float* b0b    = (const float*)d_in[s + 7];
    const float* Wi1f   = (const float*)d_in[s + 8];
    const float* Wh1f   = (const float*)d_in[s + 9];
    const float* b1f    = (const float*)d_in[s + 10];
    const float* Wi1b   = (const float*)d_in[s + 11];
    const float* Wh1b   = (const float*)d_in[s + 12];
    const float* b1b    = (const float*)d_in[s + 13];
    const float* W_keys = (const float*)d_in[s + 14];
    const float* W_en   = (const float*)d_in[s + 15];
    const float* W_post = (const float*)d_in[s + 16];
    const float* b_post = (const float*)d_in[s + 17];
    const float* W_int  = (const float*)d_in[s + 18];
    const float* b_int  = (const float*)d_in[s + 19];

    cudaFuncSetAttribute(lstm_layer, cudaFuncAttributeMaxDynamicSharedMemorySize, LSTM_SMEM);

    // reg = X @ W_reg + b_reg
    gemm1<false><<<dim3(DENSE / 128, MT / 128), 256>>>(X, -1, W_reg, b_reg, 0, DENSE, DIN, lens);

    // blocked recurrent weights (independent of gemm above)
    conv_wblk<<<3072, 192>>>(Wh0f, Wh0b, Wh1f, Wh1b);

    // layer-0 input projections
    gemm1<false><<<dim3(G4 / 128, MT / 128), 256>>>(nullptr, 0, Wi0f, b0f, 1, G4, DENSE, lens);
    gemm1<false><<<dim3(G4 / 128, MT / 128), 256>>>(nullptr, 0, Wi0b, b0b, 2, G4, DENSE, lens);

    // layer-0 recurrence -> enc0
    lstm_layer<<<128, 384, LSTM_SMEM>>>(0, lens);

    // layer-1 input projections
    gemm1<false><<<dim3(G4 / 128, MT / 128), 256>>>(nullptr, 3, Wi1f, b1f, 1, G4, E2, lens);
    gemm1<false><<<dim3(G4 / 128, MT / 128), 256>>>(nullptr, 3, Wi1b, b1b, 2, G4, E2, lens);

    // layer-1 recurrence -> enc1
    lstm_layer<<<128, 384, LSTM_SMEM>>>(1, lens);

    // ekey = tanh(enc1 @ W_keys) -> d_xpf
    gemm1<true><<<dim3(E2 / 128, MT / 128), 256>>>(nullptr, 4, W_keys, nullptr, 1, E2, E2, lens);

    // attention tail
    scores_kernel<<<MT / 8, 256>>>(W_en);
    softmax_kernel<<<BATCH, 512>>>(lens);
    context_kernel<<<dim3(E2 / 256, BATCH), 256>>>();
    post_kernel<<<dim3(E2 / 256, BATCH), 256>>>(W_post, b_post);
    intents_kernel<<<BATCH, 64>>>(W_int, b_int, (float*)d_out);
}

// round 12
// speedup vs baseline: 3.3577x; 1.0038x over previous
#include <cuda_runtime.h>
#include <math.h>
#include <stdint.h>

#define BATCH 64
#define SEQ   512
#define DIN   1024
#define DENSE 1024
#define HID   768
#define G4    (4*HID)    // 3072
#define E2    (2*HID)    // 1536
#define NINT  60
#define MT    (BATCH*SEQ) // 32768

// ---------------- static device buffers ----------------
__device__ float d_reg [(size_t)MT * DENSE];
__device__ float d_xpf [(size_t)MT * G4];
__device__ float d_xpb [(size_t)MT * G4];
__device__ float d_enc0[(size_t)MT * E2];
__device__ float d_enc1[(size_t)MT * E2];
// blocked recurrent weights: [(ld*16+jt)*48+kc] chunks of 768 float4
__device__ float4 d_wblk4[(size_t)4 * 16 * 48 * 768];
__device__ float d_h   [2][2][BATCH][HID];      // [parity][dir][b][k]
__device__ float d_scores[MT];
__device__ float d_attn  [MT];
__device__ float d_ctx [BATCH * E2];
__device__ float d_ctx2[BATCH * E2];
__device__ unsigned d_bar_cnt = 0;
__device__ volatile unsigned d_bar_gen = 0;

__device__ __forceinline__ float* buf_sel(int s) {
    switch (s) {
        case 0: return d_reg;
        case 1: return d_xpf;
        case 2: return d_xpb;
        case 3: return d_enc0;
        default: return d_enc1;
    }
}

// ---------------- cp.async helpers ----------------
__device__ __forceinline__ uint32_t sptr(const void* p) {
    return (uint32_t)__cvta_generic_to_shared(p);
}
__device__ __forceinline__ void cpa16(uint32_t d, const void* s) {
    asm volatile("cp.async.cg.shared.global [%0], [%1], 16;" :: "r"(d), "l"(s));
}
#define CPA_COMMIT() asm volatile("cp.async.commit_group;")
#define CPA_WAIT_ALL() asm volatile("cp.async.wait_group 0;")

// ---------------- software grid barrier (all blocks co-resident) ----------------
__device__ __forceinline__ void grid_bar() {
    __syncthreads();
    if (threadIdx.x == 0) {
        unsigned gen = d_bar_gen;
        __threadfence();
        unsigned arrived = atomicAdd(&d_bar_cnt, 1u);
        if (arrived == gridDim.x - 1) {
            d_bar_cnt = 0;
            __threadfence();
            d_bar_gen = gen + 1;
        } else {
            while (d_bar_gen == gen) { }
        }
        __threadfence();
    }
    __syncthreads();
}

// ================= FFMA SGEMM v2: gemm1 + cp.async B + reg-prefetch A ==========
// C[M,N] = act(A[M,K] @ W[K,N] + bias). Tile 128x128, Kt=8, 256 threads,
// 8x8 microtile (4+4 split) — EXACT gemm1 fragment pattern (all LDS.128).
// Double-buffered smem; B staged via cp.async (contiguous 16B chunks, issued a
// tile ahead); A staged via one float4 register prefetch. ONE barrier per tile.
template <bool TANH>
__global__ void __launch_bounds__(256, 2) gemm1(
    const float* __restrict__ Aext, int aSel,
    const float* __restrict__ W, const float* __restrict__ bias,
    int cSel, int N, int K, const int* __restrict__ lens)
{
    const int bm = blockIdx.y * 128;
    if (lens) {
        const int b = bm >> 9, t0 = bm & 511;
        if (t0 >= lens[b]) return;   // dead rows: outputs never consumed
    }
    const float* __restrict__ A = (aSel < 0) ? Aext : buf_sel(aSel);
    float* __restrict__ C = buf_sel(cSel);

    __shared__ float As[2][8][128];
    __shared__ float Bs[2][8][128];

    const int tid = threadIdx.x;
    const int bn = blockIdx.x * 128;
    const int a_m = tid >> 1;
    const int a_k = (tid & 1) * 4;
    const int b_k = tid >> 5;
    const int b_n = (tid & 31) * 4;
    const int tx = tid & 15;
    const int ty = tid >> 4;

    const uint32_t bsAddr0 = sptr(&Bs[0][b_k][b_n]);
    const uint32_t bsAddr1 = sptr(&Bs[1][b_k][b_n]);

    float acc[8][8];
#pragma unroll
    for (int i = 0; i < 8; i++)
#pragma unroll
        for (int j = 0; j < 8; j++) acc[i][j] = 0.f;

    const int NT = K >> 3;
    float4 av;

    auto cpaB = [&](int kt, int buf) {
        cpa16(buf ? bsAddr1 : bsAddr0, &W[(size_t)((kt << 3) + b_k) * N + bn + b_n]);
        CPA_COMMIT();
    };
    auto loadA = [&](int kt) {
        av = *(const float4*)&A[(size_t)(bm + a_m) * K + (kt << 3) + a_k];
    };
    auto storeA = [&](int buf) {
        As[buf][a_k + 0][a_m] = av.x;
        As[buf][a_k + 1][a_m] = av.y;
        As[buf][a_k + 2][a_m] = av.z;
        As[buf][a_k + 3][a_m] = av.w;
    };

    // prologue: stage tile 0 (B async, A via regs), preload A regs for tile 1
    cpaB(0, 0);
    loadA(0);
    storeA(0);
    if (NT > 1) loadA(1);
    CPA_WAIT_ALL();
    __syncthreads();

    for (int kt = 0; kt < NT; kt++) {
        const int buf = kt & 1;
        const bool more = (kt + 1 < NT);
        // issue B copy for tile kt+1 into the idle buffer (freed by last barrier)
        if (more) cpaB(kt + 1, buf ^ 1);

        // compute tile kt
#pragma unroll
        for (int kk = 0; kk < 8; kk++) {
            float ar[8], br[8];
            *(float4*)&ar[0] = *(const float4*)&As[buf][kk][ty * 4];
            *(float4*)&ar[4] = *(const float4*)&As[buf][kk][64 + ty * 4];
            *(float4*)&br[0] = *(const float4*)&Bs[buf][kk][tx * 4];
            *(float4*)&br[4] = *(const float4*)&Bs[buf][kk][64 + tx * 4];
#pragma unroll
            for (int i = 0; i < 8; i++)
#pragma unroll
                for (int j = 0; j < 8; j++)
                    acc[i][j] = fmaf(ar[i], br[j], acc[i][j]);
        }

        if (more) {
            storeA(buf ^ 1);                 // A regs for tile kt+1 -> idle buffer
            if (kt + 2 < NT) loadA(kt + 2);  // prefetch A regs for tile kt+2
            CPA_WAIT_ALL();                  // B(kt+1) landed (covered by compute)
            __syncthreads();                 // one barrier per tile
        }
    }

    // epilogue
#pragma unroll
    for (int hm = 0; hm < 2; hm++) {
#pragma unroll
        for (int i = 0; i < 4; i++) {
            int r = bm + hm * 64 + ty * 4 + i;
            int ri = hm * 4 + i;
#pragma unroll
            for (int hn = 0; hn < 2; hn++) {
                int cb = bn + hn * 64 + tx * 4;
                float4 v;
                v.x = acc[ri][hn * 4 + 0] + (bias ? bias[cb + 0] : 0.f);
                v.y = acc[ri][hn * 4 + 1] + (bias ? bias[cb + 1] : 0.f);
                v.z = acc[ri][hn * 4 + 2] + (bias ? bias[cb + 2] : 0.f);
                v.w = acc[ri][hn * 4 + 3] + (bias ? bias[cb + 3] : 0.f);
                if (TANH) { v.x = tanhf(v.x); v.y = tanhf(v.y); v.z = tanhf(v.z); v.w = tanhf(v.w); }
                *(float4*)&C[(size_t)r * N + cb] = v;
            }
        }
    }
}

// ---------------- build blocked recurrent weights ------------------------------
__global__ void conv_wblk(const float* __restrict__ W0, const float* __restrict__ W1,
                          const float* __restrict__ W2, const float* __restrict__ W3) {
    const int bid = blockIdx.x;
    const int ld = bid / 768, r = bid % 768, jt = r / 48, kc = r % 48;
    const float* W = (ld == 0) ? W0 : (ld == 1) ? W1 : (ld == 2) ? W2 : W3;
    float4* dst = d_wblk4 + ((size_t)(ld * 16 + jt) * 48 + kc) * 768;
#pragma unroll
    for (int q = 0; q < 4; q++) {
        int c = threadIdx.x + 192 * q;
        int jl = c % 48;
        int gq = c / 48;          // 0..15
        int g = gq >> 2, kq = gq & 3;
        int n = g * HID + jt * 48 + jl;
        int k = kc * 16 + kq * 4;
        float4 v;
        v.x = W[(size_t)(k + 0) * G4 + n];
        v.y = W[(size_t)(k + 1) * G4 + n];
        v.z = W[(size_t)(k + 2) * G4 + n];
        v.w = W[(size_t)(k + 3) * G4 + n];
        dst[c] = v;
    }
}

// ---------------- persistent BiLSTM layer v4: gate-split (unchanged from R11) ---
#define HS4   193                 // float4 per Hs row (772 floats)
#define WOFF  (16 * HS4)          // 3088 float4
#define GXOFF (WOFF + 2 * 768)    // 4624 float4
#define LSTM_SMEM (GXOFF * 16 + 16 * 2 * 48 * 4)   // 80128 B

__global__ void __launch_bounds__(384, 1) lstm_layer(int layer, const int* __restrict__ lens) {
    extern __shared__ float4 sm4[];
    float4* Hs  = sm4;                    // [16][HS4]
    float4* Wb0 = sm4 + WOFF;             // [768]
    float4* Wb1 = sm4 + WOFF + 768;       // [768]
    float*  Gx  = (float*)(sm4 + GXOFF);  // [16][2][48] : g,o partials

    const int tid = threadIdx.x;
    const int dir = blockIdx.x >> 6;
    const int rem = blockIdx.x & 63;
    const int b0 = (rem >> 4) * 16;
    const int jt = rem & 15;
    const int jbase = jt * 48;
    const int tx = tid % 48;
    const int ty = tid / 48;           // 0..7
    const int bg = ty & 3;             // batch group: 4 batches
    const int gh = ty >> 2;            // 0: gates i,f ; 1: gates g,o
    const int j = jbase + tx;
    const int bloc0 = bg * 4;

    const float* xp = dir ? d_xpb : d_xpf;
    float* enc = layer ? d_enc1 : d_enc0;
    const float4* wsrc = d_wblk4 + ((size_t)((layer * 2 + dir) * 16 + jt) * 48) * 768;

    int myb[4], myL[4];
#pragma unroll
    for (int bi = 0; bi < 4; bi++) {
        myb[bi] = b0 + bloc0 + bi;
        myL[bi] = lens[myb[bi]];
    }
    int blockMaxL = 0;
#pragma unroll
    for (int i = 0; i < 16; i++) blockMaxL = max(blockMaxL, lens[b0 + i]);

    for (int i = tid; i < 16 * 48; i += 384)
        d_h[0][dir][b0 + (i / 48)][jbase + (i % 48)] = 0.f;
    float c4[4] = {0.f, 0.f, 0.f, 0.f};
    grid_bar();

    const int gofs0 = (gh * 2 + 0) * 4 * 48 + tx;
    const int gofs1 = (gh * 2 + 1) * 4 * 48 + tx;

    for (int t = 0; t < SEQ; t++) {
        const int p = t & 1;
        const float4* hsrc = (const float4*)&d_h[p][dir][b0][0];
#pragma unroll
        for (int q = 0; q < 8; q++) {
            int idx = tid + q * 384;          // 0..3071
            int b = idx / 192, c = idx % 192;
            Hs[b * HS4 + c] = __ldcg(hsrc + idx);
        }
        __syncthreads();

        float acc[4][2];
#pragma unroll
        for (int bi = 0; bi < 4; bi++) {
            acc[bi][0] = 0.f;
            acc[bi][1] = 0.f;
        }

        if (t < blockMaxL) {          // uniform predicate -> barriers below are safe
            float4 pf0 = wsrc[tid];
            float4 pf1 = wsrc[tid + 384];
            Wb0[tid] = pf0; Wb0[tid + 384] = pf1;
            __syncthreads();

            for (int c = 0; c < 48; c++) {
                const float4* Wc = (c & 1) ? Wb1 : Wb0;
                float4* Wn = (c & 1) ? Wb0 : Wb1;
                const bool more = (c + 1 < 48);
                if (more) {
                    const float4* s = wsrc + (size_t)(c + 1) * 768;
                    pf0 = s[tid];
                    pf1 = s[tid + 384];
                }
#pragma unroll
                for (int kq = 0; kq < 4; kq++) {
                    const float4 w0 = Wc[kq * 48 + gofs0];
                    const float4 w1 = Wc[kq * 48 + gofs1];
                    const int kk = c * 4 + kq;
#pragma unroll
                    for (int bi = 0; bi < 4; bi++) {
                        const float4 hv = Hs[(bloc0 + bi) * HS4 + kk];
                        acc[bi][0] += hv.x * w0.x + hv.y * w0.y + hv.z * w0.z + hv.w * w0.w;
                        acc[bi][1] += hv.x * w1.x + hv.y * w1.y + hv.z * w1.z + hv.w * w1.w;
                    }
                }
                if (more) {
                    Wn[tid] = pf0;
                    Wn[tid + 384] = pf1;
                }
                __syncthreads();
            }
        }

        if (gh == 1) {
#pragma unroll
            for (int bi = 0; bi < 4; bi++) {
                Gx[((bloc0 + bi) * 2 + 0) * 48 + tx] = acc[bi][0];  // gate g
                Gx[((bloc0 + bi) * 2 + 1) * 48 + tx] = acc[bi][1];  // gate o
            }
        }
        __syncthreads();

        if (gh == 0) {
            const float* HsF = (const float*)Hs;
#pragma unroll
            for (int bi = 0; bi < 4; bi++) {
                const int b = myb[bi];
                const int L = myL[bi];
                const bool alive = (t < L);
                const int src = dir ? (alive ? (L - 1 - t) : t) : t;
                float hold = HsF[(bloc0 + bi) * (HS4 * 4) + j];
                float hnew, outv;
                if (alive) {
                    const float* xr = xp + ((size_t)b * SEQ + src) * G4;
                    float zi = acc[bi][0] + xr[j];
                    float zf = acc[bi][1] + xr[HID + j];
                    float zg = Gx[((bloc0 + bi) * 2 + 0) * 48 + tx] + xr[2 * HID + j];
                    float zo = Gx[((bloc0 + bi) * 2 + 1) * 48 + tx] + xr[3 * HID + j];
                    float si = 1.f / (1.f + expf(-zi));
                    float sf = 1.f / (1.f + expf(-zf));
                    float so = 1.f / (1.f + expf(-zo));
                    float nc = sf * c4[bi] + si * tanhf(zg);
                    c4[bi] = nc;
                    hnew = so * tanhf(nc);
                    outv = hnew;
                } else {
                    hnew = hold;
                    outv = 0.f;
                }
                d_h[p ^ 1][dir][b][j] = hnew;
                enc[((size_t)b * SEQ + src) * E2 + dir * HID + j] = outv;
            }
        }
        grid_bar();
    }
}

// ---------------- attention tail ----------------
__global__ void scores_kernel(const float* __restrict__ we) {  // ekey lives in d_xpf
    const int warp = threadIdx.x >> 5, lane = threadIdx.x & 31;
    const size_t row = (size_t)blockIdx.x * 8 + warp;
    const float* r = d_xpf + row * E2;
    float s = 0.f;
    for (int k = lane; k < E2; k += 32) s += r[k] * we[k];
#pragma unroll
    for (int o = 16; o; o >>= 1) s += __shfl_down_sync(0xffffffffu, s, o);
    if (!lane) d_scores[row] = s;
}

__global__ void softmax_kernel(const int* __restrict__ lens) {
    __shared__ float red[512];
    const int b = blockIdx.x, t = threadIdx.x;
    const int L = lens[b];
    float v = (t < L) ? d_scores[b * SEQ + t] : -INFINITY;
    red[t] = v;
    __syncthreads();
    for (int s = 256; s > 0; s >>= 1) { if (t < s) red[t] = fmaxf(red[t], red[t + s]); __syncthreads(); }
    float m = red[0];
    __syncthreads();
    float e = (t < L) ? expf(v - m) : 0.f;
    red[t] = e;
    __syncthreads();
    for (int s = 256; s > 0; s >>= 1) { if (t < s) red[t] += red[t + s]; __syncthreads(); }
    d_attn[b * SEQ + t] = e / red[0];
}

__global__ void context_kernel() {
    const int b = blockIdx.y;
    const int h = blockIdx.x * 256 + threadIdx.x;
    float acc = 0.f;
    const float* a = d_attn + b * SEQ;
    const float* e = d_enc1 + (size_t)b * SEQ * E2 + h;
    for (int t = 0; t < SEQ; t++) acc += a[t] * e[(size_t)t * E2];
    d_ctx[b * E2 + h] = acc;
}

__global__ void post_kernel(const float* __restrict__ Wp, const float* __restrict__ bp) {
    const int b = blockIdx.y;
    const int n = blockIdx.x * 256 + threadIdx.x;
    float acc = bp[n];
    const float* c = d_ctx + b * E2;
    for (int k = 0; k < E2; k++) acc += c[k] * Wp[(size_t)k * E2 + n];
    d_ctx2[b * E2 + n] = acc;
}

__global__ void intents_kernel(const float* __restrict__ Wi, const float* __restrict__ bi, float* __restrict__ out) {
    const int b = blockIdx.x, n = threadIdx.x;
    if (n >= NINT) return;
    float acc = bi[n];
    const float* c = d_ctx2 + b * E2;
    for (int k = 0; k < E2; k++) acc += c[k] * Wi[k * NINT + n];
    out[b * NINT + n] = acc;
}

// ---------------- launch ----------------
extern "C" void kernel_launch(void* const* d_in, const int* in_sizes, int n_in,
                              void* d_out, int out_size) {
    const float* X    = (const float*)d_in[0];
    const int*   lens = (const int*)  d_in[1];
    const int s = (n_in >= 23) ? 3 : 2;  // skip is_test if present
    const float* W_reg  = (const float*)d_in[s + 0];
    const float* b_reg  = (const float*)d_in[s + 1];
    const float* Wi0f   = (const float*)d_in[s + 2];
    const float* Wh0f   = (const float*)d_in[s + 3];
    const float* b0f    = (const float*)d_in[s + 4];
    const float* Wi0b   = (const float*)d_in[s + 5];
    const float* Wh0b   = (const float*)d_in[s + 6];
    const float* b0b    = (const float*)d_in[s + 7];
    const float* Wi1f   = (const float*)d_in[s + 8];
    const float* Wh1f   = (const float*)d_in[s + 9];
    const float* b1f    = (const float*)d_in[s + 10];
    const float* Wi1b   = (const float*)d_in[s + 11];
    const float* Wh1b   = (const float*)d_in[s + 12];
    const float* b1b    = (const float*)d_in[s + 13];
    const float* W_keys = (const float*)d_in[s + 14];
    const float* W_en   = (const float*)d_in[s + 15];
    const float* W_post = (const float*)d_in[s + 16];
    const float* b_post = (const float*)d_in[s + 17];
    const float* W_int  = (const float*)d_in[s + 18];
    const float* b_int  = (const float*)d_in[s + 19];

    cudaFuncSetAttribute(lstm_layer, cudaFuncAttributeMaxDynamicSharedMemorySize, LSTM_SMEM);

    // reg = X @ W_reg + b_reg
    gemm1<false><<<dim3(DENSE / 128, MT / 128), 256>>>(X, -1, W_reg, b_reg, 0, DENSE, DIN, lens);

    // blocked recurrent weights (independent of gemm above)
    conv_wblk<<<3072, 192>>>(Wh0f, Wh0b, Wh1f, Wh1b);

    // layer-0 input projections
    gemm1<false><<<dim3(G4 / 128, MT / 128), 256>>>(nullptr, 0, Wi0f, b0f, 1, G4, DENSE, lens);
    gemm1<false><<<dim3(G4 / 128, MT / 128), 256>>>(nullptr, 0, Wi0b, b0b, 2, G4, DENSE, lens);

    // layer-0 recurrence -> enc0
    lstm_layer<<<128, 384, LSTM_SMEM>>>(0, lens);

    // layer-1 input projections
    gemm1<false><<<dim3(G4 / 128, MT / 128), 256>>>(nullptr, 3, Wi1f, b1f, 1, G4, E2, lens);
    gemm1<false><<<dim3(G4 / 128, MT / 128), 256>>>(nullptr, 3, Wi1b, b1b, 2, G4, E2, lens);

    // layer-1 recurrence -> enc1
    lstm_layer<<<128, 384, LSTM_SMEM>>>(1, lens);

    // ekey = tanh(enc1 @ W_keys) -> d_xpf
    gemm1<true><<<dim3(E2 / 128, MT / 128), 256>>>(nullptr, 4, W_keys, nullptr, 1, E2, E2, lens);

    // attention tail
    scores_kernel<<<MT / 8, 256>>>(W_en);
    softmax_kernel<<<BATCH, 512>>>(lens);
    context_kernel<<<dim3(E2 / 256, BATCH), 256>>>();
    post_kernel<<<dim3(E2 / 256, BATCH), 256>>>(W_post, b_post);
    intents_kernel<<<BATCH, 64>>>(W_int, b_int, (float*)d_out);
}

// round 13
// speedup vs baseline: 3.3927x; 1.0104x over previous
#include <cuda_runtime.h>
#include <math.h>
#include <stdint.h>

#define BATCH 64
#define SEQ   512
#define DIN   1024
#define DENSE 1024
#define HID   768
#define G4    (4*HID)    // 3072
#define E2    (2*HID)    // 1536
#define NINT  60
#define MT    (BATCH*SEQ) // 32768

// ---------------- static device buffers ----------------
__device__ float d_reg [(size_t)MT * DENSE];
__device__ float d_xpf [(size_t)MT * G4];
__device__ float d_xpb [(size_t)MT * G4];
__device__ float d_enc0[(size_t)MT * E2];
__device__ float d_enc1[(size_t)MT * E2];
// blocked recurrent weights: [(ld*16+jt)*48+kc] chunks of 768 float4
__device__ float4 d_wblk4[(size_t)4 * 16 * 48 * 768];
__device__ float d_h   [2][2][BATCH][HID];      // [parity][dir][b][k]
__device__ float d_scores[MT];
__device__ float d_attn  [MT];
__device__ float d_ctx [BATCH * E2];
__device__ float d_ctx2[BATCH * E2];
__device__ unsigned d_gbar_cnt[8];
__device__ volatile unsigned d_gbar_gen[8];

__device__ __forceinline__ float* buf_sel(int s) {
    switch (s) {
        case 0: return d_reg;
        case 1: return d_xpf;
        case 2: return d_xpb;
        case 3: return d_enc0;
        default: return d_enc1;
    }
}

// ---------------- cp.async helpers ----------------
__device__ __forceinline__ uint32_t sptr(const void* p) {
    return (uint32_t)__cvta_generic_to_shared(p);
}
__device__ __forceinline__ void cpa16(uint32_t d, const void* s) {
    asm volatile("cp.async.cg.shared.global [%0], [%1], 16;" :: "r"(d), "l"(s));
}
#define CPA_COMMIT() asm volatile("cp.async.commit_group;")
#define CPA_WAIT_ALL() asm volatile("cp.async.wait_group 0;")

// ---------------- group barrier: 16 blocks sharing one (dir, batch-tile) -------
__device__ __forceinline__ void group_bar(int g) {
    __syncthreads();
    if (threadIdx.x == 0) {
        unsigned gen = d_gbar_gen[g];
        __threadfence();
        unsigned arrived = atomicAdd(&d_gbar_cnt[g], 1u);
        if (arrived == 15u) {
            d_gbar_cnt[g] = 0;
            __threadfence();
            d_gbar_gen[g] = gen + 1;
        } else {
            while (d_gbar_gen[g] == gen) { }
        }
        __threadfence();
    }
    __syncthreads();
}

// ================= FFMA SGEMM v2 (R12, unchanged) =================
template <bool TANH>
__global__ void __launch_bounds__(256, 2) gemm1(
    const float* __restrict__ Aext, int aSel,
    const float* __restrict__ W, const float* __restrict__ bias,
    int cSel, int N, int K, const int* __restrict__ lens)
{
    const int bm = blockIdx.y * 128;
    if (lens) {
        const int b = bm >> 9, t0 = bm & 511;
        if (t0 >= lens[b]) return;   // dead rows: outputs never consumed
    }
    const float* __restrict__ A = (aSel < 0) ? Aext : buf_sel(aSel);
    float* __restrict__ C = buf_sel(cSel);

    __shared__ float As[2][8][128];
    __shared__ float Bs[2][8][128];

    const int tid = threadIdx.x;
    const int bn = blockIdx.x * 128;
    const int a_m = tid >> 1;
    const int a_k = (tid & 1) * 4;
    const int b_k = tid >> 5;
    const int b_n = (tid & 31) * 4;
    const int tx = tid & 15;
    const int ty = tid >> 4;

    const uint32_t bsAddr0 = sptr(&Bs[0][b_k][b_n]);
    const uint32_t bsAddr1 = sptr(&Bs[1][b_k][b_n]);

    float acc[8][8];
#pragma unroll
    for (int i = 0; i < 8; i++)
#pragma unroll
        for (int j = 0; j < 8; j++) acc[i][j] = 0.f;

    const int NT = K >> 3;
    float4 av;

    auto cpaB = [&](int kt, int buf) {
        cpa16(buf ? bsAddr1 : bsAddr0, &W[(size_t)((kt << 3) + b_k) * N + bn + b_n]);
        CPA_COMMIT();
    };
    auto loadA = [&](int kt) {
        av = *(const float4*)&A[(size_t)(bm + a_m) * K + (kt << 3) + a_k];
    };
    auto storeA = [&](int buf) {
        As[buf][a_k + 0][a_m] = av.x;
        As[buf][a_k + 1][a_m] = av.y;
        As[buf][a_k + 2][a_m] = av.z;
        As[buf][a_k + 3][a_m] = av.w;
    };

    cpaB(0, 0);
    loadA(0);
    storeA(0);
    if (NT > 1) loadA(1);
    CPA_WAIT_ALL();
    __syncthreads();

    for (int kt = 0; kt < NT; kt++) {
        const int buf = kt & 1;
        const bool more = (kt + 1 < NT);
        if (more) cpaB(kt + 1, buf ^ 1);

#pragma unroll
        for (int kk = 0; kk < 8; kk++) {
            float ar[8], br[8];
            *(float4*)&ar[0] = *(const float4*)&As[buf][kk][ty * 4];
            *(float4*)&ar[4] = *(const float4*)&As[buf][kk][64 + ty * 4];
            *(float4*)&br[0] = *(const float4*)&Bs[buf][kk][tx * 4];
            *(float4*)&br[4] = *(const float4*)&Bs[buf][kk][64 + tx * 4];
#pragma unroll
            for (int i = 0; i < 8; i++)
#pragma unroll
                for (int j = 0; j < 8; j++)
                    acc[i][j] = fmaf(ar[i], br[j], acc[i][j]);
        }

        if (more) {
            storeA(buf ^ 1);
            if (kt + 2 < NT) loadA(kt + 2);
            CPA_WAIT_ALL();
            __syncthreads();
        }
    }

#pragma unroll
    for (int hm = 0; hm < 2; hm++) {
#pragma unroll
        for (int i = 0; i < 4; i++) {
            int r = bm + hm * 64 + ty * 4 + i;
            int ri = hm * 4 + i;
#pragma unroll
            for (int hn = 0; hn < 2; hn++) {
                int cb = bn + hn * 64 + tx * 4;
                float4 v;
                v.x = acc[ri][hn * 4 + 0] + (bias ? bias[cb + 0] : 0.f);
                v.y = acc[ri][hn * 4 + 1] + (bias ? bias[cb + 1] : 0.f);
                v.z = acc[ri][hn * 4 + 2] + (bias ? bias[cb + 2] : 0.f);
                v.w = acc[ri][hn * 4 + 3] + (bias ? bias[cb + 3] : 0.f);
                if (TANH) { v.x = tanhf(v.x); v.y = tanhf(v.y); v.z = tanhf(v.z); v.w = tanhf(v.w); }
                *(float4*)&C[(size_t)r * N + cb] = v;
            }
        }
    }
}

// ---------------- build blocked recurrent weights ------------------------------
__global__ void conv_wblk(const float* __restrict__ W0, const float* __restrict__ W1,
                          const float* __restrict__ W2, const float* __restrict__ W3) {
    const int bid = blockIdx.x;
    const int ld = bid / 768, r = bid % 768, jt = r / 48, kc = r % 48;
    const float* W = (ld == 0) ? W0 : (ld == 1) ? W1 : (ld == 2) ? W2 : W3;
    float4* dst = d_wblk4 + ((size_t)(ld * 16 + jt) * 48 + kc) * 768;
#pragma unroll
    for (int q = 0; q < 4; q++) {
        int c = threadIdx.x + 192 * q;
        int jl = c % 48;
        int gq = c / 48;          // 0..15
        int g = gq >> 2, kq = gq & 3;
        int n = g * HID + jt * 48 + jl;
        int k = kc * 16 + kq * 4;
        float4 v;
        v.x = W[(size_t)(k + 0) * G4 + n];
        v.y = W[(size_t)(k + 1) * G4 + n];
        v.z = W[(size_t)(k + 2) * G4 + n];
        v.w = W[(size_t)(k + 3) * G4 + n];
        dst[c] = v;
    }
}

// ---------------- persistent BiLSTM layer v5: group barriers + early exit -------
// 128 blocks x 384 threads. Block = (dir, bt, jt); sync group = 16 jt-blocks
// sharing (dir, bt) — the only blocks coupled through h. Group exits the time
// loop at blockMaxL (enc beyond stays 0 from zero-init; never read non-masked).
#define HS4   193                 // float4 per Hs row (772 floats)
#define WOFF  (16 * HS4)          // 3088 float4
#define GXOFF (WOFF + 2 * 768)    // 4624 float4
#define LSTM_SMEM (GXOFF * 16 + 16 * 2 * 48 * 4)   // 80128 B

__global__ void __launch_bounds__(384, 1) lstm_layer(int layer, const int* __restrict__ lens) {
    extern __shared__ float4 sm4[];
    float4* Hs  = sm4;                    // [16][HS4]
    float4* Wb0 = sm4 + WOFF;             // [768]
    float4* Wb1 = sm4 + WOFF + 768;       // [768]
    float*  Gx  = (float*)(sm4 + GXOFF);  // [16][2][48] : g,o partials

    const int tid = threadIdx.x;
    const int dir = blockIdx.x >> 6;
    const int rem = blockIdx.x & 63;
    const int b0 = (rem >> 4) * 16;
    const int jt = rem & 15;
    const int grp = blockIdx.x >> 4;   // dir*4 + bt : 8 groups of 16 blocks
    const int jbase = jt * 48;
    const int tx = tid % 48;
    const int ty = tid / 48;           // 0..7
    const int bg = ty & 3;             // batch group: 4 batches
    const int gh = ty >> 2;            // 0: gates i,f ; 1: gates g,o
    const int j = jbase + tx;
    const int bloc0 = bg * 4;

    const float* xp = dir ? d_xpb : d_xpf;
    float* enc = layer ? d_enc1 : d_enc0;
    const float4* wsrc = d_wblk4 + ((size_t)((layer * 2 + dir) * 16 + jt) * 48) * 768;

    int myb[4], myL[4];
#pragma unroll
    for (int bi = 0; bi < 4; bi++) {
        myb[bi] = b0 + bloc0 + bi;
        myL[bi] = lens[myb[bi]];
    }
    // GROUP-UNIFORM max length over all 16 batches of this group
    int blockMaxL = 0;
#pragma unroll
    for (int i = 0; i < 16; i++) blockMaxL = max(blockMaxL, lens[b0 + i]);

    for (int i = tid; i < 16 * 48; i += 384)
        d_h[0][dir][b0 + (i / 48)][jbase + (i % 48)] = 0.f;
    float c4[4] = {0.f, 0.f, 0.f, 0.f};
    group_bar(grp);

    const int gofs0 = (gh * 2 + 0) * 4 * 48 + tx;
    const int gofs1 = (gh * 2 + 1) * 4 * 48 + tx;

    for (int t = 0; t < blockMaxL; t++) {
        const int p = t & 1;
        const float4* hsrc = (const float4*)&d_h[p][dir][b0][0];
#pragma unroll
        for (int q = 0; q < 8; q++) {
            int idx = tid + q * 384;          // 0..3071
            int b = idx / 192, c = idx % 192;
            Hs[b * HS4 + c] = __ldcg(hsrc + idx);
        }
        __syncthreads();

        float acc[4][2];
#pragma unroll
        for (int bi = 0; bi < 4; bi++) {
            acc[bi][0] = 0.f;
            acc[bi][1] = 0.f;
        }

        {
            float4 pf0 = wsrc[tid];
            float4 pf1 = wsrc[tid + 384];
            Wb0[tid] = pf0; Wb0[tid + 384] = pf1;
            __syncthreads();

            for (int c = 0; c < 48; c++) {
                const float4* Wc = (c & 1) ? Wb1 : Wb0;
                float4* Wn = (c & 1) ? Wb0 : Wb1;
                const bool more = (c + 1 < 48);
                if (more) {
                    const float4* s = wsrc + (size_t)(c + 1) * 768;
                    pf0 = s[tid];
                    pf1 = s[tid + 384];
                }
#pragma unroll
                for (int kq = 0; kq < 4; kq++) {
                    const float4 w0 = Wc[kq * 48 + gofs0];
                    const float4 w1 = Wc[kq * 48 + gofs1];
                    const int kk = c * 4 + kq;
#pragma unroll
                    for (int bi = 0; bi < 4; bi++) {
                        const float4 hv = Hs[(bloc0 + bi) * HS4 + kk];
                        acc[bi][0] += hv.x * w0.x + hv.y * w0.y + hv.z * w0.z + hv.w * w0.w;
                        acc[bi][1] += hv.x * w1.x + hv.y * w1.y + hv.z * w1.z + hv.w * w1.w;
                    }
                }
                if (more) {
                    Wn[tid] = pf0;
                    Wn[tid + 384] = pf1;
                }
                __syncthreads();
            }
        }

        if (gh == 1) {
#pragma unroll
            for (int bi = 0; bi < 4; bi++) {
                Gx[((bloc0 + bi) * 2 + 0) * 48 + tx] = acc[bi][0];  // gate g
                Gx[((bloc0 + bi) * 2 + 1) * 48 + tx] = acc[bi][1];  // gate o
            }
        }
        __syncthreads();

        if (gh == 0) {
            const float* HsF = (const float*)Hs;
#pragma unroll
            for (int bi = 0; bi < 4; bi++) {
                const int b = myb[bi];
                const int L = myL[bi];
                const bool alive = (t < L);
                const int src = dir ? (alive ? (L - 1 - t) : t) : t;
                float hold = HsF[(bloc0 + bi) * (HS4 * 4) + j];
                float hnew, outv;
                if (alive) {
                    const float* xr = xp + ((size_t)b * SEQ + src) * G4;
                    float zi = acc[bi][0] + xr[j];
                    float zf = acc[bi][1] + xr[HID + j];
                    float zg = Gx[((bloc0 + bi) * 2 + 0) * 48 + tx] + xr[2 * HID + j];
                    float zo = Gx[((bloc0 + bi) * 2 + 1) * 48 + tx] + xr[3 * HID + j];
                    float si = 1.f / (1.f + expf(-zi));
                    float sf = 1.f / (1.f + expf(-zf));
                    float so = 1.f / (1.f + expf(-zo));
                    float nc = sf * c4[bi] + si * tanhf(zg);
                    c4[bi] = nc;
                    hnew = so * tanhf(nc);
                    outv = hnew;
                } else {
                    hnew = hold;
                    outv = 0.f;
                }
                d_h[p ^ 1][dir][b][j] = hnew;
                enc[((size_t)b * SEQ + src) * E2 + dir * HID + j] = outv;
            }
        }
        group_bar(grp);
    }
}

// ---------------- attention tail ----------------
__global__ void scores_kernel(const float* __restrict__ we) {  // ekey lives in d_xpf
    const int warp = threadIdx.x >> 5, lane = threadIdx.x & 31;
    const size_t row = (size_t)blockIdx.x * 8 + warp;
    const float* r = d_xpf + row * E2;
    float s = 0.f;
    for (int k = lane; k < E2; k += 32) s += r[k] * we[k];
#pragma unroll
    for (int o = 16; o; o >>= 1) s += __shfl_down_sync(0xffffffffu, s, o);
    if (!lane) d_scores[row] = s;
}

__global__ void softmax_kernel(const int* __restrict__ lens) {
    __shared__ float red[512];
    const int b = blockIdx.x, t = threadIdx.x;
    const int L = lens[b];
    float v = (t < L) ? d_scores[b * SEQ + t] : -INFINITY;
    red[t] = v;
    __syncthreads();
    for (int s = 256; s > 0; s >>= 1) { if (t < s) red[t] = fmaxf(red[t], red[t + s]); __syncthreads(); }
    float m = red[0];
    __syncthreads();
    float e = (t < L) ? expf(v - m) : 0.f;
    red[t] = e;
    __syncthreads();
    for (int s = 256; s > 0; s >>= 1) { if (t < s) red[t] += red[t + s]; __syncthreads(); }
    d_attn[b * SEQ + t] = e / red[0];
}

__global__ void context_kernel() {
    const int b = blockIdx.y;
    const int h = blockIdx.x * 256 + threadIdx.x;
    float acc = 0.f;
    const float* a = d_attn + b * SEQ;
    const float* e = d_enc1 + (size_t)b * SEQ * E2 + h;
    for (int t = 0; t < SEQ; t++) acc += a[t] * e[(size_t)t * E2];
    d_ctx[b * E2 + h] = acc;
}

__global__ void post_kernel(const float* __restrict__ Wp, const float* __restrict__ bp) {
    const int b = blockIdx.y;
    const int n = blockIdx.x * 256 + threadIdx.x;
    float acc = bp[n];
    const float* c = d_ctx + b * E2;
    for (int k = 0; k < E2; k++) acc += c[k] * Wp[(size_t)k * E2 + n];
    d_ctx2[b * E2 + n] = acc;
}

__global__ void intents_kernel(const float* __restrict__ Wi, const float* __restrict__ bi, float* __restrict__ out) {
    const int b = blockIdx.x, n = threadIdx.x;
    if (n >= NINT) return;
    float acc = bi[n];
    const float* c = d_ctx2 + b * E2;
    for (int k = 0; k < E2; k++) acc += c[k] * Wi[k * NINT + n];
    out[b * NINT + n] = acc;
}

// ---------------- launch ----------------
extern "C" void kernel_launch(void* const* d_in, const int* in_sizes, int n_in,
                              void* d_out, int out_size) {
    const float* X    = (const float*)d_in[0];
    const int*   lens = (const int*)  d_in[1];
    const int s = (n_in >= 23) ? 3 : 2;  // skip is_test if present
    const float* W_reg  = (const float*)d_in[s + 0];
    const float* b_reg  = (const float*)d_in[s + 1];
    const float* Wi0f   = (const float*)d_in[s + 2];
    const float* Wh0f   = (const float*)d_in[s + 3];
    const float* b0f    = (const float*)d_in[s + 4];
    const float* Wi0b   = (const float*)d_in[s + 5];
    const float* Wh0b   = (const float*)d_in[s + 6];
    const float* b0b    = (const float*)d_in[s + 7];
    const float* Wi1f   = (const float*)d_in[s + 8];
    const float* Wh1f   = (const float*)d_in[s + 9];
    const float* b1f    = (const float*)d_in[s + 10];
    const float* Wi1b   = (const float*)d_in[s + 11];
    const float* Wh1b   = (const float*)d_in[s + 12];
    const float* b1b    = (const float*)d_in[s + 13];
    const float* W_keys = (const float*)d_in[s + 14];
    const float* W_en   = (const float*)d_in[s + 15];
    const float* W_post = (const float*)d_in[s + 16];
    const float* b_post = (const float*)d_in[s + 17];
    const float* W_int  = (const float*)d_in[s + 18];
    const float* b_int  = (const float*)d_in[s + 19];

    cudaFuncSetAttribute(lstm_layer, cudaFuncAttributeMaxDynamicSharedMemorySize, LSTM_SMEM);

    // reg = X @ W_reg + b_reg
    gemm1<false><<<dim3(DENSE / 128, MT / 128), 256>>>(X, -1, W_reg, b_reg, 0, DENSE, DIN, lens);

    // blocked recurrent weights (independent of gemm above)
    conv_wblk<<<3072, 192>>>(Wh0f, Wh0b, Wh1f, Wh1b);

    // layer-0 input projections
    gemm1<false><<<dim3(G4 / 128, MT / 128), 256>>>(nullptr, 0, Wi0f, b0f, 1, G4, DENSE, lens);
    gemm1<false><<<dim3(G4 / 128, MT / 128), 256>>>(nullptr, 0, Wi0b, b0b, 2, G4, DENSE, lens);

    // layer-0 recurrence -> enc0
    lstm_layer<<<128, 384, LSTM_SMEM>>>(0, lens);

    // layer-1 input projections
    gemm1<false><<<dim3(G4 / 128, MT / 128), 256>>>(nullptr, 3, Wi1f, b1f, 1, G4, E2, lens);
    gemm1<false><<<dim3(G4 / 128, MT / 128), 256>>>(nullptr, 3, Wi1b, b1b, 2, G4, E2, lens);

    // layer-1 recurrence -> enc1
    lstm_layer<<<128, 384, LSTM_SMEM>>>(1, lens);

    // ekey = tanh(enc1 @ W_keys) -> d_xpf
    gemm1<true><<<dim3(E2 / 128, MT / 128), 256>>>(nullptr, 4, W_keys, nullptr, 1, E2, E2, lens);

    // attention tail
    scores_kernel<<<MT / 8, 256>>>(W_en);
    softmax_kernel<<<BATCH, 512>>>(lens);
    context_kernel<<<dim3(E2 / 256, BATCH), 256>>>();
    post_kernel<<<dim3(E2 / 256, BATCH), 256>>>(W_post, b_post);
    intents_kernel<<<BATCH, 64>>>(W_int, b_int, (float*)d_out);
}

// round 14
// speedup vs baseline: 3.5550x; 1.0478x over previous
#include <cuda_runtime.h>
#include <math.h>
#include <stdint.h>

#define BATCH 64
#define SEQ   512
#define DIN   1024
#define DENSE 1024
#define HID   768
#define G4    (4*HID)    // 3072
#define E2    (2*HID)    // 1536
#define NINT  60
#define MT    (BATCH*SEQ) // 32768

// ---------------- static device buffers ----------------
__device__ float d_reg [(size_t)MT * DENSE];
__device__ float d_xpf [(size_t)MT * G4];
__device__ float d_xpb [(size_t)MT * G4];
__device__ float d_enc0[(size_t)MT * E2];
__device__ float d_enc1[(size_t)MT * E2];
// blocked recurrent weights: [(ld*16+jt)*48+kc] chunks of 768 float4
__device__ float4 d_wblk4[(size_t)4 * 16 * 48 * 768];
__device__ float d_h   [2][2][BATCH][HID];      // [parity][dir][b][k]
__device__ float d_scores[MT];
__device__ float d_attn  [MT];
__device__ float d_ctx [BATCH * E2];
__device__ float d_ctx2[BATCH * E2];
__device__ unsigned d_gbar_cnt[8];
__device__ volatile unsigned d_gbar_gen[8];

__device__ __forceinline__ float* buf_sel(int s) {
    switch (s) {
        case 0: return d_reg;
        case 1: return d_xpf;
        case 2: return d_xpb;
        case 3: return d_enc0;
        default: return d_enc1;
    }
}

// ---------------- cp.async helpers ----------------
__device__ __forceinline__ uint32_t sptr(const void* p) {
    return (uint32_t)__cvta_generic_to_shared(p);
}
__device__ __forceinline__ void cpa16(uint32_t d, const void* s) {
    asm volatile("cp.async.cg.shared.global [%0], [%1], 16;" :: "r"(d), "l"(s));
}
#define CPA_COMMIT() asm volatile("cp.async.commit_group;")
#define CPA_WAIT_ALL() asm volatile("cp.async.wait_group 0;")

// ---------------- group barrier: 16 blocks sharing one (dir, batch-tile) -------
__device__ __forceinline__ void group_bar(int g) {
    __syncthreads();
    if (threadIdx.x == 0) {
        unsigned gen = d_gbar_gen[g];
        __threadfence();
        unsigned arrived = atomicAdd(&d_gbar_cnt[g], 1u);
        if (arrived == 15u) {
            d_gbar_cnt[g] = 0;
            __threadfence();
            d_gbar_gen[g] = gen + 1;
        } else {
            while (d_gbar_gen[g] == gen) { }
        }
        __threadfence();
    }
    __syncthreads();
}

// ================= FFMA SGEMM v2 (R12, unchanged) =================
template <bool TANH>
__global__ void __launch_bounds__(256, 2) gemm1(
    const float* __restrict__ Aext, int aSel,
    const float* __restrict__ W, const float* __restrict__ bias,
    int cSel, int N, int K, const int* __restrict__ lens)
{
    const int bm = blockIdx.y * 128;
    if (lens) {
        const int b = bm >> 9, t0 = bm & 511;
        if (t0 >= lens[b]) return;   // dead rows: outputs never consumed
    }
    const float* __restrict__ A = (aSel < 0) ? Aext : buf_sel(aSel);
    float* __restrict__ C = buf_sel(cSel);

    __shared__ float As[2][8][128];
    __shared__ float Bs[2][8][128];

    const int tid = threadIdx.x;
    const int bn = blockIdx.x * 128;
    const int a_m = tid >> 1;
    const int a_k = (tid & 1) * 4;
    const int b_k = tid >> 5;
    const int b_n = (tid & 31) * 4;
    const int tx = tid & 15;
    const int ty = tid >> 4;

    const uint32_t bsAddr0 = sptr(&Bs[0][b_k][b_n]);
    const uint32_t bsAddr1 = sptr(&Bs[1][b_k][b_n]);

    float acc[8][8];
#pragma unroll
    for (int i = 0; i < 8; i++)
#pragma unroll
        for (int j = 0; j < 8; j++) acc[i][j] = 0.f;

    const int NT = K >> 3;
    float4 av;

    auto cpaB = [&](int kt, int buf) {
        cpa16(buf ? bsAddr1 : bsAddr0, &W[(size_t)((kt << 3) + b_k) * N + bn + b_n]);
        CPA_COMMIT();
    };
    auto loadA = [&](int kt) {
        av = *(const float4*)&A[(size_t)(bm + a_m) * K + (kt << 3) + a_k];
    };
    auto storeA = [&](int buf) {
        As[buf][a_k + 0][a_m] = av.x;
        As[buf][a_k + 1][a_m] = av.y;
        As[buf][a_k + 2][a_m] = av.z;
        As[buf][a_k + 3][a_m] = av.w;
    };

    cpaB(0, 0);
    loadA(0);
    storeA(0);
    if (NT > 1) loadA(1);
    CPA_WAIT_ALL();
    __syncthreads();

    for (int kt = 0; kt < NT; kt++) {
        const int buf = kt & 1;
        const bool more = (kt + 1 < NT);
        if (more) cpaB(kt + 1, buf ^ 1);

#pragma unroll
        for (int kk = 0; kk < 8; kk++) {
            float ar[8], br[8];
            *(float4*)&ar[0] = *(const float4*)&As[buf][kk][ty * 4];
            *(float4*)&ar[4] = *(const float4*)&As[buf][kk][64 + ty * 4];
            *(float4*)&br[0] = *(const float4*)&Bs[buf][kk][tx * 4];
            *(float4*)&br[4] = *(const float4*)&Bs[buf][kk][64 + tx * 4];
#pragma unroll
            for (int i = 0; i < 8; i++)
#pragma unroll
                for (int j = 0; j < 8; j++)
                    acc[i][j] = fmaf(ar[i], br[j], acc[i][j]);
        }

        if (more) {
            storeA(buf ^ 1);
            if (kt + 2 < NT) loadA(kt + 2);
            CPA_WAIT_ALL();
            __syncthreads();
        }
    }

#pragma unroll
    for (int hm = 0; hm < 2; hm++) {
#pragma unroll
        for (int i = 0; i < 4; i++) {
            int r = bm + hm * 64 + ty * 4 + i;
            int ri = hm * 4 + i;
#pragma unroll
            for (int hn = 0; hn < 2; hn++) {
                int cb = bn + hn * 64 + tx * 4;
                float4 v;
                v.x = acc[ri][hn * 4 + 0] + (bias ? bias[cb + 0] : 0.f);
                v.y = acc[ri][hn * 4 + 1] + (bias ? bias[cb + 1] : 0.f);
                v.z = acc[ri][hn * 4 + 2] + (bias ? bias[cb + 2] : 0.f);
                v.w = acc[ri][hn * 4 + 3] + (bias ? bias[cb + 3] : 0.f);
                if (TANH) { v.x = tanhf(v.x); v.y = tanhf(v.y); v.z = tanhf(v.z); v.w = tanhf(v.w); }
                *(float4*)&C[(size_t)r * N + cb] = v;
            }
        }
    }
}

// ---------------- build blocked recurrent weights (split into 2 launches) ------
// 1536 blocks x 192 threads; block = (ldrel, jt, kc); thread writes 4 float4.
__global__ void conv_wblk2(const float* __restrict__ Wa, const float* __restrict__ Wb,
                           int ldbase) {
    const int bid = blockIdx.x;
    const int ldrel = bid / 768, r = bid % 768, jt = r / 48, kc = r % 48;
    const float* W = ldrel ? Wb : Wa;
    const int ld = ldbase + ldrel;
    float4* dst = d_wblk4 + ((size_t)(ld * 16 + jt) * 48 + kc) * 768;
#pragma unroll
    for (int q = 0; q < 4; q++) {
        int c = threadIdx.x + 192 * q;
        int jl = c % 48;
        int gq = c / 48;          // 0..15
        int g = gq >> 2, kq = gq & 3;
        int n = g * HID + jt * 48 + jl;
        int k = kc * 16 + kq * 4;
        float4 v;
        v.x = W[(size_t)(k + 0) * G4 + n];
        v.y = W[(size_t)(k + 1) * G4 + n];
        v.z = W[(size_t)(k + 2) * G4 + n];
        v.w = W[(size_t)(k + 3) * G4 + n];
        dst[c] = v;
    }
}

// ---------------- persistent BiLSTM layer v6: 32-k chunks ----------------------
// 128 blocks x 384 threads. Block = (dir, bt, jt); sync group = 16 jt-blocks.
// Weight buffers now hold TWO 768-float4 sub-chunks (32 k): 24 iterations/step,
// syncs halved vs v5. Group-uniform early exit; gate-split recombine via Gx.
#define HS4   193                 // float4 per Hs row (772 floats)
#define WOFF  (16 * HS4)          // 3088 float4
#define WBUF  1536                // float4 per weight buffer (32 k)
#define GXOFF (WOFF + 2 * WBUF)   // 6160 float4
#define LSTM_SMEM (GXOFF * 16 + 16 * 2 * 48 * 4)   // 98560 + 6144 = 104704 B

__global__ void __launch_bounds__(384, 1) lstm_layer(int layer, const int* __restrict__ lens) {
    extern __shared__ float4 sm4[];
    float4* Hs  = sm4;                    // [16][HS4]
    float4* Wb0 = sm4 + WOFF;             // [1536]
    float4* Wb1 = sm4 + WOFF + WBUF;      // [1536]
    float*  Gx  = (float*)(sm4 + GXOFF);  // [16][2][48] : g,o partials

    const int tid = threadIdx.x;
    const int dir = blockIdx.x >> 6;
    const int rem = blockIdx.x & 63;
    const int b0 = (rem >> 4) * 16;
    const int jt = rem & 15;
    const int grp = blockIdx.x >> 4;   // dir*4 + bt : 8 groups of 16 blocks
    const int jbase = jt * 48;
    const int tx = tid % 48;
    const int ty = tid / 48;           // 0..7
    const int bg = ty & 3;             // batch group: 4 batches
    const int gh = ty >> 2;            // 0: gates i,f ; 1: gates g,o
    const int j = jbase + tx;
    const int bloc0 = bg * 4;

    const float* xp = dir ? d_xpb : d_xpf;
    float* enc = layer ? d_enc1 : d_enc0;
    const float4* wsrc = d_wblk4 + ((size_t)((layer * 2 + dir) * 16 + jt) * 48) * 768;

    int myb[4], myL[4];
#pragma unroll
    for (int bi = 0; bi < 4; bi++) {
        myb[bi] = b0 + bloc0 + bi;
        myL[bi] = lens[myb[bi]];
    }
    int blockMaxL = 0;
#pragma unroll
    for (int i = 0; i < 16; i++) blockMaxL = max(blockMaxL, lens[b0 + i]);

    for (int i = tid; i < 16 * 48; i += 384)
        d_h[0][dir][b0 + (i / 48)][jbase + (i % 48)] = 0.f;
    float c4[4] = {0.f, 0.f, 0.f, 0.f};
    group_bar(grp);

    // within-sub-chunk row offsets for this thread's two gates
    const int gofs0 = (gh * 2 + 0) * 4 * 48 + tx;
    const int gofs1 = (gh * 2 + 1) * 4 * 48 + tx;

    for (int t = 0; t < blockMaxL; t++) {
        const int p = t & 1;
        const float4* hsrc = (const float4*)&d_h[p][dir][b0][0];
#pragma unroll
        for (int q = 0; q < 8; q++) {
            int idx = tid + q * 384;          // 0..3071
            int b = idx / 192, c = idx % 192;
            Hs[b * HS4 + c] = __ldcg(hsrc + idx);
        }
        __syncthreads();

        float acc[4][2];
#pragma unroll
        for (int bi = 0; bi < 4; bi++) {
            acc[bi][0] = 0.f;
            acc[bi][1] = 0.f;
        }

        {
            // prologue: stage buffer 0 = sub-chunks 0,1 (1536 f4, 4 per thread)
            float4 pf0 = wsrc[tid];
            float4 pf1 = wsrc[tid + 384];
            float4 pf2 = wsrc[tid + 768];
            float4 pf3 = wsrc[tid + 1152];
            Wb0[tid] = pf0;        Wb0[tid + 384] = pf1;
            Wb0[tid + 768] = pf2;  Wb0[tid + 1152] = pf3;
            __syncthreads();

            for (int c = 0; c < 24; c++) {
                const float4* Wc = (c & 1) ? Wb1 : Wb0;
                float4* Wn = (c & 1) ? Wb0 : Wb1;
                const bool more = (c + 1 < 24);
                if (more) {
                    const float4* s = wsrc + (size_t)(c + 1) * WBUF;
                    pf0 = s[tid];        pf1 = s[tid + 384];
                    pf2 = s[tid + 768];  pf3 = s[tid + 1152];
                }
#pragma unroll
                for (int kq = 0; kq < 8; kq++) {
                    const int sub = kq >> 2, kqi = kq & 3;
                    const float4 w0 = Wc[sub * 768 + kqi * 48 + gofs0];
                    const float4 w1 = Wc[sub * 768 + kqi * 48 + gofs1];
                    const int kk = c * 8 + kq;
#pragma unroll
                    for (int bi = 0; bi < 4; bi++) {
                        const float4 hv = Hs[(bloc0 + bi) * HS4 + kk];
                        acc[bi][0] += hv.x * w0.x + hv.y * w0.y + hv.z * w0.z + hv.w * w0.w;
                        acc[bi][1] += hv.x * w1.x + hv.y * w1.y + hv.z * w1.z + hv.w * w1.w;
                    }
                }
                if (more) {
                    Wn[tid] = pf0;        Wn[tid + 384] = pf1;
                    Wn[tid + 768] = pf2;  Wn[tid + 1152] = pf3;
                }
                __syncthreads();
            }
        }

        if (gh == 1) {
#pragma unroll
            for (int bi = 0; bi < 4; bi++) {
                Gx[((bloc0 + bi) * 2 + 0) * 48 + tx] = acc[bi][0];  // gate g
                Gx[((bloc0 + bi) * 2 + 1) * 48 + tx] = acc[bi][1];  // gate o
            }
        }
        __syncthreads();

        if (gh == 0) {
            const float* HsF = (const float*)Hs;
#pragma unroll
            for (int bi = 0; bi < 4; bi++) {
                const int b = myb[bi];
                const int L = myL[bi];
                const bool alive = (t < L);
                const int src = dir ? (alive ? (L - 1 - t) : t) : t;
                float hold = HsF[(bloc0 + bi) * (HS4 * 4) + j];
                float hnew, outv;
                if (alive) {
                    const float* xr = xp + ((size_t)b * SEQ + src) * G4;
                    float zi = acc[bi][0] + xr[j];
                    float zf = acc[bi][1] + xr[HID + j];
                    float zg = Gx[((bloc0 + bi) * 2 + 0) * 48 + tx] + xr[2 * HID + j];
                    float zo = Gx[((bloc0 + bi) * 2 + 1) * 48 + tx] + xr[3 * HID + j];
                    float si = 1.f / (1.f + expf(-zi));
                    float sf = 1.f / (1.f + expf(-zf));
                    float so = 1.f / (1.f + expf(-zo));
                    float nc = sf * c4[bi] + si * tanhf(zg);
                    c4[bi] = nc;
                    hnew = so * tanhf(nc);
                    outv = hnew;
                } else {
                    hnew = hold;
                    outv = 0.f;
                }
                d_h[p ^ 1][dir][b][j] = hnew;
                enc[((size_t)b * SEQ + src) * E2 + dir * HID + j] = outv;
            }
        }
        group_bar(grp);
    }
}

// ---------------- attention tail ----------------
__global__ void scores_kernel(const float* __restrict__ we) {  // ekey lives in d_xpf
    const int warp = threadIdx.x >> 5, lane = threadIdx.x & 31;
    const size_t row = (size_t)blockIdx.x * 8 + warp;
    const float* r = d_xpf + row * E2;
    float s = 0.f;
    for (int k = lane; k < E2; k += 32) s += r[k] * we[k];
#pragma unroll
    for (int o = 16; o; o >>= 1) s += __shfl_down_sync(0xffffffffu, s, o);
    if (!lane) d_scores[row] = s;
}

__global__ void softmax_kernel(const int* __restrict__ lens) {
    __shared__ float red[512];
    const int b = blockIdx.x, t = threadIdx.x;
    const int L = lens[b];
    float v = (t < L) ? d_scores[b * SEQ + t] : -INFINITY;
    red[t] = v;
    __syncthreads();
    for (int s = 256; s > 0; s >>= 1) { if (t < s) red[t] = fmaxf(red[t], red[t + s]); __syncthreads(); }
    float m = red[0];
    __syncthreads();
    float e = (t < L) ? expf(v - m) : 0.f;
    red[t] = e;
    __syncthreads();
    for (int s = 256; s > 0; s >>= 1) { if (t < s) red[t] += red[t + s]; __syncthreads(); }
    d_attn[b * SEQ + t] = e / red[0];
}

__global__ void context_kernel() {
    const int b = blockIdx.y;
    const int h = blockIdx.x * 256 + threadIdx.x;
    float acc = 0.f;
    const float* a = d_attn + b * SEQ;
    const float* e = d_enc1 + (size_t)b * SEQ * E2 + h;
    for (int t = 0; t < SEQ; t++) acc += a[t] * e[(size_t)t * E2];
    d_ctx[b * E2 + h] = acc;
}

__global__ void post_kernel(const float* __restrict__ Wp, const float* __restrict__ bp) {
    const int b = blockIdx.y;
    const int n = blockIdx.x * 256 + threadIdx.x;
    float acc = bp[n];
    const float* c = d_ctx + b * E2;
    for (int k = 0; k < E2; k++) acc += c[k] * Wp[(size_t)k * E2 + n];
    d_ctx2[b * E2 + n] = acc;
}

__global__ void intents_kernel(const float* __restrict__ Wi, const float* __restrict__ bi, float* __restrict__ out) {
    const int b = blockIdx.x, n = threadIdx.x;
    if (n >= NINT) return;
    float acc = bi[n];
    const float* c = d_ctx2 + b * E2;
    for (int k = 0; k < E2; k++) acc += c[k] * Wi[k * NINT + n];
    out[b * NINT + n] = acc;
}

// ---------------- launch ----------------
extern "C" void kernel_launch(void* const* d_in, const int* in_sizes, int n_in,
                              void* d_out, int out_size) {
    const float* X    = (const float*)d_in[0];
    const int*   lens = (const int*)  d_in[1];
    const int s = (n_in >= 23) ? 3 : 2;  // skip is_test if present
    const float* W_reg  = (const float*)d_in[s + 0];
    const float* b_reg  = (const float*)d_in[s + 1];
    const float* Wi0f   = (const float*)d_in[s + 2];
    const float* Wh0f   = (const float*)d_in[s + 3];
    const float* b0f    = (const float*)d_in[s + 4];
    const float* Wi0b   = (const float*)d_in[s + 5];
    const float* Wh0b   = (const float*)d_in[s + 6];
    const float* b0b    = (const float*)d_in[s + 7];
    const float* Wi1f   = (const float*)d_in[s + 8];
    const float* Wh1f   = (const float*)d_in[s + 9];
    const float* b1f    = (const float*)d_in[s + 10];
    const float* Wi1b   = (const float*)d_in[s + 11];
    const float* Wh1b   = (const float*)d_in[s + 12];
    const float* b1b    = (const float*)d_in[s + 13];
    const float* W_keys = (const float*)d_in[s + 14];
    const float* W_en   = (const float*)d_in[s + 15];
    const float* W_post = (const float*)d_in[s + 16];
    const float* b_post = (const float*)d_in[s + 17];
    const float* W_int  = (const float*)d_in[s + 18];
    const float* b_int  = (const float*)d_in[s + 19];

    cudaFuncSetAttribute(lstm_layer, cudaFuncAttributeMaxDynamicSharedMemorySize, LSTM_SMEM);

    // launches 0,1: blocked recurrent weights (two launches -> lstm0 is launch 5)
    conv_wblk2<<<1536, 192>>>(Wh0f, Wh0b, 0);
    conv_wblk2<<<1536, 192>>>(Wh1f, Wh1b, 2);

    // launch 2: reg = X @ W_reg + b_reg
    gemm1<false><<<dim3(DENSE / 128, MT / 128), 256>>>(X, -1, W_reg, b_reg, 0, DENSE, DIN, lens);

    // launches 3,4: layer-0 input projections
    gemm1<false><<<dim3(G4 / 128, MT / 128), 256>>>(nullptr, 0, Wi0f, b0f, 1, G4, DENSE, lens);
    gemm1<false><<<dim3(G4 / 128, MT / 128), 256>>>(nullptr, 0, Wi0b, b0b, 2, G4, DENSE, lens);

    // launch 5 (ncu-captured): layer-0 recurrence -> enc0
    lstm_layer<<<128, 384, LSTM_SMEM>>>(0, lens);

    // layer-1 input projections
    gemm1<false><<<dim3(G4 / 128, MT / 128), 256>>>(nullptr, 3, Wi1f, b1f, 1, G4, E2, lens);
    gemm1<false><<<dim3(G4 / 128, MT / 128), 256>>>(nullptr, 3, Wi1b, b1b, 2, G4, E2, lens);

    // layer-1 recurrence -> enc1
    lstm_layer<<<128, 384, LSTM_SMEM>>>(1, lens);

    // ekey = tanh(enc1 @ W_keys) -> d_xpf
    gemm1<true><<<dim3(E2 / 128, MT / 128), 256>>>(nullptr, 4, W_keys, nullptr, 1, E2, E2, lens);

    // attention tail
    scores_kernel<<<MT / 8, 256>>>(W_en);
    softmax_kernel<<<BATCH, 512>>>(lens);
    context_kernel<<<dim3(E2 / 256, BATCH), 256>>>();
    post_kernel<<<dim3(E2 / 256, BATCH), 256>>>(W_post, b_post);
    intents_kernel<<<BATCH, 64>>>(W_int, b_int, (float*)d_out);
}

// round 15
// speedup vs baseline: 3.6757x; 1.0340x over previous
#include <cuda_runtime.h>
#include <math.h>
#include <stdint.h>

#define BATCH 64
#define SEQ   512
#define DIN   1024
#define DENSE 1024
#define HID   768
#define G4    (4*HID)    // 3072
#define E2    (2*HID)    // 1536
#define NINT  60
#define MT    (BATCH*SEQ) // 32768

// ---------------- static device buffers ----------------
__device__ float d_reg [(size_t)MT * DENSE];
__device__ float d_xpf [(size_t)MT * G4];
__device__ float d_xpb [(size_t)MT * G4];
__device__ float d_enc0[(size_t)MT * E2];
__device__ float d_enc1[(size_t)MT * E2];
// blocked recurrent weights: [(ld*16+jt)*48+kc] chunks of 768 float4
__device__ float4 d_wblk4[(size_t)4 * 16 * 48 * 768];
__device__ float d_h   [2][2][BATCH][HID];      // [parity][dir][b][k]
__device__ float d_scores[MT];
__device__ float d_attn  [MT];
__device__ float d_ctx [BATCH * E2];
__device__ float d_ctx2[BATCH * E2];
__device__ unsigned d_gbar_cnt[8];
__device__ volatile unsigned d_gbar_gen[8];

__device__ __forceinline__ float* buf_sel(int s) {
    switch (s) {
        case 0: return d_reg;
        case 1: return d_xpf;
        case 2: return d_xpb;
        case 3: return d_enc0;
        default: return d_enc1;
    }
}

// ---------------- cp.async helpers ----------------
__device__ __forceinline__ uint32_t sptr(const void* p) {
    return (uint32_t)__cvta_generic_to_shared(p);
}
__device__ __forceinline__ void cpa16(uint32_t d, const void* s) {
    asm volatile("cp.async.cg.shared.global [%0], [%1], 16;" :: "r"(d), "l"(s));
}
#define CPA_COMMIT() asm volatile("cp.async.commit_group;")
#define CPA_WAIT_ALL() asm volatile("cp.async.wait_group 0;")

// ---------------- group barrier: 16 blocks sharing one (dir, batch-tile) -------
__device__ __forceinline__ void group_bar(int g) {
    __syncthreads();
    if (threadIdx.x == 0) {
        unsigned gen = d_gbar_gen[g];
        __threadfence();
        unsigned arrived = atomicAdd(&d_gbar_cnt[g], 1u);
        if (arrived == 15u) {
            d_gbar_cnt[g] = 0;
            __threadfence();
            d_gbar_gen[g] = gen + 1;
        } else {
            while (d_gbar_gen[g] == gen) { }
        }
        __threadfence();
    }
    __syncthreads();
}

// ================= FFMA SGEMM v2 (R12, unchanged) =================
template <bool TANH>
__global__ void __launch_bounds__(256, 2) gemm1(
    const float* __restrict__ Aext, int aSel,
    const float* __restrict__ W, const float* __restrict__ bias,
    int cSel, int N, int K, const int* __restrict__ lens)
{
    const int bm = blockIdx.y * 128;
    if (lens) {
        const int b = bm >> 9, t0 = bm & 511;
        if (t0 >= lens[b]) return;   // dead rows: outputs never consumed
    }
    const float* __restrict__ A = (aSel < 0) ? Aext : buf_sel(aSel);
    float* __restrict__ C = buf_sel(cSel);

    __shared__ float As[2][8][128];
    __shared__ float Bs[2][8][128];

    const int tid = threadIdx.x;
    const int bn = blockIdx.x * 128;
    const int a_m = tid >> 1;
    const int a_k = (tid & 1) * 4;
    const int b_k = tid >> 5;
    const int b_n = (tid & 31) * 4;
    const int tx = tid & 15;
    const int ty = tid >> 4;

    const uint32_t bsAddr0 = sptr(&Bs[0][b_k][b_n]);
    const uint32_t bsAddr1 = sptr(&Bs[1][b_k][b_n]);

    float acc[8][8];
#pragma unroll
    for (int i = 0; i < 8; i++)
#pragma unroll
        for (int j = 0; j < 8; j++) acc[i][j] = 0.f;

    const int NT = K >> 3;
    float4 av;

    auto cpaB = [&](int kt, int buf) {
        cpa16(buf ? bsAddr1 : bsAddr0, &W[(size_t)((kt << 3) + b_k) * N + bn + b_n]);
        CPA_COMMIT();
    };
    auto loadA = [&](int kt) {
        av = *(const float4*)&A[(size_t)(bm + a_m) * K + (kt << 3) + a_k];
    };
    auto storeA = [&](int buf) {
        As[buf][a_k + 0][a_m] = av.x;
        As[buf][a_k + 1][a_m] = av.y;
        As[buf][a_k + 2][a_m] = av.z;
        As[buf][a_k + 3][a_m] = av.w;
    };

    cpaB(0, 0);
    loadA(0);
    storeA(0);
    if (NT > 1) loadA(1);
    CPA_WAIT_ALL();
    __syncthreads();

    for (int kt = 0; kt < NT; kt++) {
        const int buf = kt & 1;
        const bool more = (kt + 1 < NT);
        if (more) cpaB(kt + 1, buf ^ 1);

#pragma unroll
        for (int kk = 0; kk < 8; kk++) {
            float ar[8], br[8];
            *(float4*)&ar[0] = *(const float4*)&As[buf][kk][ty * 4];
            *(float4*)&ar[4] = *(const float4*)&As[buf][kk][64 + ty * 4];
            *(float4*)&br[0] = *(const float4*)&Bs[buf][kk][tx * 4];
            *(float4*)&br[4] = *(const float4*)&Bs[buf][kk][64 + tx * 4];
#pragma unroll
            for (int i = 0; i < 8; i++)
#pragma unroll
                for (int j = 0; j < 8; j++)
                    acc[i][j] = fmaf(ar[i], br[j], acc[i][j]);
        }

        if (more) {
            storeA(buf ^ 1);
            if (kt + 2 < NT) loadA(kt + 2);
            CPA_WAIT_ALL();
            __syncthreads();
        }
    }

#pragma unroll
    for (int hm = 0; hm < 2; hm++) {
#pragma unroll
        for (int i = 0; i < 4; i++) {
            int r = bm + hm * 64 + ty * 4 + i;
            int ri = hm * 4 + i;
#pragma unroll
            for (int hn = 0; hn < 2; hn++) {
                int cb = bn + hn * 64 + tx * 4;
                float4 v;
                v.x = acc[ri][hn * 4 + 0] + (bias ? bias[cb + 0] : 0.f);
                v.y = acc[ri][hn * 4 + 1] + (bias ? bias[cb + 1] : 0.f);
                v.z = acc[ri][hn * 4 + 2] + (bias ? bias[cb + 2] : 0.f);
                v.w = acc[ri][hn * 4 + 3] + (bias ? bias[cb + 3] : 0.f);
                if (TANH) { v.x = tanhf(v.x); v.y = tanhf(v.y); v.z = tanhf(v.z); v.w = tanhf(v.w); }
                *(float4*)&C[(size_t)r * N + cb] = v;
            }
        }
    }
}

// ---------------- build blocked recurrent weights (two launches) ---------------
__global__ void conv_wblk2(const float* __restrict__ Wa, const float* __restrict__ Wb,
                           int ldbase) {
    const int bid = blockIdx.x;
    const int ldrel = bid / 768, r = bid % 768, jt = r / 48, kc = r % 48;
    const float* W = ldrel ? Wb : Wa;
    const int ld = ldbase + ldrel;
    float4* dst = d_wblk4 + ((size_t)(ld * 16 + jt) * 48 + kc) * 768;
#pragma unroll
    for (int q = 0; q < 4; q++) {
        int c = threadIdx.x + 192 * q;
        int jl = c % 48;
        int gq = c / 48;          // 0..15
        int g = gq >> 2, kq = gq & 3;
        int n = g * HID + jt * 48 + jl;
        int k = kc * 16 + kq * 4;
        float4 v;
        v.x = W[(size_t)(k + 0) * G4 + n];
        v.y = W[(size_t)(k + 1) * G4 + n];
        v.z = W[(size_t)(k + 2) * G4 + n];
        v.w = W[(size_t)(k + 3) * G4 + n];
        dst[c] = v;
    }
}

// ---------------- persistent BiLSTM layer v7: 64-k chunks + cp.async staging ---
// 128 blocks x 384 threads. Block = (dir, bt, jt); sync group = 16 jt-blocks.
// Weight chunks (64 k = 3072 float4) and the h snapshot staged via cp.async —
// no staging registers, no STS in the hot loop, one sync per chunk iteration.
#define HS4   193                 // float4 per Hs row (772 floats)
#define WOFF  (16 * HS4)          // 3088 float4
#define WBUF  3072                // float4 per weight buffer (64 k)
#define NIT   12                  // chunk iterations per step
#define GXOFF (WOFF + 2 * WBUF)   // 9232 float4
#define LSTM_SMEM (GXOFF * 16 + 16 * 2 * 48 * 4)   // 147712 + 6144 = 153856 B

__global__ void __launch_bounds__(384, 1) lstm_layer(int layer, const int* __restrict__ lens) {
    extern __shared__ float4 sm4[];
    float4* Hs  = sm4;                    // [16][HS4]
    float4* Wb0 = sm4 + WOFF;             // [3072]
    float4* Wb1 = sm4 + WOFF + WBUF;      // [3072]
    float*  Gx  = (float*)(sm4 + GXOFF);  // [16][2][48] : g,o partials

    const int tid = threadIdx.x;
    const int dir = blockIdx.x >> 6;
    const int rem = blockIdx.x & 63;
    const int b0 = (rem >> 4) * 16;
    const int jt = rem & 15;
    const int grp = blockIdx.x >> 4;   // dir*4 + bt : 8 groups of 16 blocks
    const int jbase = jt * 48;
    const int tx = tid % 48;
    const int ty = tid / 48;           // 0..7
    const int bg = ty & 3;             // batch group: 4 batches
    const int gh = ty >> 2;            // 0: gates i,f ; 1: gates g,o
    const int j = jbase + tx;
    const int bloc0 = bg * 4;

    const float* xp = dir ? d_xpb : d_xpf;
    float* enc = layer ? d_enc1 : d_enc0;
    const float4* wsrc = d_wblk4 + ((size_t)((layer * 2 + dir) * 16 + jt) * 48) * 768;

    // cp.async destination addresses
    const uint32_t wb0Addr = sptr(Wb0) + (uint32_t)tid * 16;
    const uint32_t wb1Addr = sptr(Wb1) + (uint32_t)tid * 16;
    uint32_t hsAddr[8];
#pragma unroll
    for (int q = 0; q < 8; q++) {
        int idx = tid + q * 384;          // 0..3071
        int b = idx / 192, c = idx % 192;
        hsAddr[q] = sptr(Hs) + (uint32_t)(b * HS4 + c) * 16;
    }

    int myb[4], myL[4];
#pragma unroll
    for (int bi = 0; bi < 4; bi++) {
        myb[bi] = b0 + bloc0 + bi;
        myL[bi] = lens[myb[bi]];
    }
    int blockMaxL = 0;
#pragma unroll
    for (int i = 0; i < 16; i++) blockMaxL = max(blockMaxL, lens[b0 + i]);

    for (int i = tid; i < 16 * 48; i += 384)
        d_h[0][dir][b0 + (i / 48)][jbase + (i % 48)] = 0.f;
    float c4[4] = {0.f, 0.f, 0.f, 0.f};
    group_bar(grp);

    // within-sub-chunk row offsets for this thread's two gates
    const int gofs0 = (gh * 2 + 0) * 4 * 48 + tx;
    const int gofs1 = (gh * 2 + 1) * 4 * 48 + tx;

    auto cpaW = [&](int c, int buf) {
        const char* s = (const char*)(wsrc + (size_t)c * WBUF);
        const uint32_t d = buf ? wb1Addr : wb0Addr;
#pragma unroll
        for (int q = 0; q < 8; q++)
            cpa16(d + (uint32_t)(q * 384) * 16, s + ((size_t)tid + q * 384) * 16);
        CPA_COMMIT();
    };

    for (int t = 0; t < blockMaxL; t++) {
        const int p = t & 1;
        // stage h snapshot + weight chunk 0 in one async group set
        const float4* hsrc = (const float4*)&d_h[p][dir][b0][0];
#pragma unroll
        for (int q = 0; q < 8; q++)
            cpa16(hsAddr[q], hsrc + tid + q * 384);
        CPA_COMMIT();
        cpaW(0, 0);
        CPA_WAIT_ALL();
        __syncthreads();

        float acc[4][2];
#pragma unroll
        for (int bi = 0; bi < 4; bi++) {
            acc[bi][0] = 0.f;
            acc[bi][1] = 0.f;
        }

        for (int c = 0; c < NIT; c++) {
            const int buf = c & 1;
            const bool more = (c + 1 < NIT);
            if (more) cpaW(c + 1, buf ^ 1);   // buf^1 freed by previous barrier
            const float4* Wc = buf ? Wb1 : Wb0;
#pragma unroll
            for (int kq = 0; kq < 16; kq++) {
                const int sub = kq >> 2, kqi = kq & 3;
                const float4 w0 = Wc[sub * 768 + kqi * 48 + gofs0];
                const float4 w1 = Wc[sub * 768 + kqi * 48 + gofs1];
                const int kk = c * 16 + kq;
#pragma unroll
                for (int bi = 0; bi < 4; bi++) {
                    const float4 hv = Hs[(bloc0 + bi) * HS4 + kk];
                    acc[bi][0] += hv.x * w0.x + hv.y * w0.y + hv.z * w0.z + hv.w * w0.w;
                    acc[bi][1] += hv.x * w1.x + hv.y * w1.y + hv.z * w1.z + hv.w * w1.w;
                }
            }
            if (more) {
                CPA_WAIT_ALL();      // chunk c+1 landed (covered by compute)
                __syncthreads();     // frees buf for chunk c+2's cp.async
            }
        }

        if (gh == 1) {
#pragma unroll
            for (int bi = 0; bi < 4; bi++) {
                Gx[((bloc0 + bi) * 2 + 0) * 48 + tx] = acc[bi][0];  // gate g
                Gx[((bloc0 + bi) * 2 + 1) * 48 + tx] = acc[bi][1];  // gate o
            }
        }
        __syncthreads();

        if (gh == 0) {
            const float* HsF = (const float*)Hs;
#pragma unroll
            for (int bi = 0; bi < 4; bi++) {
                const int b = myb[bi];
                const int L = myL[bi];
                const bool alive = (t < L);
                const int src = dir ? (alive ? (L - 1 - t) : t) : t;
                float hold = HsF[(bloc0 + bi) * (HS4 * 4) + j];
                float hnew, outv;
                if (alive) {
                    const float* xr = xp + ((size_t)b * SEQ + src) * G4;
                    float zi = acc[bi][0] + xr[j];
                    float zf = acc[bi][1] + xr[HID + j];
                    float zg = Gx[((bloc0 + bi) * 2 + 0) * 48 + tx] + xr[2 * HID + j];
                    float zo = Gx[((bloc0 + bi) * 2 + 1) * 48 + tx] + xr[3 * HID + j];
                    float si = 1.f / (1.f + expf(-zi));
                    float sf = 1.f / (1.f + expf(-zf));
                    float so = 1.f / (1.f + expf(-zo));
                    float nc = sf * c4[bi] + si * tanhf(zg);
                    c4[bi] = nc;
                    hnew = so * tanhf(nc);
                    outv = hnew;
                } else {
                    hnew = hold;
                    outv = 0.f;
                }
                d_h[p ^ 1][dir][b][j] = hnew;
                enc[((size_t)b * SEQ + src) * E2 + dir * HID + j] = outv;
            }
        }
        group_bar(grp);
    }
}

// ---------------- attention tail ----------------
__global__ void scores_kernel(const float* __restrict__ we) {  // ekey lives in d_xpf
    const int warp = threadIdx.x >> 5, lane = threadIdx.x & 31;
    const size_t row = (size_t)blockIdx.x * 8 + warp;
    const float* r = d_xpf + row * E2;
    float s = 0.f;
    for (int k = lane; k < E2; k += 32) s += r[k] * we[k];
#pragma unroll
    for (int o = 16; o; o >>= 1) s += __shfl_down_sync(0xffffffffu, s, o);
    if (!lane) d_scores[row] = s;
}

__global__ void softmax_kernel(const int* __restrict__ lens) {
    __shared__ float red[512];
    const int b = blockIdx.x, t = threadIdx.x;
    const int L = lens[b];
    float v = (t < L) ? d_scores[b * SEQ + t] : -INFINITY;
    red[t] = v;
    __syncthreads();
    for (int s = 256; s > 0; s >>= 1) { if (t < s) red[t] = fmaxf(red[t], red[t + s]); __syncthreads(); }
    float m = red[0];
    __syncthreads();
    float e = (t < L) ? expf(v - m) : 0.f;
    red[t] = e;
    __syncthreads();
    for (int s = 256; s > 0; s >>= 1) { if (t < s) red[t] += red[t + s]; __syncthreads(); }
    d_attn[b * SEQ + t] = e / red[0];
}

__global__ void context_kernel() {
    const int b = blockIdx.y;
    const int h = blockIdx.x * 256 + threadIdx.x;
    float acc = 0.f;
    const float* a = d_attn + b * SEQ;
    const float* e = d_enc1 + (size_t)b * SEQ * E2 + h;
    for (int t = 0; t < SEQ; t++) acc += a[t] * e[(size_t)t * E2];
    d_ctx[b * E2 + h] = acc;
}

__global__ void post_kernel(const float* __restrict__ Wp, const float* __restrict__ bp) {
    const int b = blockIdx.y;
    const int n = blockIdx.x * 256 + threadIdx.x;
    float acc = bp[n];
    const float* c = d_ctx + b * E2;
    for (int k = 0; k < E2; k++) acc += c[k] * Wp[(size_t)k * E2 + n];
    d_ctx2[b * E2 + n] = acc;
}

__global__ void intents_kernel(const float* __restrict__ Wi, const float* __restrict__ bi, float* __restrict__ out) {
    const int b = blockIdx.x, n = threadIdx.x;
    if (n >= NINT) return;
    float acc = bi[n];
    const float* c = d_ctx2 + b * E2;
    for (int k = 0; k < E2; k++) acc += c[k] * Wi[k * NINT + n];
    out[b * NINT + n] = acc;
}

// ---------------- launch ----------------
extern "C" void kernel_launch(void* const* d_in, const int* in_sizes, int n_in,
                              void* d_out, int out_size) {
    const float* X    = (const float*)d_in[0];
    const int*   lens = (const int*)  d_in[1];
    const int s = (n_in >= 23) ? 3 : 2;  // skip is_test if present
    const float* W_reg  = (const float*)d_in[s + 0];
    const float* b_reg  = (const float*)d_in[s + 1];
    const float* Wi0f   = (const float*)d_in[s + 2];
    const float* Wh0f   = (const float*)d_in[s + 3];
    const float* b0f    = (const float*)d_in[s + 4];
    const float* Wi0b   = (const float*)d_in[s + 5];
    const float* Wh0b   = (const float*)d_in[s + 6];
    const float* b0b    = (const float*)d_in[s + 7];
    const float* Wi1f   = (const float*)d_in[s + 8];
    const float* Wh1f   = (const float*)d_in[s + 9];
    const float* b1f    = (const float*)d_in[s + 10];
    const float* Wi1b   = (const float*)d_in[s + 11];
    const float* Wh1b   = (const float*)d_in[s + 12];
    const float* b1b    = (const float*)d_in[s + 13];
    const float* W_keys = (const float*)d_in[s + 14];
    const float* W_en   = (const float*)d_in[s + 15];
    const float* W_post = (const float*)d_in[s + 16];
    const float* b_post = (const float*)d_in[s + 17];
    const float* W_int  = (const float*)d_in[s + 18];
    const float* b_int  = (const float*)d_in[s + 19];

    cudaFuncSetAttribute(lstm_layer, cudaFuncAttributeMaxDynamicSharedMemorySize, LSTM_SMEM);

    // blocked recurrent weights
    conv_wblk2<<<1536, 192>>>(Wh0f, Wh0b, 0);
    conv_wblk2<<<1536, 192>>>(Wh1f, Wh1b, 2);

    // reg = X @ W_reg + b_reg
    gemm1<false><<<dim3(DENSE / 128, MT / 128), 256>>>(X, -1, W_reg, b_reg, 0, DENSE, DIN, lens);

    // layer-0 input projections
    gemm1<false><<<dim3(G4 / 128, MT / 128), 256>>>(nullptr, 0, Wi0f, b0f, 1, G4, DENSE, lens);
    gemm1<false><<<dim3(G4 / 128, MT / 128), 256>>>(nullptr, 0, Wi0b, b0b, 2, G4, DENSE, lens);

    // layer-0 recurrence -> enc0
    lstm_layer<<<128, 384, LSTM_SMEM>>>(0, lens);

    // layer-1 input projections
    gemm1<false><<<dim3(G4 / 128, MT / 128), 256>>>(nullptr, 3, Wi1f, b1f, 1, G4, E2, lens);
    gemm1<false><<<dim3(G4 / 128, MT / 128), 256>>>(nullptr, 3, Wi1b, b1b, 2, G4, E2, lens);

    // layer-1 recurrence -> enc1
    lstm_layer<<<128, 384, LSTM_SMEM>>>(1, lens);

    // ekey = tanh(enc1 @ W_keys) -> d_xpf
    gemm1<true><<<dim3(E2 / 128, MT / 128), 256>>>(nullptr, 4, W_keys, nullptr, 1, E2, E2, lens);

    // attention tail
    scores_kernel<<<MT / 8, 256>>>(W_en);
    softmax_kernel<<<BATCH, 512>>>(lens);
    context_kernel<<<dim3(E2 / 256, BATCH), 256>>>();
    post_kernel<<<dim3(E2 / 256, BATCH), 256>>>(W_post, b_post);
    intents_kernel<<<BATCH, 64>>>(W_int, b_int, (float*)d_out);
}

// round 16
// speedup vs baseline: 3.7780x; 1.0278x over previous
#include <cuda_runtime.h>
#include <math.h>
#include <stdint.h>

#define BATCH 64
#define SEQ   512
#define DIN   1024
#define DENSE 1024
#define HID   768
#define G4    (4*HID)    // 3072
#define E2    (2*HID)    // 1536
#define NINT  60
#define MT    (BATCH*SEQ) // 32768

// ---------------- static device buffers ----------------
__device__ float d_reg [(size_t)MT * DENSE];
__device__ float d_xpf [(size_t)MT * G4];
__device__ float d_xpb [(size_t)MT * G4];
__device__ float d_enc0[(size_t)MT * E2];
__device__ float d_enc1[(size_t)MT * E2];
// resident recurrent weights: [ld(4)][jt(64)][k(768)][jl(12)][g(4)] floats
#define WRES_F 36864   // floats per (ld, jt) slice
__device__ float d_wres[(size_t)4 * 64 * WRES_F];
__device__ float d_hT  [2][2][HID][BATCH];      // [parity][dir][j][b] (transposed)
__device__ float d_scores[MT];
__device__ float d_attn  [MT];
__device__ float d_ctx [BATCH * E2];
__device__ float d_ctx2[BATCH * E2];
__device__ unsigned d_gbar_cnt[2];
__device__ volatile unsigned d_gbar_gen[2];

__device__ __forceinline__ float* buf_sel(int s) {
    switch (s) {
        case 0: return d_reg;
        case 1: return d_xpf;
        case 2: return d_xpb;
        case 3: return d_enc0;
        default: return d_enc1;
    }
}

// ---------------- cp.async helpers ----------------
__device__ __forceinline__ uint32_t sptr(const void* p) {
    return (uint32_t)__cvta_generic_to_shared(p);
}
__device__ __forceinline__ void cpa16(uint32_t d, const void* s) {
    asm volatile("cp.async.cg.shared.global [%0], [%1], 16;" :: "r"(d), "l"(s));
}
#define CPA_COMMIT() asm volatile("cp.async.commit_group;")
#define CPA_WAIT_ALL() asm volatile("cp.async.wait_group 0;")

// ---------------- group barrier: 64 blocks sharing one dir ----------------
__device__ __forceinline__ void group_bar(int g) {
    __syncthreads();
    if (threadIdx.x == 0) {
        unsigned gen = d_gbar_gen[g];
        __threadfence();
        unsigned arrived = atomicAdd(&d_gbar_cnt[g], 1u);
        if (arrived == 63u) {
            d_gbar_cnt[g] = 0;
            __threadfence();
            d_gbar_gen[g] = gen + 1;
        } else {
            while (d_gbar_gen[g] == gen) { }
        }
        __threadfence();
    }
    __syncthreads();
}

// ================= FFMA SGEMM v2 (R12, unchanged) =================
template <bool TANH>
__global__ void __launch_bounds__(256, 2) gemm1(
    const float* __restrict__ Aext, int aSel,
    const float* __restrict__ W, const float* __restrict__ bias,
    int cSel, int N, int K, const int* __restrict__ lens)
{
    const int bm = blockIdx.y * 128;
    if (lens) {
        const int b = bm >> 9, t0 = bm & 511;
        if (t0 >= lens[b]) return;   // dead rows: outputs never consumed
    }
    const float* __restrict__ A = (aSel < 0) ? Aext : buf_sel(aSel);
    float* __restrict__ C = buf_sel(cSel);

    __shared__ float As[2][8][128];
    __shared__ float Bs[2][8][128];

    const int tid = threadIdx.x;
    const int bn = blockIdx.x * 128;
    const int a_m = tid >> 1;
    const int a_k = (tid & 1) * 4;
    const int b_k = tid >> 5;
    const int b_n = (tid & 31) * 4;
    const int tx = tid & 15;
    const int ty = tid >> 4;

    const uint32_t bsAddr0 = sptr(&Bs[0][b_k][b_n]);
    const uint32_t bsAddr1 = sptr(&Bs[1][b_k][b_n]);

    float acc[8][8];
#pragma unroll
    for (int i = 0; i < 8; i++)
#pragma unroll
        for (int j = 0; j < 8; j++) acc[i][j] = 0.f;

    const int NT = K >> 3;
    float4 av;

    auto cpaB = [&](int kt, int buf) {
        cpa16(buf ? bsAddr1 : bsAddr0, &W[(size_t)((kt << 3) + b_k) * N + bn + b_n]);
        CPA_COMMIT();
    };
    auto loadA = [&](int kt) {
        av = *(const float4*)&A[(size_t)(bm + a_m) * K + (kt << 3) + a_k];
    };
    auto storeA = [&](int buf) {
        As[buf][a_k + 0][a_m] = av.x;
        As[buf][a_k + 1][a_m] = av.y;
        As[buf][a_k + 2][a_m] = av.z;
        As[buf][a_k + 3][a_m] = av.w;
    };

    cpaB(0, 0);
    loadA(0);
    storeA(0);
    if (NT > 1) loadA(1);
    CPA_WAIT_ALL();
    __syncthreads();

    for (int kt = 0; kt < NT; kt++) {
        const int buf = kt & 1;
        const bool more = (kt + 1 < NT);
        if (more) cpaB(kt + 1, buf ^ 1);

#pragma unroll
        for (int kk = 0; kk < 8; kk++) {
            float ar[8], br[8];
            *(float4*)&ar[0] = *(const float4*)&As[buf][kk][ty * 4];
            *(float4*)&ar[4] = *(const float4*)&As[buf][kk][64 + ty * 4];
            *(float4*)&br[0] = *(const float4*)&Bs[buf][kk][tx * 4];
            *(float4*)&br[4] = *(const float4*)&Bs[buf][kk][64 + tx * 4];
#pragma unroll
            for (int i = 0; i < 8; i++)
#pragma unroll
                for (int j = 0; j < 8; j++)
                    acc[i][j] = fmaf(ar[i], br[j], acc[i][j]);
        }

        if (more) {
            storeA(buf ^ 1);
            if (kt + 2 < NT) loadA(kt + 2);
            CPA_WAIT_ALL();
            __syncthreads();
        }
    }

#pragma unroll
    for (int hm = 0; hm < 2; hm++) {
#pragma unroll
        for (int i = 0; i < 4; i++) {
            int r = bm + hm * 64 + ty * 4 + i;
            int ri = hm * 4 + i;
#pragma unroll
            for (int hn = 0; hn < 2; hn++) {
                int cb = bn + hn * 64 + tx * 4;
                float4 v;
                v.x = acc[ri][hn * 4 + 0] + (bias ? bias[cb + 0] : 0.f);
                v.y = acc[ri][hn * 4 + 1] + (bias ? bias[cb + 1] : 0.f);
                v.z = acc[ri][hn * 4 + 2] + (bias ? bias[cb + 2] : 0.f);
                v.w = acc[ri][hn * 4 + 3] + (bias ? bias[cb + 3] : 0.f);
                if (TANH) { v.x = tanhf(v.x); v.y = tanhf(v.y); v.z = tanhf(v.z); v.w = tanhf(v.w); }
                *(float4*)&C[(size_t)r * N + cb] = v;
            }
        }
    }
}

// ---------------- build resident recurrent weights -----------------------------
// grid 256 = ld(4) x jt(64), 384 threads.
// d_wres[(ld*64+jt)*36864 + k*48 + jl*4 + g] = Wh_ld[k][g*HID + jt*12 + jl]
__global__ void conv_wres(const float* __restrict__ W0, const float* __restrict__ W1,
                          const float* __restrict__ W2, const float* __restrict__ W3) {
    const int ld = blockIdx.x >> 6, jt = blockIdx.x & 63;
    const float* W = (ld == 0) ? W0 : (ld == 1) ? W1 : (ld == 2) ? W2 : W3;
    float* dst = d_wres + (size_t)(ld * 64 + jt) * WRES_F;
    for (int i = threadIdx.x; i < WRES_F; i += 384) {
        int k = i / 48, r = i % 48, jl = r >> 2, g = r & 3;
        dst[i] = W[(size_t)k * G4 + g * HID + jt * 12 + jl];
    }
}

// ---------------- persistent BiLSTM layer v8: resident weights -----------------
// 128 blocks = dir(2) x jt(64), 384 threads. Thread = (jl = tid>>5, bq = tid&31):
// owns j = jt*12+jl, batches 2bq,2bq+1, ALL 4 gates (8 acc) — no recombination.
// Weights (147KB) loaded ONCE into smem before the time loop. h transposed [j][b]
// in global; per step only h chunks (16KB x12, double-buffered cp.async) + Xs move.
// h state held in registers (thread owns its (j,b) pair across all steps).
#define HCH   4096                 // floats per h chunk (64 k x 64 b)
#define XROW  52                   // padded Xs row (floats)
#define SM_W  0
#define SM_H  WRES_F               // 36864
#define SM_X  (WRES_F + 2 * HCH)   // 45056
#define SM_L  (SM_X + 64 * XROW)   // 48384
#define LSTM_SMEM ((SM_L + 64) * 4)  // 193,792 B

__global__ void __launch_bounds__(384, 1) lstm_layer(int layer, const int* __restrict__ lens) {
    extern __shared__ float smf[];
    float* Wres = smf + SM_W;      // [768][12][4]
    float* HsB  = smf + SM_H;      // 2 x [64][64]
    float* Xs   = smf + SM_X;      // [64][XROW] : [b][g*12+jl]
    int*   lenS = (int*)(smf + SM_L);

    const int tid = threadIdx.x;
    const int dir = blockIdx.x >> 6;
    const int jt  = blockIdx.x & 63;
    const int jl  = tid >> 5;          // 0..11
    const int bq  = tid & 31;          // 0..31
    const int j   = jt * 12 + jl;
    const int b0  = bq * 2;

    const float* xp = dir ? d_xpb : d_xpf;
    float* enc = layer ? d_enc1 : d_enc0;
    const float* wsrc = d_wres + (size_t)((layer * 2 + dir) * 64 + jt) * WRES_F;

    // load lens + resident weights
    if (tid < 64) lenS[tid] = lens[tid];
    {
        const float4* s4 = (const float4*)wsrc;
        float4* d4 = (float4*)Wres;
        for (int i = tid; i < WRES_F / 4; i += 384) d4[i] = s4[i];
    }
    __syncthreads();

    int gML = 0;
#pragma unroll
    for (int i = 0; i < 64; i++) gML = max(gML, lenS[i]);
    const int L0 = lenS[b0], L1 = lenS[b0 + 1];

    // zero h parity-0 for this block's j-slice (all batches)
    for (int i = tid; i < 12 * 64; i += 384)
        d_hT[0][dir][jt * 12 + (i >> 6)][i & 63] = 0.f;
    float hreg[2] = {0.f, 0.f};
    float c2[2] = {0.f, 0.f};
    group_bar(dir);

    const uint32_t hsAddr = sptr(HsB);
    const uint32_t xsAddr = sptr(Xs);

    for (int t = 0; t < gML; t++) {
        const int p = t & 1;
        const float4* hsrc4 = (const float4*)&d_hT[p][dir][0][0];  // 12288 f4

        auto stageH = [&](int c, int buf) {
            const float4* s = hsrc4 + c * (HCH / 4);
            const uint32_t d = hsAddr + buf * (HCH * 4);
#pragma unroll
            for (int q = 0; q < 3; q++) {
                int idx = tid + q * 384;
                if (idx < HCH / 4) cpa16(d + idx * 16, s + idx);
            }
            CPA_COMMIT();
        };

        // stage h chunk 0 + Xs (x-projection slice, [b][g*12+jl], 48B per (b,g))
        stageH(0, 0);
#pragma unroll
        for (int q = 0; q < 2; q++) {
            int ci = tid + q * 384;            // 0..767
            int b = ci / 12, r = ci % 12;
            int g = r / 3, part = r % 3;
            int L = lenS[b];
            int src = (t < L) ? (dir ? (L - 1 - t) : t) : t;
            cpa16(xsAddr + (uint32_t)(b * XROW + g * 12 + part * 4) * 4,
                  xp + ((size_t)b * SEQ + src) * G4 + g * HID + jt * 12 + part * 4);
        }
        CPA_COMMIT();
        CPA_WAIT_ALL();
        __syncthreads();

        float acc[2][4];
#pragma unroll
        for (int bi = 0; bi < 2; bi++)
#pragma unroll
            for (int g = 0; g < 4; g++) acc[bi][g] = 0.f;

        for (int c = 0; c < 12; c++) {
            const int buf = c & 1;
            const bool more = (c + 1 < 12);
            if (more) stageH(c + 1, buf ^ 1);   // buf^1 freed by previous barrier
            const float* H = HsB + buf * HCH;
            const float* Wc = Wres + c * 64 * 48;
#pragma unroll 8
            for (int kk = 0; kk < 64; kk++) {
                const float4 w = *(const float4*)&Wc[kk * 48 + jl * 4];
                const float2 hv = *(const float2*)&H[kk * 64 + b0];
                acc[0][0] += hv.x * w.x;
                acc[0][1] += hv.x * w.y;
                acc[0][2] += hv.x * w.z;
                acc[0][3] += hv.x * w.w;
                acc[1][0] += hv.y * w.x;
                acc[1][1] += hv.y * w.y;
                acc[1][2] += hv.y * w.z;
                acc[1][3] += hv.y * w.w;
            }
            if (more) {
                CPA_WAIT_ALL();
                __syncthreads();
            }
        }

        // thread-local pointwise (all 4 gates owned here)
#pragma unroll
        for (int bi = 0; bi < 2; bi++) {
            const int b = b0 + bi;
            const int L = bi ? L1 : L0;
            const bool alive = (t < L);
            const int src = alive ? (dir ? (L - 1 - t) : t) : t;
            float hnew, outv;
            if (alive) {
                const float* xr = Xs + b * XROW;
                float zi = acc[bi][0] + xr[jl];
                float zf = acc[bi][1] + xr[12 + jl];
                float zg = acc[bi][2] + xr[24 + jl];
                float zo = acc[bi][3] + xr[36 + jl];
                float si = 1.f / (1.f + expf(-zi));
                float sf = 1.f / (1.f + expf(-zf));
                float so = 1.f / (1.f + expf(-zo));
                float nc = sf * c2[bi] + si * tanhf(zg);
                c2[bi] = nc;
                hnew = so * tanhf(nc);
                outv = hnew;
            } else {
                hnew = hreg[bi];
                outv = 0.f;
            }
            hreg[bi] = hnew;
            enc[((size_t)b * SEQ + src) * E2 + dir * HID + j] = outv;
        }
        *(float2*)&d_hT[p ^ 1][dir][j][b0] = make_float2(hreg[0], hreg[1]);

        group_bar(dir);
    }
}

// ---------------- attention tail ----------------
__global__ void scores_kernel(const float* __restrict__ we) {  // ekey lives in d_xpf
    const int warp = threadIdx.x >> 5, lane = threadIdx.x & 31;
    const size_t row = (size_t)blockIdx.x * 8 + warp;
    const float* r = d_xpf + row * E2;
    float s = 0.f;
    for (int k = lane; k < E2; k += 32) s += r[k] * we[k];
#pragma unroll
    for (int o = 16; o; o >>= 1) s += __shfl_down_sync(0xffffffffu, s, o);
    if (!lane) d_scores[row] = s;
}

__global__ void softmax_kernel(const int* __restrict__ lens) {
    __shared__ float red[512];
    const int b = blockIdx.x, t = threadIdx.x;
    const int L = lens[b];
    float v = (t < L) ? d_scores[b * SEQ + t] : -INFINITY;
    red[t] = v;
    __syncthreads();
    for (int s = 256; s > 0; s >>= 1) { if (t < s) red[t] = fmaxf(red[t], red[t + s]); __syncthreads(); }
    float m = red[0];
    __syncthreads();
    float e = (t < L) ? expf(v - m) : 0.f;
    red[t] = e;
    __syncthreads();
    for (int s = 256; s > 0; s >>= 1) { if (t < s) red[t] += red[t + s]; __syncthreads(); }
    d_attn[b * SEQ + t] = e / red[0];
}

__global__ void context_kernel() {
    const int b = blockIdx.y;
    const int h = blockIdx.x * 256 + threadIdx.x;
    float acc = 0.f;
    const float* a = d_attn + b * SEQ;
    const float* e = d_enc1 + (size_t)b * SEQ * E2 + h;
    for (int t = 0; t < SEQ; t++) acc += a[t] * e[(size_t)t * E2];
    d_ctx[b * E2 + h] = acc;
}

__global__ void post_kernel(const float* __restrict__ Wp, const float* __restrict__ bp) {
    const int b = blockIdx.y;
    const int n = blockIdx.x * 256 + threadIdx.x;
    float acc = bp[n];
    const float* c = d_ctx + b * E2;
    for (int k = 0; k < E2; k++) acc += c[k] * Wp[(size_t)k * E2 + n];
    d_ctx2[b * E2 + n] = acc;
}

__global__ void intents_kernel(const float* __restrict__ Wi, const float* __restrict__ bi, float* __restrict__ out) {
    const int b = blockIdx.x, n = threadIdx.x;
    if (n >= NINT) return;
    float acc = bi[n];
    const float* c = d_ctx2 + b * E2;
    for (int k = 0; k < E2; k++) acc += c[k] * Wi[k * NINT + n];
    out[b * NINT + n] = acc;
}

// ---------------- launch ----------------
extern "C" void kernel_launch(void* const* d_in, const int* in_sizes, int n_in,
                              void* d_out, int out_size) {
    const float* X    = (const float*)d_in[0];
    const int*   lens = (const int*)  d_in[1];
    const int s = (n_in >= 23) ? 3 : 2;  // skip is_test if present
    const float* W_reg  = (const float*)d_in[s + 0];
    const float* b_reg  = (const float*)d_in[s + 1];
    const float* Wi0f   = (const float*)d_in[s + 2];
    const float* Wh0f   = (const float*)d_in[s + 3];
    const float* b0f    = (const float*)d_in[s + 4];
    const float* Wi0b   = (const float*)d_in[s + 5];
    const float* Wh0b   = (const float*)d_in[s + 6];
    const float* b0b    = (const float*)d_in[s + 7];
    const float* Wi1f   = (const float*)d_in[s + 8];
    const float* Wh1f   = (const float*)d_in[s + 9];
    const float* b1f    = (const float*)d_in[s + 10];
    const float* Wi1b   = (const float*)d_in[s + 11];
    const float* Wh1b   = (const float*)d_in[s + 12];
    const float* b1b    = (const float*)d_in[s + 13];
    const float* W_keys = (const float*)d_in[s + 14];
    const float* W_en   = (const float*)d_in[s + 15];
    const float* W_post = (const float*)d_in[s + 16];
    const float* b_post = (const float*)d_in[s + 17];
    const float* W_int  = (const float*)d_in[s + 18];
    const float* b_int  = (const float*)d_in[s + 19];

    cudaFuncSetAttribute(lstm_layer, cudaFuncAttributeMaxDynamicSharedMemorySize, LSTM_SMEM);

    // resident recurrent weights (all 4 (layer,dir) slices)
    conv_wres<<<256, 384>>>(Wh0f, Wh0b, Wh1f, Wh1b);

    // reg = X @ W_reg + b_reg
    gemm1<false><<<dim3(DENSE / 128, MT / 128), 256>>>(X, -1, W_reg, b_reg, 0, DENSE, DIN, lens);

    // layer-0 input projections
    gemm1<false><<<dim3(G4 / 128, MT / 128), 256>>>(nullptr, 0, Wi0f, b0f, 1, G4, DENSE, lens);
    gemm1<false><<<dim3(G4 / 128, MT / 128), 256>>>(nullptr, 0, Wi0b, b0b, 2, G4, DENSE, lens);

    // layer-0 recurrence -> enc0
    lstm_layer<<<128, 384, LSTM_SMEM>>>(0, lens);

    // layer-1 input projections
    gemm1<false><<<dim3(G4 / 128, MT / 128), 256>>>(nullptr, 3, Wi1f, b1f, 1, G4, E2, lens);
    gemm1<false><<<dim3(G4 / 128, MT / 128), 256>>>(nullptr, 3, Wi1b, b1b, 2, G4, E2, lens);

    // layer-1 recurrence -> enc1
    lstm_layer<<<128, 384, LSTM_SMEM>>>(1, lens);

    // ekey = tanh(enc1 @ W_keys) -> d_xpf
    gemm1<true><<<dim3(E2 / 128, MT / 128), 256>>>(nullptr, 4, W_keys, nullptr, 1, E2, E2, lens);

    // attention tail
    scores_kernel<<<MT / 8, 256>>>(W_en);
    softmax_kernel<<<BATCH, 512>>>(lens);
    context_kernel<<<dim3(E2 / 256, BATCH), 256>>>();
    post_kernel<<<dim3(E2 / 256, BATCH), 256>>>(W_post, b_post);
    intents_kernel<<<BATCH, 64>>>(W_int, b_int, (float*)d_out);
}

// round 17
// speedup vs baseline: 4.1894x; 1.1089x over previous
#include <cuda_runtime.h>
#include <math.h>
#include <stdint.h>

#define BATCH 64
#define SEQ   512
#define DIN   1024
#define DENSE 1024
#define HID   768
#define G4    (4*HID)    // 3072
#define E2    (2*HID)    // 1536
#define NINT  60
#define MT    (BATCH*SEQ) // 32768

// ---------------- static device buffers ----------------
__device__ float d_xT   [(size_t)DIN * MT];     // X transposed [k][m]
__device__ float d_regT [(size_t)DENSE * MT];   // reg transposed [k][m]
__device__ float d_xpf  [(size_t)MT * G4];
__device__ float d_xpb  [(size_t)MT * G4];
__device__ float d_enc0T[(size_t)E2 * MT];      // enc0 transposed [n][m]
__device__ float d_enc1T[(size_t)E2 * MT];      // enc1 transposed [n][m]
// resident recurrent weights: [ld(4)][jt(64)][k(768)][jl(12)][g(4)] floats
#define WRES_F 36864
__device__ float d_wres[(size_t)4 * 64 * WRES_F];
__device__ float d_hT  [2][2][HID][BATCH];      // [parity][dir][j][b]
__device__ float d_scores[MT];
__device__ float d_attn  [MT];
__device__ float d_ctx [BATCH * E2];
__device__ float d_ctx2[BATCH * E2];
__device__ unsigned d_gbar_cnt[2];
__device__ volatile unsigned d_gbar_gen[2];

// ---------------- cp.async helpers ----------------
__device__ __forceinline__ uint32_t sptr(const void* p) {
    return (uint32_t)__cvta_generic_to_shared(p);
}
__device__ __forceinline__ void cpa16(uint32_t d, const void* s) {
    asm volatile("cp.async.cg.shared.global [%0], [%1], 16;" :: "r"(d), "l"(s));
}
#define CPA_COMMIT() asm volatile("cp.async.commit_group;")
#define CPA_WAIT_ALL() asm volatile("cp.async.wait_group 0;")

// ---------------- group barrier: 64 blocks sharing one dir ----------------
__device__ __forceinline__ void group_bar(int g) {
    __syncthreads();
    if (threadIdx.x == 0) {
        unsigned gen = d_gbar_gen[g];
        __threadfence();
        unsigned arrived = atomicAdd(&d_gbar_cnt[g], 1u);
        if (arrived == 63u) {
            d_gbar_cnt[g] = 0;
            __threadfence();
            d_gbar_gen[g] = gen + 1;
        } else {
            while (d_gbar_gen[g] == gen) { }
        }
        __threadfence();
    }
    __syncthreads();
}

// ================= gemmT: both operands k-major, full cp.async =================
// C[M,N] = act(A^T-stored[K][MT] @ W[K,N] + bias). Tile 128x128, Kt=16,
// 256 threads, 8x8 microtile (4+4 split), LDS.128 fragments (gemm1 pattern).
// ONE barrier per 16-k tile; zero register staging.
// CT: write C transposed (scattered; used only for the small reg GEMM).
template <bool TANH, bool CT>
__global__ void __launch_bounds__(256, 2) gemmT(
    int aSel, const float* __restrict__ W, const float* __restrict__ bias,
    int cSel, int N, int K, const int* __restrict__ lens)
{
    const int bm = blockIdx.y * 128;
    if (lens) {
        const int b = bm >> 9, t0 = bm & 511;
        if (t0 >= lens[b]) return;   // dead rows: outputs never consumed
    }
    const float* __restrict__ A =
        (aSel == 0) ? d_xT : (aSel == 1) ? d_regT : (aSel == 2) ? d_enc0T : d_enc1T;
    float* __restrict__ C = (cSel == 0) ? d_regT : (cSel == 1) ? d_xpf : d_xpb;

    __shared__ float As[2][16][128];
    __shared__ float Bs[2][16][128];

    const int tid = threadIdx.x;
    const int bn = blockIdx.x * 128;
    const int tx = tid & 15;
    const int ty = tid >> 4;

    // stage chunk indices: 512 f4 chunks per operand per tile, 2 per thread
    const int kr0 = tid >> 5,          o0 = (tid & 31) * 4;
    const int kr1 = (tid + 256) >> 5,  o1 = (tid & 31) * 4;  // +256 keeps o same

    const uint32_t asb = sptr(&As[0][0][0]);
    const uint32_t bsb = sptr(&Bs[0][0][0]);

    auto stage = [&](int kt, int buf) {
        const int k0 = kt << 4;
        const uint32_t ab = asb + (uint32_t)buf * (16 * 128 * 4);
        const uint32_t bb = bsb + (uint32_t)buf * (16 * 128 * 4);
        cpa16(ab + (uint32_t)(kr0 * 128 + o0) * 4, &A[(size_t)(k0 + kr0) * MT + bm + o0]);
        cpa16(ab + (uint32_t)(kr1 * 128 + o1) * 4, &A[(size_t)(k0 + kr1) * MT + bm + o1]);
        cpa16(bb + (uint32_t)(kr0 * 128 + o0) * 4, &W[(size_t)(k0 + kr0) * N + bn + o0]);
        cpa16(bb + (uint32_t)(kr1 * 128 + o1) * 4, &W[(size_t)(k0 + kr1) * N + bn + o1]);
        CPA_COMMIT();
    };

    float acc[8][8];
#pragma unroll
    for (int i = 0; i < 8; i++)
#pragma unroll
        for (int j = 0; j < 8; j++) acc[i][j] = 0.f;

    const int NT = K >> 4;

    stage(0, 0);
    CPA_WAIT_ALL();
    __syncthreads();

    for (int kt = 0; kt < NT; kt++) {
        const int buf = kt & 1;
        const bool more = (kt + 1 < NT);
        if (more) stage(kt + 1, buf ^ 1);   // buf^1 freed by previous barrier

#pragma unroll
        for (int kk = 0; kk < 16; kk++) {
            float ar[8], br[8];
            *(float4*)&ar[0] = *(const float4*)&As[buf][kk][ty * 4];
            *(float4*)&ar[4] = *(const float4*)&As[buf][kk][64 + ty * 4];
            *(float4*)&br[0] = *(const float4*)&Bs[buf][kk][tx * 4];
            *(float4*)&br[4] = *(const float4*)&Bs[buf][kk][64 + tx * 4];
#pragma unroll
            for (int i = 0; i < 8; i++)
#pragma unroll
                for (int j = 0; j < 8; j++)
                    acc[i][j] = fmaf(ar[i], br[j], acc[i][j]);
        }

        if (more) {
            CPA_WAIT_ALL();    // tile kt+1 landed (covered by compute)
            __syncthreads();   // one barrier per tile
        }
    }

    // epilogue
#pragma unroll
    for (int hm = 0; hm < 2; hm++) {
#pragma unroll
        for (int i = 0; i < 4; i++) {
            const int row = bm + hm * 64 + ty * 4 + i;
            const int ri = hm * 4 + i;
#pragma unroll
            for (int hn = 0; hn < 2; hn++) {
                const int cb = bn + hn * 64 + tx * 4;
                float4 v;
                v.x = acc[ri][hn * 4 + 0] + (bias ? bias[cb + 0] : 0.f);
                v.y = acc[ri][hn * 4 + 1] + (bias ? bias[cb + 1] : 0.f);
                v.z = acc[ri][hn * 4 + 2] + (bias ? bias[cb + 2] : 0.f);
                v.w = acc[ri][hn * 4 + 3] + (bias ? bias[cb + 3] : 0.f);
                if (TANH) { v.x = tanhf(v.x); v.y = tanhf(v.y); v.z = tanhf(v.z); v.w = tanhf(v.w); }
                if (CT) {
                    C[(size_t)(cb + 0) * MT + row] = v.x;
                    C[(size_t)(cb + 1) * MT + row] = v.y;
                    C[(size_t)(cb + 2) * MT + row] = v.z;
                    C[(size_t)(cb + 3) * MT + row] = v.w;
                } else {
                    *(float4*)&C[(size_t)row * N + cb] = v;
                }
            }
        }
    }
}

// ---------------- X transpose: X[m][k] -> d_xT[k][m] ----------------
__global__ void transpose_x(const float* __restrict__ X) {
    __shared__ float tile[32][33];
    const int m0 = blockIdx.x * 32, k0 = blockIdx.y * 32;
    const int tx = threadIdx.x, ty = threadIdx.y;
    for (int i = ty; i < 32; i += 8)
        tile[i][tx] = X[(size_t)(m0 + i) * DIN + k0 + tx];
    __syncthreads();
    for (int i = ty; i < 32; i += 8)
        d_xT[(size_t)(k0 + i) * MT + m0 + tx] = tile[tx][i];
}

// ---------------- build resident recurrent weights -----------------------------
__global__ void conv_wres(const float* __restrict__ W0, const float* __restrict__ W1,
                          const float* __restrict__ W2, const float* __restrict__ W3) {
    const int ld = blockIdx.x >> 6, jt = blockIdx.x & 63;
    const float* W = (ld == 0) ? W0 : (ld == 1) ? W1 : (ld == 2) ? W2 : W3;
    float* dst = d_wres + (size_t)(ld * 64 + jt) * WRES_F;
    for (int i = threadIdx.x; i < WRES_F; i += 384) {
        int k = i / 48, r = i % 48, jl = r >> 2, g = r & 3;
        dst[i] = W[(size_t)k * G4 + g * HID + jt * 12 + jl];
    }
}

// ---------------- persistent BiLSTM layer v8 (R16) — enc written TRANSPOSED ----
#define HCH   4096                 // floats per h chunk (64 k x 64 b)
#define XROW  52                   // padded Xs row (floats)
#define SM_W  0
#define SM_H  WRES_F               // 36864
#define SM_X  (WRES_F + 2 * HCH)   // 45056
#define SM_L  (SM_X + 64 * XROW)   // 48384
#define LSTM_SMEM ((SM_L + 64) * 4)  // 193,792 B

__global__ void __launch_bounds__(384, 1) lstm_layer(int layer, const int* __restrict__ lens) {
    extern __shared__ float smf[];
    float* Wres = smf + SM_W;      // [768][12][4]
    float* HsB  = smf + SM_H;      // 2 x [64][64]
    float* Xs   = smf + SM_X;      // [64][XROW]
    int*   lenS = (int*)(smf + SM_L);

    const int tid = threadIdx.x;
    const int dir = blockIdx.x >> 6;
    const int jt  = blockIdx.x & 63;
    const int jl  = tid >> 5;          // 0..11
    const int bq  = tid & 31;          // 0..31
    const int j   = jt * 12 + jl;
    const int b0  = bq * 2;

    const float* xp = dir ? d_xpb : d_xpf;
    float* encT = layer ? d_enc1T : d_enc0T;
    const float* wsrc = d_wres + (size_t)((layer * 2 + dir) * 64 + jt) * WRES_F;

    if (tid < 64) lenS[tid] = lens[tid];
    {
        const float4* s4 = (const float4*)wsrc;
        float4* d4 = (float4*)Wres;
        for (int i = tid; i < WRES_F / 4; i += 384) d4[i] = s4[i];
    }
    __syncthreads();

    int gML = 0;
#pragma unroll
    for (int i = 0; i < 64; i++) gML = max(gML, lenS[i]);
    const int L0 = lenS[b0], L1 = lenS[b0 + 1];

    for (int i = tid; i < 12 * 64; i += 384)
        d_hT[0][dir][jt * 12 + (i >> 6)][i & 63] = 0.f;
    float hreg[2] = {0.f, 0.f};
    float c2[2] = {0.f, 0.f};
    group_bar(dir);

    const uint32_t hsAddr = sptr(HsB);
    const uint32_t xsAddr = sptr(Xs);

    for (int t = 0; t < gML; t++) {
        const int p = t & 1;
        const float4* hsrc4 = (const float4*)&d_hT[p][dir][0][0];

        auto stageH = [&](int c, int buf) {
            const float4* s = hsrc4 + c * (HCH / 4);
            const uint32_t d = hsAddr + buf * (HCH * 4);
#pragma unroll
            for (int q = 0; q < 3; q++) {
                int idx = tid + q * 384;
                if (idx < HCH / 4) cpa16(d + idx * 16, s + idx);
            }
            CPA_COMMIT();
        };

        stageH(0, 0);
#pragma unroll
        for (int q = 0; q < 2; q++) {
            int ci = tid + q * 384;
            int b = ci / 12, r = ci % 12;
            int g = r / 3, part = r % 3;
            int L = lenS[b];
            int src = (t < L) ? (dir ? (L - 1 - t) : t) : t;
            cpa16(xsAddr + (uint32_t)(b * XROW + g * 12 + part * 4) * 4,
                  xp + ((size_t)b * SEQ + src) * G4 + g * HID + jt * 12 + part * 4);
        }
        CPA_COMMIT();
        CPA_WAIT_ALL();
        __syncthreads();

        float acc[2][4];
#pragma unroll
        for (int bi = 0; bi < 2; bi++)
#pragma unroll
            for (int g = 0; g < 4; g++) acc[bi][g] = 0.f;

        for (int c = 0; c < 12; c++) {
            const int buf = c & 1;
            const bool more = (c + 1 < 12);
            if (more) stageH(c + 1, buf ^ 1);
            const float* H = HsB + buf * HCH;
            const float* Wc = Wres + c * 64 * 48;
#pragma unroll 8
            for (int kk = 0; kk < 64; kk++) {
                const float4 w = *(const float4*)&Wc[kk * 48 + jl * 4];
                const float2 hv = *(const float2*)&H[kk * 64 + b0];
                acc[0][0] += hv.x * w.x;
                acc[0][1] += hv.x * w.y;
                acc[0][2] += hv.x * w.z;
                acc[0][3] += hv.x * w.w;
                acc[1][0] += hv.y * w.x;
                acc[1][1] += hv.y * w.y;
                acc[1][2] += hv.y * w.z;
                acc[1][3] += hv.y * w.w;
            }
            if (more) {
                CPA_WAIT_ALL();
                __syncthreads();
            }
        }

#pragma unroll
        for (int bi = 0; bi < 2; bi++) {
            const int b = b0 + bi;
            const int L = bi ? L1 : L0;
            const bool alive = (t < L);
            const int src = alive ? (dir ? (L - 1 - t) : t) : t;
            float hnew, outv;
            if (alive) {
                const float* xr = Xs + b * XROW;
                float zi = acc[bi][0] + xr[jl];
                float zf = acc[bi][1] + xr[12 + jl];
                float zg = acc[bi][2] + xr[24 + jl];
                float zo = acc[bi][3] + xr[36 + jl];
                float si = 1.f / (1.f + expf(-zi));
                float sf = 1.f / (1.f + expf(-zf));
                float so = 1.f / (1.f + expf(-zo));
                float nc = sf * c2[bi] + si * tanhf(zg);
                c2[bi] = nc;
                hnew = so * tanhf(nc);
                outv = hnew;
            } else {
                hnew = hreg[bi];
                outv = 0.f;
            }
            hreg[bi] = hnew;
            encT[(size_t)(dir * HID + j) * MT + b * SEQ + src] = outv;
        }
        *(float2*)&d_hT[p ^ 1][dir][j][b0] = make_float2(hreg[0], hreg[1]);

        group_bar(dir);
    }
}

// ---------------- attention tail ----------------
__global__ void scores_kernel(const float* __restrict__ we) {  // ekey lives in d_xpf
    const int warp = threadIdx.x >> 5, lane = threadIdx.x & 31;
    const size_t row = (size_t)blockIdx.x * 8 + warp;
    const float* r = d_xpf + row * E2;
    float s = 0.f;
    for (int k = lane; k < E2; k += 32) s += r[k] * we[k];
#pragma unroll
    for (int o = 16; o; o >>= 1) s += __shfl_down_sync(0xffffffffu, s, o);
    if (!lane) d_scores[row] = s;
}

__global__ void softmax_kernel(const int* __restrict__ lens) {
    __shared__ float red[512];
    const int b = blockIdx.x, t = threadIdx.x;
    const int L = lens[b];
    float v = (t < L) ? d_scores[b * SEQ + t] : -INFINITY;
    red[t] = v;
    __syncthreads();
    for (int s = 256; s > 0; s >>= 1) { if (t < s) red[t] = fmaxf(red[t], red[t + s]); __syncthreads(); }
    float m = red[0];
    __syncthreads();
    float e = (t < L) ? expf(v - m) : 0.f;
    red[t] = e;
    __syncthreads();
    for (int s = 256; s > 0; s >>= 1) { if (t < s) red[t] += red[t + s]; __syncthreads(); }
    d_attn[b * SEQ + t] = e / red[0];
}

// context over transposed enc1: contiguous-in-t warp reads
__global__ void context_kernel() {
    const int warp = threadIdx.x >> 5, lane = threadIdx.x & 31;
    const int h = blockIdx.x * 8 + warp;
    const int b = blockIdx.y;
    const float* a = d_attn + b * SEQ;
    const float* e = d_enc1T + (size_t)h * MT + b * SEQ;
    float s = 0.f;
    for (int t = lane; t < SEQ; t += 32) s += a[t] * e[t];
#pragma unroll
    for (int o = 16; o; o >>= 1) s += __shfl_down_sync(0xffffffffu, s, o);
    if (!lane) d_ctx[b * E2 + h] = s;
}

__global__ void post_kernel(const float* __restrict__ Wp, const float* __restrict__ bp) {
    const int b = blockIdx.y;
    const int n = blockIdx.x * 256 + threadIdx.x;
    float acc = bp[n];
    const float* c = d_ctx + b * E2;
    for (int k = 0; k < E2; k++) acc += c[k] * Wp[(size_t)k * E2 + n];
    d_ctx2[b * E2 + n] = acc;
}

__global__ void intents_kernel(const float* __restrict__ Wi, const float* __restrict__ bi, float* __restrict__ out) {
    const int b = blockIdx.x, n = threadIdx.x;
    if (n >= NINT) return;
    float acc = bi[n];
    const float* c = d_ctx2 + b * E2;
    for (int k = 0; k < E2; k++) acc += c[k] * Wi[k * NINT + n];
    out[b * NINT + n] = acc;
}

// ---------------- launch ----------------
extern "C" void kernel_launch(void* const* d_in, const int* in_sizes, int n_in,
                              void* d_out, int out_size) {
    const float* X    = (const float*)d_in[0];
    const int*   lens = (const int*)  d_in[1];
    const int s = (n_in >= 23) ? 3 : 2;  // skip is_test if present
    const float* W_reg  = (const float*)d_in[s + 0];
    const float* b_reg  = (const float*)d_in[s + 1];
    const float* Wi0f   = (const float*)d_in[s + 2];
    const float* Wh0f   = (const float*)d_in[s + 3];
    const float* b0f    = (const float*)d_in[s + 4];
    const float* Wi0b   = (const float*)d_in[s + 5];
    const float* Wh0b   = (const float*)d_in[s + 6];
    const float* b0b    = (const float*)d_in[s + 7];
    const float* Wi1f   = (const float*)d_in[s + 8];
    const float* Wh1f   = (const float*)d_in[s + 9];
    const float* b1f    = (const float*)d_in[s + 10];
    const float* Wi1b   = (const float*)d_in[s + 11];
    const float* Wh1b   = (const float*)d_in[s + 12];
    const float* b1b    = (const float*)d_in[s + 13];
    const float* W_keys = (const float*)d_in[s + 14];
    const float* W_en   = (const float*)d_in[s + 15];
    const float* W_post = (const float*)d_in[s + 16];
    const float* b_post = (const float*)d_in[s + 17];
    const float* W_int  = (const float*)d_in[s + 18];
    const float* b_int  = (const float*)d_in[s + 19];

    cudaFuncSetAttribute(lstm_layer, cudaFuncAttributeMaxDynamicSharedMemorySize, LSTM_SMEM);

    // resident recurrent weights + X transpose
    conv_wres<<<256, 384>>>(Wh0f, Wh0b, Wh1f, Wh1b);
    transpose_x<<<dim3(MT / 32, DIN / 32), dim3(32, 8)>>>(X);

    // regT = (X @ W_reg + b_reg)^T   (A = d_xT, C transposed)
    gemmT<false, true><<<dim3(DENSE / 128, MT / 128), 256>>>(0, W_reg, b_reg, 0, DENSE, DIN, lens);

    // layer-0 input projections (A = d_regT)
    gemmT<false, false><<<dim3(G4 / 128, MT / 128), 256>>>(1, Wi0f, b0f, 1, G4, DENSE, lens);
    gemmT<false, false><<<dim3(G4 / 128, MT / 128), 256>>>(1, Wi0b, b0b, 2, G4, DENSE, lens);

    // layer-0 recurrence -> enc0T
    lstm_layer<<<128, 384, LSTM_SMEM>>>(0, lens);

    // layer-1 input projections (A = d_enc0T)
    gemmT<false, false><<<dim3(G4 / 128, MT / 128), 256>>>(2, Wi1f, b1f, 1, G4, E2, lens);
    gemmT<false, false><<<dim3(G4 / 128, MT / 128), 256>>>(2, Wi1b, b1b, 2, G4, E2, lens);

    // layer-1 recurrence -> enc1T
    lstm_layer<<<128, 384, LSTM_SMEM>>>(1, lens);

    // ekey = tanh(enc1 @ W_keys) -> d_xpf   (A = d_enc1T)
    gemmT<true, false><<<dim3(E2 / 128, MT / 128), 256>>>(3, W_keys, nullptr, 1, E2, E2, lens);

    // attention tail
    scores_kernel<<<MT / 8, 256>>>(W_en);
    softmax_kernel<<<BATCH, 512>>>(lens);
    context_kernel<<<dim3(E2 / 8, BATCH), 256>>>();
    post_kernel<<<dim3(E2 / 256, BATCH), 256>>>(W_post, b_post);
    intents_kernel<<<BATCH, 64>>>(W_int, b_int, (float*)d_out);
}